// round 2
// baseline (speedup 1.0000x reference)
#include <cuda_runtime.h>
#include <cuda_bf16.h>
#include <math.h>

// Problem constants
#define LAYERS 2
#define BATCH  2
#define SEQ    2048
#define DMODEL 768
#define NHEADS 12
#define KVHEADS 4
#define NREP   3
#define HEADD  64
#define FFDIM  3072
#define ROWS   (BATCH*SEQ)     // 4096

// ---------------------------------------------------------------------------
// Scratch (allocation-free: __device__ globals)
// ---------------------------------------------------------------------------
__device__ float g_h[ROWS * DMODEL];
__device__ float g_q[ROWS * DMODEL];
__device__ float g_k[ROWS * KVHEADS*HEADD];
__device__ float g_v[ROWS * KVHEADS*HEADD];
__device__ float g_attn[ROWS * DMODEL];
__device__ float g_x[ROWS * DMODEL];
__device__ float g_ff[ROWS * FFDIM];

// ---------------------------------------------------------------------------
// RMSNorm: one block per row of 768
// ---------------------------------------------------------------------------
__global__ void __launch_bounds__(256) rmsnorm_k(const float* __restrict__ x,
                                                 const float* __restrict__ w,
                                                 float* __restrict__ y)
{
    int row = blockIdx.x;
    const float* xr = x + (size_t)row * DMODEL;
    float* yr = y + (size_t)row * DMODEL;
    int t = threadIdx.x;
    float v0 = xr[t], v1 = xr[t + 256], v2 = xr[t + 512];
    float ss = v0*v0 + v1*v1 + v2*v2;
    #pragma unroll
    for (int off = 16; off > 0; off >>= 1)
        ss += __shfl_xor_sync(0xffffffffu, ss, off);
    __shared__ float red[8];
    if ((t & 31) == 0) red[t >> 5] = ss;
    __syncthreads();
    if (t < 32) {
        float s = (t < 8) ? red[t] : 0.f;
        #pragma unroll
        for (int off = 4; off > 0; off >>= 1)
            s += __shfl_xor_sync(0xffffffffu, s, off);
        if (t == 0) red[0] = s;
    }
    __syncthreads();
    float inv = 1.0f / sqrtf(red[0] * (1.0f / DMODEL) + 1e-6f);
    yr[t]       = v0 * inv * w[t];
    yr[t + 256] = v1 * inv * w[t + 256];
    yr[t + 512] = v2 * inv * w[t + 512];
}

// ---------------------------------------------------------------------------
// RoPE: in-place, one thread per (row, head, freq-pair)
// ---------------------------------------------------------------------------
__global__ void __launch_bounds__(256) rope_k(float* __restrict__ t, int nh)
{
    int idx = blockIdx.x * blockDim.x + threadIdx.x;
    int total = ROWS * nh * (HEADD / 2);
    if (idx >= total) return;
    int i   = idx & 31;
    int h   = (idx >> 5) % nh;
    int row = idx / (32 * nh);
    int s   = row & (SEQ - 1);
    float freq = (float)exp(-9.210340371976184 * ((double)i / 32.0));
    float ang = (float)s * freq;
    float sn, cs;
    sincosf(ang, &sn, &cs);
    float* p = t + (size_t)row * (nh * HEADD) + h * HEADD + 2 * i;
    float t0 = p[0], t1 = p[1];
    p[0] = t0 * cs - t1 * sn;
    p[1] = t0 * sn + t1 * cs;
}

// ---------------------------------------------------------------------------
// SGEMM: C(MxN) = A(MxK) @ B(KxN), 128x128x16 tiles, 256 threads, 8x8/thread
// Software-pipelined: next K-slice prefetched to registers during compute.
// MODE 0: C = AB
// MODE 1: C = AB + R        (residual add; R may alias C)
// MODE 2: C = silu(AB)
// MODE 3: C = C * AB        (gated multiply into existing C)
// ---------------------------------------------------------------------------
template<int MODE>
__global__ void __launch_bounds__(256) sgemm_k(const float* __restrict__ A,
                                               const float* __restrict__ Bm,
                                               float* __restrict__ C,
                                               const float* __restrict__ R,
                                               int M, int N, int K)
{
    __shared__ float As[16][132];   // transposed A tile, padded
    __shared__ float Bs[16][128];
    int tid = threadIdx.x;
    int m0 = blockIdx.y * 128;
    int n0 = blockIdx.x * 128;
    int trow = (tid >> 4) * 8;
    int tcol = (tid & 15) * 8;
    float acc[8][8];
    #pragma unroll
    for (int i = 0; i < 8; i++)
        #pragma unroll
        for (int j = 0; j < 8; j++) acc[i][j] = 0.f;

    const float* Aptr = A + (size_t)m0 * K;
    const float* Bptr = Bm + n0;

    // per-thread load coordinates (2 float4 each for A and B)
    int ar[2], ac[2], br[2], bc[2];
    #pragma unroll
    for (int qq = 0; qq < 2; qq++) {
        int id = tid + qq * 256;
        ar[qq] = id >> 2;            // 0..127
        ac[qq] = (id & 3) * 4;       // 0..12
        br[qq] = id >> 5;            // 0..15
        bc[qq] = (id & 31) * 4;      // 0..124
    }

    float4 aR[2], bR[2];
    // preload tile 0
    #pragma unroll
    for (int qq = 0; qq < 2; qq++) {
        aR[qq] = *(const float4*)(Aptr + (size_t)ar[qq] * K + ac[qq]);
        bR[qq] = *(const float4*)(Bptr + (size_t)br[qq] * N + bc[qq]);
    }

    for (int k0 = 0; k0 < K; k0 += 16) {
        // store current regs to smem
        #pragma unroll
        for (int qq = 0; qq < 2; qq++) {
            As[ac[qq] + 0][ar[qq]] = aR[qq].x;
            As[ac[qq] + 1][ar[qq]] = aR[qq].y;
            As[ac[qq] + 2][ar[qq]] = aR[qq].z;
            As[ac[qq] + 3][ar[qq]] = aR[qq].w;
            *(float4*)&Bs[br[qq]][bc[qq]] = bR[qq];
        }
        __syncthreads();

        // prefetch next tile into regs (overlaps with compute below)
        int kn = k0 + 16;
        if (kn < K) {
            #pragma unroll
            for (int qq = 0; qq < 2; qq++) {
                aR[qq] = *(const float4*)(Aptr + (size_t)ar[qq] * K + kn + ac[qq]);
                bR[qq] = *(const float4*)(Bptr + (size_t)(kn + br[qq]) * N + bc[qq]);
            }
        }

        #pragma unroll
        for (int kk = 0; kk < 16; kk++) {
            float a[8], b[8];
            *(float4*)(a)     = *(float4*)&As[kk][trow];
            *(float4*)(a + 4) = *(float4*)&As[kk][trow + 4];
            *(float4*)(b)     = *(float4*)&Bs[kk][tcol];
            *(float4*)(b + 4) = *(float4*)&Bs[kk][tcol + 4];
            #pragma unroll
            for (int i = 0; i < 8; i++)
                #pragma unroll
                for (int j = 0; j < 8; j++)
                    acc[i][j] = fmaf(a[i], b[j], acc[i][j]);
        }
        __syncthreads();
    }

    #pragma unroll
    for (int i = 0; i < 8; i++) {
        size_t row = (size_t)(m0 + trow + i);
        #pragma unroll
        for (int j = 0; j < 8; j++) {
            size_t idx = row * N + (n0 + tcol + j);
            float v = acc[i][j];
            if (MODE == 1) v += R[idx];
            if (MODE == 2) v = v / (1.0f + expf(-v));
            if (MODE == 3) v *= C[idx];
            C[idx] = v;
        }
    }
}

// ---------------------------------------------------------------------------
// Flash attention (causal, GQA kvh = h/NREP). Grid (S/64, H, B), 256 threads.
// BQ=64, BK=32, static shared memory (~41.7KB, no attribute call needed).
// Thread map: ty=tid>>4 (16 row-groups of 4), tx=tid&15.
//   scores: thread computes rows ty*4+i, cols tx*2+j (64x32 tile)
//   output: thread computes rows ty*4+i, cols tx*4+j (64x64 tile)
// ---------------------------------------------------------------------------
__global__ void __launch_bounds__(256) flash_kernel(const float* __restrict__ q,
                                                    const float* __restrict__ k,
                                                    const float* __restrict__ v,
                                                    float* __restrict__ o)
{
    __shared__ float Qs[64][65];
    __shared__ float Ks[32][65];
    __shared__ float Vs[32][68];   // padded to 68 so float4 reads stay 16B-aligned
    __shared__ float Ps[64][33];

    int qt = blockIdx.x, h = blockIdx.y, b = blockIdx.z;
    int kvh = h / NREP;
    int tid = threadIdx.x;
    int ty = tid >> 4, tx = tid & 15;
    int q0 = qt * 64;

    const float* qbase = q + (size_t)(b * SEQ + q0) * DMODEL + h * HEADD;
    for (int i = tid; i < 64 * 64; i += 256) {
        int r = i >> 6, d = i & 63;
        Qs[r][d] = qbase[(size_t)r * DMODEL + d];
    }

    float m[4], l[4], o_acc[4][4];
    #pragma unroll
    for (int i = 0; i < 4; i++) {
        m[i] = -INFINITY; l[i] = 0.f;
        #pragma unroll
        for (int j = 0; j < 4; j++) o_acc[i][j] = 0.f;
    }

    const float* kbase = k + (size_t)(b * SEQ) * (KVHEADS * HEADD) + kvh * HEADD;
    const float* vbase = v + (size_t)(b * SEQ) * (KVHEADS * HEADD) + kvh * HEADD;

    int ntiles = 2 * qt + 2;   // keys [0, q0+64)
    for (int kt = 0; kt < ntiles; kt++) {
        __syncthreads();
        // load K/V tile: 32 rows x 64 cols = 2048 elems, 8 per thread
        for (int i = tid; i < 32 * 64; i += 256) {
            int r = i >> 6, d = i & 63;
            size_t goff = (size_t)(kt * 32 + r) * (KVHEADS * HEADD) + d;
            Ks[r][d] = kbase[goff];
            Vs[r][d] = vbase[goff];
        }
        __syncthreads();

        float s[4][2];
        #pragma unroll
        for (int i = 0; i < 4; i++) { s[i][0] = 0.f; s[i][1] = 0.f; }

        #pragma unroll 8
        for (int kk = 0; kk < 64; kk++) {
            float a[4], bb[2];
            #pragma unroll
            for (int i = 0; i < 4; i++) a[i] = Qs[ty * 4 + i][kk];
            bb[0] = Ks[tx * 2 + 0][kk];
            bb[1] = Ks[tx * 2 + 1][kk];
            #pragma unroll
            for (int i = 0; i < 4; i++) {
                s[i][0] = fmaf(a[i], bb[0], s[i][0]);
                s[i][1] = fmaf(a[i], bb[1], s[i][1]);
            }
        }

        #pragma unroll
        for (int i = 0; i < 4; i++) { s[i][0] *= 0.125f; s[i][1] *= 0.125f; }

        if (kt >= 2 * qt) {   // tiles overlapping the diagonal
            #pragma unroll
            for (int i = 0; i < 4; i++) {
                int qg = q0 + ty * 4 + i;
                int kg = kt * 32 + tx * 2;
                if (kg > qg)     s[i][0] = -INFINITY;
                if (kg + 1 > qg) s[i][1] = -INFINITY;
            }
        }

        #pragma unroll
        for (int i = 0; i < 4; i++) {
            float mx = fmaxf(s[i][0], s[i][1]);
            #pragma unroll
            for (int off = 8; off > 0; off >>= 1)
                mx = fmaxf(mx, __shfl_xor_sync(0xffffffffu, mx, off, 16));
            float mnew = fmaxf(m[i], mx);
            float p0 = expf(s[i][0] - mnew);
            float p1 = expf(s[i][1] - mnew);
            float sum = p0 + p1;
            #pragma unroll
            for (int off = 8; off > 0; off >>= 1)
                sum += __shfl_xor_sync(0xffffffffu, sum, off, 16);
            float alpha = expf(m[i] - mnew);
            l[i] = l[i] * alpha + sum;
            m[i] = mnew;
            #pragma unroll
            for (int j = 0; j < 4; j++) o_acc[i][j] *= alpha;
            int r = ty * 4 + i;
            Ps[r][tx * 2 + 0] = p0;
            Ps[r][tx * 2 + 1] = p1;
        }
        __syncthreads();

        #pragma unroll 8
        for (int kk = 0; kk < 32; kk++) {
            float p[4];
            #pragma unroll
            for (int i = 0; i < 4; i++) p[i] = Ps[ty * 4 + i][kk];
            float4 vv = *(float4*)&Vs[kk][tx * 4];
            #pragma unroll
            for (int i = 0; i < 4; i++) {
                o_acc[i][0] = fmaf(p[i], vv.x, o_acc[i][0]);
                o_acc[i][1] = fmaf(p[i], vv.y, o_acc[i][1]);
                o_acc[i][2] = fmaf(p[i], vv.z, o_acc[i][2]);
                o_acc[i][3] = fmaf(p[i], vv.w, o_acc[i][3]);
            }
        }
    }

    float* obase = o + (size_t)(b * SEQ + q0) * DMODEL + h * HEADD;
    #pragma unroll
    for (int i = 0; i < 4; i++) {
        float invl = 1.0f / l[i];
        #pragma unroll
        for (int j = 0; j < 4; j++)
            obase[(size_t)(ty * 4 + i) * DMODEL + tx * 4 + j] = o_acc[i][j] * invl;
    }
}

// ---------------------------------------------------------------------------
// Launch sequence
// ---------------------------------------------------------------------------
extern "C" void kernel_launch(void* const* d_in, const int* in_sizes, int n_in,
                              void* d_out, int out_size)
{
    (void)in_sizes; (void)n_in; (void)out_size;
    const float* x_in = (const float*)d_in[0];
    const float* Wq   = (const float*)d_in[1];
    const float* Wk   = (const float*)d_in[2];
    const float* Wv   = (const float*)d_in[3];
    const float* Wo   = (const float*)d_in[4];
    const float* an_w = (const float*)d_in[5];
    const float* w0   = (const float*)d_in[6];
    const float* w1   = (const float*)d_in[7];
    const float* w2   = (const float*)d_in[8];
    const float* sn_w = (const float*)d_in[9];
    const float* on_w = (const float*)d_in[10];

    float *h, *q, *k, *v, *attn, *x, *ff;
    cudaGetSymbolAddress((void**)&h,    g_h);
    cudaGetSymbolAddress((void**)&q,    g_q);
    cudaGetSymbolAddress((void**)&k,    g_k);
    cudaGetSymbolAddress((void**)&v,    g_v);
    cudaGetSymbolAddress((void**)&attn, g_attn);
    cudaGetSymbolAddress((void**)&x,    g_x);
    cudaGetSymbolAddress((void**)&ff,   g_ff);

    const float* cur = x_in;
    for (int li = 0; li < LAYERS; li++) {
        rmsnorm_k<<<ROWS, 256>>>(cur, an_w + (size_t)li * DMODEL, h);

        sgemm_k<0><<<dim3(6, 32), 256>>>(h, Wq + (size_t)li * DMODEL * DMODEL, q, nullptr,
                                         ROWS, DMODEL, DMODEL);
        sgemm_k<0><<<dim3(2, 32), 256>>>(h, Wk + (size_t)li * DMODEL * (KVHEADS*HEADD), k, nullptr,
                                         ROWS, KVHEADS*HEADD, DMODEL);
        sgemm_k<0><<<dim3(2, 32), 256>>>(h, Wv + (size_t)li * DMODEL * (KVHEADS*HEADD), v, nullptr,
                                         ROWS, KVHEADS*HEADD, DMODEL);

        rope_k<<<(ROWS * NHEADS * 32 + 255) / 256, 256>>>(q, NHEADS);
        rope_k<<<(ROWS * KVHEADS * 32 + 255) / 256, 256>>>(k, KVHEADS);

        flash_kernel<<<dim3(SEQ / 64, NHEADS, BATCH), 256>>>(q, k, v, attn);

        // x = cur + attn @ Wo
        sgemm_k<1><<<dim3(6, 32), 256>>>(attn, Wo + (size_t)li * DMODEL * DMODEL, x, cur,
                                         ROWS, DMODEL, DMODEL);

        rmsnorm_k<<<ROWS, 256>>>(x, sn_w + (size_t)li * DMODEL, h);

        // ff = silu(h @ w0); ff *= h @ w1; x += ff @ w2
        sgemm_k<2><<<dim3(24, 32), 256>>>(h, w0 + (size_t)li * DMODEL * FFDIM, ff, nullptr,
                                          ROWS, FFDIM, DMODEL);
        sgemm_k<3><<<dim3(24, 32), 256>>>(h, w1 + (size_t)li * DMODEL * FFDIM, ff, nullptr,
                                          ROWS, FFDIM, DMODEL);
        sgemm_k<1><<<dim3(6, 32), 256>>>(ff, w2 + (size_t)li * FFDIM * DMODEL, x, x,
                                         ROWS, DMODEL, FFDIM);
        cur = x;
    }

    rmsnorm_k<<<ROWS, 256>>>(x, on_w, (float*)d_out);
}

// round 5
// speedup vs baseline: 1.0934x; 1.0934x over previous
#include <cuda_runtime.h>
#include <cuda_bf16.h>
#include <math.h>
#include <stdint.h>

// Problem constants
#define LAYERS 2
#define BATCH  2
#define SEQ    2048
#define DMODEL 768
#define NHEADS 12
#define KVHEADS 4
#define NREP   3
#define HEADD  64
#define FFDIM  3072
#define ROWS   (BATCH*SEQ)     // 4096
#define QKVW   1280            // 768 q + 256 k + 256 v

// ---------------------------------------------------------------------------
// Scratch (allocation-free: __device__ globals)
// ---------------------------------------------------------------------------
__device__ float g_h[ROWS * DMODEL];
__device__ float g_qkv[ROWS * QKVW];
__device__ float g_attn[ROWS * DMODEL];
__device__ float g_x[ROWS * DMODEL];
__device__ float g_ff[ROWS * FFDIM];
__device__ float g_wqkv[LAYERS * DMODEL * QKVW];
__device__ float g_w01[LAYERS * DMODEL * 2 * FFDIM];

// ---------------------------------------------------------------------------
// RMSNorm: one block per row of 768
// ---------------------------------------------------------------------------
__global__ void __launch_bounds__(256) rmsnorm_k(const float* __restrict__ x,
                                                 const float* __restrict__ w,
                                                 float* __restrict__ y)
{
    int row = blockIdx.x;
    const float* xr = x + (size_t)row * DMODEL;
    float* yr = y + (size_t)row * DMODEL;
    int t = threadIdx.x;
    float v0 = xr[t], v1 = xr[t + 256], v2 = xr[t + 512];
    float ss = v0*v0 + v1*v1 + v2*v2;
    #pragma unroll
    for (int off = 16; off > 0; off >>= 1)
        ss += __shfl_xor_sync(0xffffffffu, ss, off);
    __shared__ float red[8];
    if ((t & 31) == 0) red[t >> 5] = ss;
    __syncthreads();
    if (t < 32) {
        float s = (t < 8) ? red[t] : 0.f;
        #pragma unroll
        for (int off = 4; off > 0; off >>= 1)
            s += __shfl_xor_sync(0xffffffffu, s, off);
        if (t == 0) red[0] = s;
    }
    __syncthreads();
    float inv = 1.0f / sqrtf(red[0] * (1.0f / DMODEL) + 1e-6f);
    yr[t]       = v0 * inv * w[t];
    yr[t + 256] = v1 * inv * w[t + 256];
    yr[t + 512] = v2 * inv * w[t + 512];
}

// ---------------------------------------------------------------------------
// Weight packing (runs inside the graph every replay; ~10us total)
// ---------------------------------------------------------------------------
__global__ void __launch_bounds__(256) pack_qkv_w(const float* __restrict__ Wq,
                                                  const float* __restrict__ Wk,
                                                  const float* __restrict__ Wv,
                                                  float* __restrict__ dst)
{
    int idx = blockIdx.x * 256 + threadIdx.x;
    const int total = LAYERS * DMODEL * QKVW;
    if (idx >= total) return;
    int col = idx % QKVW;
    int d   = (idx / QKVW) % DMODEL;
    int l   = idx / (QKVW * DMODEL);
    float v;
    if (col < 768)       v = Wq[((size_t)l * DMODEL + d) * 768 + col];
    else if (col < 1024) v = Wk[((size_t)l * DMODEL + d) * 256 + (col - 768)];
    else                 v = Wv[((size_t)l * DMODEL + d) * 256 + (col - 1024)];
    dst[idx] = v;
}

__global__ void __launch_bounds__(256) pack_w01(const float* __restrict__ w0,
                                                const float* __restrict__ w1,
                                                float* __restrict__ dst)
{
    int idx = blockIdx.x * 256 + threadIdx.x;
    const int total = LAYERS * DMODEL * 2 * FFDIM;
    if (idx >= total) return;
    int col = idx % (2 * FFDIM);
    int d   = (idx / (2 * FFDIM)) % DMODEL;
    int l   = idx / (2 * FFDIM * DMODEL);
    int f   = col >> 1;
    size_t src = ((size_t)l * DMODEL + d) * FFDIM + f;
    dst[idx] = (col & 1) ? w1[src] : w0[src];
}

// ---------------------------------------------------------------------------
// RoPE on packed qkv: q heads 0..11 at col h*64, k heads at 768 + kvh*64
// ---------------------------------------------------------------------------
__global__ void __launch_bounds__(256) rope_packed(float* __restrict__ qkv)
{
    int idx = blockIdx.x * 256 + threadIdx.x;
    const int total = ROWS * 16 * 32;   // 12 q heads + 4 k heads, 32 pairs each
    if (idx >= total) return;
    int i    = idx & 31;
    int hh   = (idx >> 5) & 15;
    int row  = idx >> 9;
    int s    = row & (SEQ - 1);
    float freq = (float)exp(-9.210340371976184 * ((double)i / 32.0));
    float ang = (float)s * freq;
    float sn, cs;
    sincosf(ang, &sn, &cs);
    int coff = (hh < 12) ? hh * 64 : 768 + (hh - 12) * 64;
    float* p = qkv + (size_t)row * QKVW + coff + 2 * i;
    float t0 = p[0], t1 = p[1];
    p[0] = t0 * cs - t1 * sn;
    p[1] = t0 * sn + t1 * cs;
}

// ---------------------------------------------------------------------------
// tf32 tensor-core GEMM: C(MxN) = A(MxK) @ B(KxN)
// 128x128x32 block tile, 256 threads (8 warps as 2x4), warp tile 64x32.
// Smem holds fragment-permuted tf32 tiles -> conflict-free LDS.128/LDS.64.
// MODE 0: C = AB
// MODE 1: C = AB + R        (R may alias C)
// MODE 2: gated: cols are interleaved (w0,w1) pairs; writes silu(c0)*c1
//         to C with width N/2.
// ---------------------------------------------------------------------------
__device__ __forceinline__ unsigned f2tf(float x) {
    unsigned r; asm("cvt.rna.tf32.f32 %0, %1;" : "=r"(r) : "f"(x)); return r;
}

__device__ __forceinline__ void mma8(float* d, const unsigned* a, const unsigned* b) {
    asm volatile("mma.sync.aligned.m16n8k8.row.col.f32.tf32.tf32.f32 "
        "{%0,%1,%2,%3}, {%4,%5,%6,%7}, {%8,%9}, {%0,%1,%2,%3};"
        : "+f"(d[0]), "+f"(d[1]), "+f"(d[2]), "+f"(d[3])
        : "r"(a[0]), "r"(a[1]), "r"(a[2]), "r"(a[3]), "r"(b[0]), "r"(b[1]));
}

template<int MODE>
__global__ void __launch_bounds__(256) tgemm_k(const float* __restrict__ A,
                                               const float* __restrict__ Bm,
                                               float* __restrict__ C,
                                               const float* __restrict__ R,
                                               int M, int N, int K)
{
    // As[ks][mt][lane][j]: lane holds a-regs j=0..3 of m-tile mt, k-step ks
    // Bs[ks][nt][lane][j]: lane holds b-regs j=0..1 of n-tile nt
    __shared__ unsigned As[4][8][32][4];   // 16 KB
    __shared__ unsigned Bs[4][16][32][2];  // 16 KB

    int tid = threadIdx.x, lane = tid & 31, warp = tid >> 5;
    int wm = warp >> 2, wn = warp & 3;
    int m0 = blockIdx.y * 128, n0 = blockIdx.x * 128;

    float acc[4][4][4];
    #pragma unroll
    for (int a = 0; a < 4; a++)
        #pragma unroll
        for (int b = 0; b < 4; b++)
            #pragma unroll
            for (int c = 0; c < 4; c++) acc[a][b][c] = 0.f;

    const float* Ab = A + (size_t)m0 * K;
    const float* Bb = Bm + n0;

    // global-load coordinates (4 float4 each from A and B per K-tile)
    int rA = tid >> 3;            // 0..31 (+32*i)
    int cA = (tid & 7) * 4;       // 0..28, fixed
    int rB = tid >> 5;            // 0..7  (+8*i)
    int cB = (tid & 31) * 4;      // 0..124, fixed

    // A store decomposition (per-thread constants)
    int ksA = cA >> 3;
    int khA = (cA >> 2) & 1;
    // B store decomposition
    int tgB = rB & 3;
    int khB = (rB >> 2) & 1;
    int ntB = cB >> 3;
    int nnB = cB & 7;             // 0 or 4

    float4 pa[4], pb[4];
    #pragma unroll
    for (int i = 0; i < 4; i++) {
        pa[i] = *(const float4*)(Ab + (size_t)(rA + 32 * i) * K + cA);
        pb[i] = *(const float4*)(Bb + (size_t)(rB + 8 * i) * N + cB);
    }

    for (int k0 = 0; k0 < K; k0 += 32) {
        // store prefetched tile (tf32-converted) into permuted smem
        #pragma unroll
        for (int i = 0; i < 4; i++) {
            int r = rA + 32 * i;
            int mt = r >> 4, rr = r & 15;
            int gg = rr & 7, jr = rr >> 3;
            int j = jr + 2 * khA;
            unsigned* dst = &As[ksA][mt][gg * 4][j];
            dst[0]  = f2tf(pa[i].x);
            dst[4]  = f2tf(pa[i].y);
            dst[8]  = f2tf(pa[i].z);
            dst[12] = f2tf(pa[i].w);
        }
        #pragma unroll
        for (int i = 0; i < 4; i++) {
            unsigned* dst = &Bs[i][ntB][nnB * 4 + tgB][khB];
            dst[0]  = f2tf(pb[i].x);
            dst[8]  = f2tf(pb[i].y);
            dst[16] = f2tf(pb[i].z);
            dst[24] = f2tf(pb[i].w);
        }
        __syncthreads();

        // prefetch next K-tile
        int kn = k0 + 32;
        if (kn < K) {
            #pragma unroll
            for (int i = 0; i < 4; i++) {
                pa[i] = *(const float4*)(Ab + (size_t)(rA + 32 * i) * K + kn + cA);
                pb[i] = *(const float4*)(Bb + (size_t)(kn + rB + 8 * i) * N + cB);
            }
        }

        #pragma unroll
        for (int ks = 0; ks < 4; ks++) {
            unsigned af[4][4], bf[4][2];
            #pragma unroll
            for (int mt = 0; mt < 4; mt++)
                *(uint4*)af[mt] = *(const uint4*)&As[ks][wm * 4 + mt][lane][0];
            #pragma unroll
            for (int nt = 0; nt < 4; nt++)
                *(uint2*)bf[nt] = *(const uint2*)&Bs[ks][wn * 4 + nt][lane][0];
            #pragma unroll
            for (int mt = 0; mt < 4; mt++)
                #pragma unroll
                for (int nt = 0; nt < 4; nt++)
                    mma8(acc[mt][nt], af[mt], bf[nt]);
        }
        __syncthreads();
    }

    // epilogue
    int g = lane >> 2, tg = lane & 3;
    #pragma unroll
    for (int mt = 0; mt < 4; mt++) {
        int row = m0 + wm * 64 + mt * 16 + g;
        #pragma unroll
        for (int nt = 0; nt < 4; nt++) {
            int col = n0 + wn * 32 + nt * 8 + tg * 2;
            float* c = acc[mt][nt];
            if (MODE == 2) {
                int half = N >> 1;
                size_t o0 = (size_t)row * half + (col >> 1);
                float s0 = c[0] / (1.0f + expf(-c[0]));
                float s2 = c[2] / (1.0f + expf(-c[2]));
                C[o0]                    = s0 * c[1];
                C[o0 + (size_t)8 * half] = s2 * c[3];
            } else {
                size_t i0 = (size_t)row * N + col;
                size_t i1 = i0 + (size_t)8 * N;
                float2 v0 = make_float2(c[0], c[1]);
                float2 v1 = make_float2(c[2], c[3]);
                if (MODE == 1) {
                    v0.x += R[i0]; v0.y += R[i0 + 1];
                    v1.x += R[i1]; v1.y += R[i1 + 1];
                }
                *(float2*)&C[i0] = v0;
                *(float2*)&C[i1] = v1;
            }
        }
    }
}

// ---------------------------------------------------------------------------
// Flash attention (causal, GQA). Reads packed qkv (row stride 1280).
// Grid (S/64, H, B), 256 threads. BQ=64, BK=32, static smem.
// ---------------------------------------------------------------------------
__global__ void __launch_bounds__(256) flash_kernel(const float* __restrict__ qkv,
                                                    float* __restrict__ o)
{
    __shared__ float Qs[64][65];
    __shared__ float Ks[32][65];
    __shared__ float Vs[32][68];
    __shared__ float Ps[64][33];

    int qt = blockIdx.x, h = blockIdx.y, b = blockIdx.z;
    int kvh = h / NREP;
    int tid = threadIdx.x;
    int ty = tid >> 4, tx = tid & 15;
    int q0 = qt * 64;

    const float* qbase = qkv + (size_t)(b * SEQ + q0) * QKVW + h * HEADD;
    for (int i = tid; i < 64 * 64; i += 256) {
        int r = i >> 6, d = i & 63;
        Qs[r][d] = qbase[(size_t)r * QKVW + d];
    }

    float m[4], l[4], o_acc[4][4];
    #pragma unroll
    for (int i = 0; i < 4; i++) {
        m[i] = -INFINITY; l[i] = 0.f;
        #pragma unroll
        for (int j = 0; j < 4; j++) o_acc[i][j] = 0.f;
    }

    const float* kbase = qkv + (size_t)(b * SEQ) * QKVW + 768 + kvh * HEADD;
    const float* vbase = qkv + (size_t)(b * SEQ) * QKVW + 1024 + kvh * HEADD;

    int ntiles = 2 * qt + 2;
    for (int kt = 0; kt < ntiles; kt++) {
        __syncthreads();
        for (int i = tid; i < 32 * 64; i += 256) {
            int r = i >> 6, d = i & 63;
            size_t goff = (size_t)(kt * 32 + r) * QKVW + d;
            Ks[r][d] = kbase[goff];
            Vs[r][d] = vbase[goff];
        }
        __syncthreads();

        float s[4][2];
        #pragma unroll
        for (int i = 0; i < 4; i++) { s[i][0] = 0.f; s[i][1] = 0.f; }

        #pragma unroll 8
        for (int kk = 0; kk < 64; kk++) {
            float a[4], bb[2];
            #pragma unroll
            for (int i = 0; i < 4; i++) a[i] = Qs[ty * 4 + i][kk];
            bb[0] = Ks[tx * 2 + 0][kk];
            bb[1] = Ks[tx * 2 + 1][kk];
            #pragma unroll
            for (int i = 0; i < 4; i++) {
                s[i][0] = fmaf(a[i], bb[0], s[i][0]);
                s[i][1] = fmaf(a[i], bb[1], s[i][1]);
            }
        }

        #pragma unroll
        for (int i = 0; i < 4; i++) { s[i][0] *= 0.125f; s[i][1] *= 0.125f; }

        if (kt >= 2 * qt) {
            #pragma unroll
            for (int i = 0; i < 4; i++) {
                int qg = q0 + ty * 4 + i;
                int kg = kt * 32 + tx * 2;
                if (kg > qg)     s[i][0] = -INFINITY;
                if (kg + 1 > qg) s[i][1] = -INFINITY;
            }
        }

        #pragma unroll
        for (int i = 0; i < 4; i++) {
            float mx = fmaxf(s[i][0], s[i][1]);
            #pragma unroll
            for (int off = 8; off > 0; off >>= 1)
                mx = fmaxf(mx, __shfl_xor_sync(0xffffffffu, mx, off, 16));
            float mnew = fmaxf(m[i], mx);
            float p0 = expf(s[i][0] - mnew);
            float p1 = expf(s[i][1] - mnew);
            float sum = p0 + p1;
            #pragma unroll
            for (int off = 8; off > 0; off >>= 1)
                sum += __shfl_xor_sync(0xffffffffu, sum, off, 16);
            float alpha = expf(m[i] - mnew);
            l[i] = l[i] * alpha + sum;
            m[i] = mnew;
            #pragma unroll
            for (int j = 0; j < 4; j++) o_acc[i][j] *= alpha;
            int r = ty * 4 + i;
            Ps[r][tx * 2 + 0] = p0;
            Ps[r][tx * 2 + 1] = p1;
        }
        __syncthreads();

        #pragma unroll 8
        for (int kk = 0; kk < 32; kk++) {
            float p[4];
            #pragma unroll
            for (int i = 0; i < 4; i++) p[i] = Ps[ty * 4 + i][kk];
            float4 vv = *(float4*)&Vs[kk][tx * 4];
            #pragma unroll
            for (int i = 0; i < 4; i++) {
                o_acc[i][0] = fmaf(p[i], vv.x, o_acc[i][0]);
                o_acc[i][1] = fmaf(p[i], vv.y, o_acc[i][1]);
                o_acc[i][2] = fmaf(p[i], vv.z, o_acc[i][2]);
                o_acc[i][3] = fmaf(p[i], vv.w, o_acc[i][3]);
            }
        }
    }

    float* obase = o + (size_t)(b * SEQ + q0) * DMODEL + h * HEADD;
    #pragma unroll
    for (int i = 0; i < 4; i++) {
        float invl = 1.0f / l[i];
        #pragma unroll
        for (int j = 0; j < 4; j++)
            obase[(size_t)(ty * 4 + i) * DMODEL + tx * 4 + j] = o_acc[i][j] * invl;
    }
}

// ---------------------------------------------------------------------------
// Launch sequence
// ---------------------------------------------------------------------------
extern "C" void kernel_launch(void* const* d_in, const int* in_sizes, int n_in,
                              void* d_out, int out_size)
{
    (void)in_sizes; (void)n_in; (void)out_size;
    const float* x_in = (const float*)d_in[0];
    const float* Wq   = (const float*)d_in[1];
    const float* Wk   = (const float*)d_in[2];
    const float* Wv   = (const float*)d_in[3];
    const float* Wo   = (const float*)d_in[4];
    const float* an_w = (const float*)d_in[5];
    const float* w0   = (const float*)d_in[6];
    const float* w1   = (const float*)d_in[7];
    const float* w2   = (const float*)d_in[8];
    const float* sn_w = (const float*)d_in[9];
    const float* on_w = (const float*)d_in[10];

    float *h, *qkv, *attn, *x, *ff, *wqkv, *w01;
    cudaGetSymbolAddress((void**)&h,    g_h);
    cudaGetSymbolAddress((void**)&qkv,  g_qkv);
    cudaGetSymbolAddress((void**)&attn, g_attn);
    cudaGetSymbolAddress((void**)&x,    g_x);
    cudaGetSymbolAddress((void**)&ff,   g_ff);
    cudaGetSymbolAddress((void**)&wqkv, g_wqkv);
    cudaGetSymbolAddress((void**)&w01,  g_w01);

    // pack weights (captured; runs each replay)
    {
        int t1 = LAYERS * DMODEL * QKVW;
        pack_qkv_w<<<(t1 + 255) / 256, 256>>>(Wq, Wk, Wv, wqkv);
        int t2 = LAYERS * DMODEL * 2 * FFDIM;
        pack_w01<<<(t2 + 255) / 256, 256>>>(w0, w1, w01);
    }

    const float* cur = x_in;
    for (int li = 0; li < LAYERS; li++) {
        rmsnorm_k<<<ROWS, 256>>>(cur, an_w + (size_t)li * DMODEL, h);

        // fused QKV projection: [4096,768] @ [768,1280]
        tgemm_k<0><<<dim3(QKVW / 128, ROWS / 128), 256>>>(
            h, wqkv + (size_t)li * DMODEL * QKVW, qkv, nullptr,
            ROWS, QKVW, DMODEL);

        rope_packed<<<(ROWS * 16 * 32 + 255) / 256, 256>>>(qkv);

        flash_kernel<<<dim3(SEQ / 64, NHEADS, BATCH), 256>>>(qkv, attn);

        // x = cur + attn @ Wo
        tgemm_k<1><<<dim3(DMODEL / 128, ROWS / 128), 256>>>(
            attn, Wo + (size_t)li * DMODEL * DMODEL, x, cur,
            ROWS, DMODEL, DMODEL);

        rmsnorm_k<<<ROWS, 256>>>(x, sn_w + (size_t)li * DMODEL, h);

        // ff = silu(h@w0) * (h@w1), fused via interleaved packing, N=6144
        tgemm_k<2><<<dim3(2 * FFDIM / 128, ROWS / 128), 256>>>(
            h, w01 + (size_t)li * DMODEL * 2 * FFDIM, ff, nullptr,
            ROWS, 2 * FFDIM, DMODEL);

        // x += ff @ w2
        tgemm_k<1><<<dim3(DMODEL / 128, ROWS / 128), 256>>>(
            ff, w2 + (size_t)li * FFDIM * DMODEL, x, x,
            ROWS, DMODEL, FFDIM);
        cur = x;
    }

    rmsnorm_k<<<ROWS, 256>>>(x, on_w, (float*)d_out);
}

// round 6
// speedup vs baseline: 2.3799x; 2.1766x over previous
#include <cuda_runtime.h>
#include <cuda_bf16.h>
#include <math.h>
#include <stdint.h>

// Problem constants
#define LAYERS 2
#define BATCH  2
#define SEQ    2048
#define DMODEL 768
#define NHEADS 12
#define KVHEADS 4
#define NREP   3
#define HEADD  64
#define FFDIM  3072
#define ROWS   (BATCH*SEQ)     // 4096
#define QKVW   1280            // 768 q + 256 k + 256 v

// ---------------------------------------------------------------------------
// Scratch (allocation-free: __device__ globals)
// ---------------------------------------------------------------------------
__device__ float g_hp[ROWS * DMODEL];        // rmsnorm out, A-fragment-permuted
__device__ float g_qkv[ROWS * QKVW];         // row-major (flash reads it)
__device__ float g_attnp[ROWS * DMODEL];     // attention out, A-permuted
__device__ float g_x[ROWS * DMODEL];         // residual stream, row-major
__device__ float g_ffp[ROWS * FFDIM];        // gated FFN intermediate, A-permuted
__device__ float g_wqkvp[LAYERS * DMODEL * QKVW];      // B-permuted weights
__device__ float g_w01p[LAYERS * DMODEL * 2 * FFDIM];
__device__ float g_wop[LAYERS * DMODEL * DMODEL];
__device__ float g_w2p[LAYERS * FFDIM * DMODEL];

// ---------------------------------------------------------------------------
// tf32 helpers + fragment-permuted offset maps (M is always ROWS=4096)
// A perm:  [k8][m16(256)][lane(32)][j(4)]  (m16 stride 128, k8 stride 32768)
//   lane = (m&7)*4 + (k&3),  j = ((m>>3)&1) + 2*((k>>2)&1)
// B perm:  [k8][n8(N/8)][lane(32)][kh(2)]
//   lane = (n&7)*4 + (k&3),  kh = (k>>2)&1
// ---------------------------------------------------------------------------
__device__ __forceinline__ unsigned f2tf(float x) {
    unsigned r; asm("cvt.rna.tf32.f32 %0, %1;" : "=r"(r) : "f"(x)); return r;
}
__device__ __forceinline__ float tf32f(float x) { return __uint_as_float(f2tf(x)); }

__device__ __forceinline__ size_t aperm_off(int m, int k) {
    return (size_t)(k >> 3) * 32768 + (size_t)(m >> 4) * 128
         + ((m & 7) * 4 + (k & 3)) * 4 + ((m >> 3) & 1) + 2 * ((k >> 2) & 1);
}

__device__ __forceinline__ void mma8(float* d, const unsigned* a, const unsigned* b) {
    asm volatile("mma.sync.aligned.m16n8k8.row.col.f32.tf32.tf32.f32 "
        "{%0,%1,%2,%3}, {%4,%5,%6,%7}, {%8,%9}, {%0,%1,%2,%3};"
        : "+f"(d[0]), "+f"(d[1]), "+f"(d[2]), "+f"(d[3])
        : "r"(a[0]), "r"(a[1]), "r"(a[2]), "r"(a[3]), "r"(b[0]), "r"(b[1]));
}

// ---------------------------------------------------------------------------
// Weight pack kernels: one thread per float2 (dst words 2q, 2q+1 = kh pair).
// Warp covers one full 256B fragment block -> fully coalesced writes.
// ---------------------------------------------------------------------------
__device__ __forceinline__ void pack_coords(int q, int N, int& k, int& n, int& dw) {
    dw = 2 * q;
    int block = dw >> 6;
    int lane  = (dw & 63) >> 1;
    int n8cnt = N >> 3;
    int k8 = block / n8cnt, n8 = block - k8 * n8cnt;
    n = n8 * 8 + (lane >> 2);
    k = k8 * 8 + (lane & 3);
}

__global__ void __launch_bounds__(256) pack_qkv_w(const float* __restrict__ Wq,
                                                  const float* __restrict__ Wk,
                                                  const float* __restrict__ Wv,
                                                  float* __restrict__ dst)
{
    int p = blockIdx.x * 256 + threadIdx.x;
    const int perL = DMODEL * QKVW / 2;
    if (p >= LAYERS * perL) return;
    int l = p / perL, q = p - l * perL;
    int k, n, dw; pack_coords(q, QKVW, k, n, dw);
    float v0, v1;
    if (n < 768) {
        const float* s = Wq + ((size_t)l * DMODEL + k) * 768 + n;
        v0 = s[0]; v1 = s[4 * 768];
    } else if (n < 1024) {
        const float* s = Wk + ((size_t)l * DMODEL + k) * 256 + (n - 768);
        v0 = s[0]; v1 = s[4 * 256];
    } else {
        const float* s = Wv + ((size_t)l * DMODEL + k) * 256 + (n - 1024);
        v0 = s[0]; v1 = s[4 * 256];
    }
    float2 o; o.x = tf32f(v0); o.y = tf32f(v1);
    *(float2*)(dst + (size_t)l * DMODEL * QKVW + dw) = o;
}

__global__ void __launch_bounds__(256) pack_w01(const float* __restrict__ w0,
                                                const float* __restrict__ w1,
                                                float* __restrict__ dst)
{
    int p = blockIdx.x * 256 + threadIdx.x;
    const int perL = DMODEL * 2 * FFDIM / 2;
    if (p >= LAYERS * perL) return;
    int l = p / perL, q = p - l * perL;
    int k, n, dw; pack_coords(q, 2 * FFDIM, k, n, dw);
    int f = n >> 1;
    const float* s = ((n & 1) ? w1 : w0) + ((size_t)l * DMODEL + k) * FFDIM + f;
    float2 o; o.x = tf32f(s[0]); o.y = tf32f(s[4 * FFDIM]);
    *(float2*)(dst + (size_t)l * DMODEL * 2 * FFDIM + dw) = o;
}

__global__ void __launch_bounds__(256) pack_w_gen(const float* __restrict__ src,
                                                  float* __restrict__ dst,
                                                  int K, int N)
{
    int p = blockIdx.x * 256 + threadIdx.x;
    const int perL = (K * N) >> 1;
    if (p >= LAYERS * perL) return;
    int l = p / perL, q = p - l * perL;
    int k, n, dw; pack_coords(q, N, k, n, dw);
    const float* s = src + ((size_t)l * K + k) * N + n;
    float2 o; o.x = tf32f(s[0]); o.y = tf32f(s[(size_t)4 * N]);
    *(float2*)(dst + (size_t)l * K * N + dw) = o;
}

// ---------------------------------------------------------------------------
// RMSNorm: one block per row of 768. PERM=1 -> write A-fragment-permuted+tf32
// ---------------------------------------------------------------------------
template<int PERM>
__global__ void __launch_bounds__(256) rmsnorm_k(const float* __restrict__ x,
                                                 const float* __restrict__ w,
                                                 float* __restrict__ y)
{
    int row = blockIdx.x;
    const float* xr = x + (size_t)row * DMODEL;
    int t = threadIdx.x;
    float v0 = xr[t], v1 = xr[t + 256], v2 = xr[t + 512];
    float ss = v0*v0 + v1*v1 + v2*v2;
    #pragma unroll
    for (int off = 16; off > 0; off >>= 1)
        ss += __shfl_xor_sync(0xffffffffu, ss, off);
    __shared__ float red[8];
    if ((t & 31) == 0) red[t >> 5] = ss;
    __syncthreads();
    if (t < 32) {
        float s = (t < 8) ? red[t] : 0.f;
        #pragma unroll
        for (int off = 4; off > 0; off >>= 1)
            s += __shfl_xor_sync(0xffffffffu, s, off);
        if (t == 0) red[0] = s;
    }
    __syncthreads();
    float inv = 1.0f / sqrtf(red[0] * (1.0f / DMODEL) + 1e-6f);
    float o0 = v0 * inv * w[t];
    float o1 = v1 * inv * w[t + 256];
    float o2 = v2 * inv * w[t + 512];
    if (PERM) {
        y[aperm_off(row, t)]       = tf32f(o0);
        y[aperm_off(row, t + 256)] = tf32f(o1);
        y[aperm_off(row, t + 512)] = tf32f(o2);
    } else {
        float* yr = y + (size_t)row * DMODEL;
        yr[t] = o0; yr[t + 256] = o1; yr[t + 512] = o2;
    }
}

// ---------------------------------------------------------------------------
// RoPE on packed qkv (row-major): q heads at col h*64, k heads at 768+kvh*64
// ---------------------------------------------------------------------------
__global__ void __launch_bounds__(256) rope_packed(float* __restrict__ qkv)
{
    int idx = blockIdx.x * 256 + threadIdx.x;
    const int total = ROWS * 16 * 32;
    if (idx >= total) return;
    int i    = idx & 31;
    int hh   = (idx >> 5) & 15;
    int row  = idx >> 9;
    int s    = row & (SEQ - 1);
    float freq = (float)exp(-9.210340371976184 * ((double)i / 32.0));
    float ang = (float)s * freq;
    float sn, cs;
    sincosf(ang, &sn, &cs);
    int coff = (hh < 12) ? hh * 64 : 768 + (hh - 12) * 64;
    float* p = qkv + (size_t)row * QKVW + coff + 2 * i;
    float t0 = p[0], t1 = p[1];
    p[0] = t0 * cs - t1 * sn;
    p[1] = t0 * sn + t1 * cs;
}

// ---------------------------------------------------------------------------
// tf32 tensor-core GEMM on pre-permuted operands. M == 4096 always.
// 128x128x32 block tile, 256 threads (8 warps 2x4), warp tile 64x32.
// Tile load = contiguous copy (LDG.128 -> STS.128, conflict-free).
// MODE 0: C = AB                (row-major out)
// MODE 1: C = AB + R            (row-major out; R may alias C)
// MODE 2: interleaved (w0,w1) cols; writes silu(c0)*c1 A-PERMUTED (K=N/2)
// ---------------------------------------------------------------------------
template<int MODE>
__global__ void __launch_bounds__(256) tgemm_k(const float* __restrict__ Ap,
                                               const float* __restrict__ Bp,
                                               float* __restrict__ C,
                                               const float* __restrict__ R,
                                               int N, int K)
{
    __shared__ float As[4][8][32][4];    // 16 KB
    __shared__ float Bs[4][16][32][2];   // 16 KB

    int tid = threadIdx.x, lane = tid & 31, warp = tid >> 5;
    int wm = warp >> 2, wn = warp & 3;
    int m0 = blockIdx.y * 128, n0 = blockIdx.x * 128;

    float acc[4][4][4];
    #pragma unroll
    for (int a = 0; a < 4; a++)
        #pragma unroll
        for (int b = 0; b < 4; b++)
            #pragma unroll
            for (int c = 0; c < 4; c++) acc[a][b][c] = 0.f;

    const int k8n = N >> 3;
    // A copy: thread handles (p=ks, mt=warp, lane); contiguous 512B per (ks,mt)
    const float* Ag = Ap + (size_t)((m0 >> 4) + warp) * 128 + lane * 4;
    // B copy: thread handles (p=ks, nt=tid>>4, r=tid&15) -> 16B
    const float* Bg = Bp + (size_t)((n0 >> 3) + (tid >> 4)) * 64 + (tid & 15) * 4;

    float4* AsDst = (float4*)As + warp * 32 + lane;          // + p*256
    float4* BsDst = (float4*)Bs + (tid >> 4) * 16 + (tid & 15);  // + p*256

    float4 pa[4], pb[4];
    #pragma unroll
    for (int p = 0; p < 4; p++) {
        pa[p] = *(const float4*)(Ag + (size_t)p * 32768);
        pb[p] = *(const float4*)(Bg + (size_t)p * k8n * 64);
    }

    for (int k0 = 0; k0 < K; k0 += 32) {
        #pragma unroll
        for (int p = 0; p < 4; p++) {
            AsDst[p * 256] = pa[p];
            BsDst[p * 256] = pb[p];
        }
        __syncthreads();

        int kn8 = (k0 >> 3) + 4;
        if (k0 + 32 < K) {
            #pragma unroll
            for (int p = 0; p < 4; p++) {
                pa[p] = *(const float4*)(Ag + (size_t)(kn8 + p) * 32768);
                pb[p] = *(const float4*)(Bg + (size_t)(kn8 + p) * k8n * 64);
            }
        }

        #pragma unroll
        for (int ks = 0; ks < 4; ks++) {
            unsigned af[4][4], bf[4][2];
            #pragma unroll
            for (int mt = 0; mt < 4; mt++)
                *(uint4*)af[mt] = *(const uint4*)&As[ks][wm * 4 + mt][lane][0];
            #pragma unroll
            for (int nt = 0; nt < 4; nt++)
                *(uint2*)bf[nt] = *(const uint2*)&Bs[ks][wn * 4 + nt][lane][0];
            #pragma unroll
            for (int mt = 0; mt < 4; mt++)
                #pragma unroll
                for (int nt = 0; nt < 4; nt++)
                    mma8(acc[mt][nt], af[mt], bf[nt]);
        }
        __syncthreads();
    }

    // epilogue
    int g = lane >> 2, tg = lane & 3;
    #pragma unroll
    for (int mt = 0; mt < 4; mt++) {
        int row = m0 + wm * 64 + mt * 16 + g;
        #pragma unroll
        for (int nt = 0; nt < 4; nt++) {
            float* c = acc[mt][nt];
            if (MODE == 2) {
                int f = (n0 >> 1) + wn * 16 + nt * 4 + tg;
                float s0 = c[0] / (1.0f + expf(-c[0]));
                float s2 = c[2] / (1.0f + expf(-c[2]));
                C[aperm_off(row,     f)] = tf32f(s0 * c[1]);
                C[aperm_off(row + 8, f)] = tf32f(s2 * c[3]);
            } else {
                int col = n0 + wn * 32 + nt * 8 + tg * 2;
                size_t i0 = (size_t)row * N + col;
                size_t i1 = i0 + (size_t)8 * N;
                float2 v0 = make_float2(c[0], c[1]);
                float2 v1 = make_float2(c[2], c[3]);
                if (MODE == 1) {
                    v0.x += R[i0]; v0.y += R[i0 + 1];
                    v1.x += R[i1]; v1.y += R[i1 + 1];
                }
                *(float2*)&C[i0] = v0;
                *(float2*)&C[i1] = v1;
            }
        }
    }
}

// ---------------------------------------------------------------------------
// Flash attention (causal, GQA). Reads packed qkv (row stride 1280).
// Grid (S/64, H, B), 256 threads. BQ=64, BK=32, static smem.
// Epilogue writes A-fragment-permuted output (feeds Wo gemm).
// ---------------------------------------------------------------------------
__global__ void __launch_bounds__(256) flash_kernel(const float* __restrict__ qkv,
                                                    float* __restrict__ op)
{
    __shared__ float Qs[64][65];
    __shared__ float Ks[32][65];
    __shared__ float Vs[32][68];
    __shared__ float Ps[64][33];

    int qt = blockIdx.x, h = blockIdx.y, b = blockIdx.z;
    int kvh = h / NREP;
    int tid = threadIdx.x;
    int ty = tid >> 4, tx = tid & 15;
    int q0 = qt * 64;

    const float* qbase = qkv + (size_t)(b * SEQ + q0) * QKVW + h * HEADD;
    for (int i = tid; i < 64 * 64; i += 256) {
        int r = i >> 6, d = i & 63;
        Qs[r][d] = qbase[(size_t)r * QKVW + d];
    }

    float m[4], l[4], o_acc[4][4];
    #pragma unroll
    for (int i = 0; i < 4; i++) {
        m[i] = -INFINITY; l[i] = 0.f;
        #pragma unroll
        for (int j = 0; j < 4; j++) o_acc[i][j] = 0.f;
    }

    const float* kbase = qkv + (size_t)(b * SEQ) * QKVW + 768 + kvh * HEADD;
    const float* vbase = qkv + (size_t)(b * SEQ) * QKVW + 1024 + kvh * HEADD;

    int ntiles = 2 * qt + 2;
    for (int kt = 0; kt < ntiles; kt++) {
        __syncthreads();
        for (int i = tid; i < 32 * 64; i += 256) {
            int r = i >> 6, d = i & 63;
            size_t goff = (size_t)(kt * 32 + r) * QKVW + d;
            Ks[r][d] = kbase[goff];
            Vs[r][d] = vbase[goff];
        }
        __syncthreads();

        float s[4][2];
        #pragma unroll
        for (int i = 0; i < 4; i++) { s[i][0] = 0.f; s[i][1] = 0.f; }

        #pragma unroll 8
        for (int kk = 0; kk < 64; kk++) {
            float a[4], bb[2];
            #pragma unroll
            for (int i = 0; i < 4; i++) a[i] = Qs[ty * 4 + i][kk];
            bb[0] = Ks[tx * 2 + 0][kk];
            bb[1] = Ks[tx * 2 + 1][kk];
            #pragma unroll
            for (int i = 0; i < 4; i++) {
                s[i][0] = fmaf(a[i], bb[0], s[i][0]);
                s[i][1] = fmaf(a[i], bb[1], s[i][1]);
            }
        }

        #pragma unroll
        for (int i = 0; i < 4; i++) { s[i][0] *= 0.125f; s[i][1] *= 0.125f; }

        if (kt >= 2 * qt) {
            #pragma unroll
            for (int i = 0; i < 4; i++) {
                int qg = q0 + ty * 4 + i;
                int kg = kt * 32 + tx * 2;
                if (kg > qg)     s[i][0] = -INFINITY;
                if (kg + 1 > qg) s[i][1] = -INFINITY;
            }
        }

        #pragma unroll
        for (int i = 0; i < 4; i++) {
            float mx = fmaxf(s[i][0], s[i][1]);
            #pragma unroll
            for (int off = 8; off > 0; off >>= 1)
                mx = fmaxf(mx, __shfl_xor_sync(0xffffffffu, mx, off, 16));
            float mnew = fmaxf(m[i], mx);
            float p0 = expf(s[i][0] - mnew);
            float p1 = expf(s[i][1] - mnew);
            float sum = p0 + p1;
            #pragma unroll
            for (int off = 8; off > 0; off >>= 1)
                sum += __shfl_xor_sync(0xffffffffu, sum, off, 16);
            float alpha = expf(m[i] - mnew);
            l[i] = l[i] * alpha + sum;
            m[i] = mnew;
            #pragma unroll
            for (int j = 0; j < 4; j++) o_acc[i][j] *= alpha;
            int r = ty * 4 + i;
            Ps[r][tx * 2 + 0] = p0;
            Ps[r][tx * 2 + 1] = p1;
        }
        __syncthreads();

        #pragma unroll 8
        for (int kk = 0; kk < 32; kk++) {
            float p[4];
            #pragma unroll
            for (int i = 0; i < 4; i++) p[i] = Ps[ty * 4 + i][kk];
            float4 vv = *(float4*)&Vs[kk][tx * 4];
            #pragma unroll
            for (int i = 0; i < 4; i++) {
                o_acc[i][0] = fmaf(p[i], vv.x, o_acc[i][0]);
                o_acc[i][1] = fmaf(p[i], vv.y, o_acc[i][1]);
                o_acc[i][2] = fmaf(p[i], vv.z, o_acc[i][2]);
                o_acc[i][3] = fmaf(p[i], vv.w, o_acc[i][3]);
            }
        }
    }

    #pragma unroll
    for (int i = 0; i < 4; i++) {
        float invl = 1.0f / l[i];
        int mrow = b * SEQ + q0 + ty * 4 + i;
        #pragma unroll
        for (int j = 0; j < 4; j++) {
            int kcol = h * HEADD + tx * 4 + j;
            op[aperm_off(mrow, kcol)] = tf32f(o_acc[i][j] * invl);
        }
    }
}

// ---------------------------------------------------------------------------
// Launch sequence
// ---------------------------------------------------------------------------
extern "C" void kernel_launch(void* const* d_in, const int* in_sizes, int n_in,
                              void* d_out, int out_size)
{
    (void)in_sizes; (void)n_in; (void)out_size;
    const float* x_in = (const float*)d_in[0];
    const float* Wq   = (const float*)d_in[1];
    const float* Wk   = (const float*)d_in[2];
    const float* Wv   = (const float*)d_in[3];
    const float* Wo   = (const float*)d_in[4];
    const float* an_w = (const float*)d_in[5];
    const float* w0   = (const float*)d_in[6];
    const float* w1   = (const float*)d_in[7];
    const float* w2   = (const float*)d_in[8];
    const float* sn_w = (const float*)d_in[9];
    const float* on_w = (const float*)d_in[10];

    float *hp, *qkv, *attnp, *x, *ffp, *wqkvp, *w01p, *wop, *w2p;
    cudaGetSymbolAddress((void**)&hp,    g_hp);
    cudaGetSymbolAddress((void**)&qkv,   g_qkv);
    cudaGetSymbolAddress((void**)&attnp, g_attnp);
    cudaGetSymbolAddress((void**)&x,     g_x);
    cudaGetSymbolAddress((void**)&ffp,   g_ffp);
    cudaGetSymbolAddress((void**)&wqkvp, g_wqkvp);
    cudaGetSymbolAddress((void**)&w01p,  g_w01p);
    cudaGetSymbolAddress((void**)&wop,   g_wop);
    cudaGetSymbolAddress((void**)&w2p,   g_w2p);

    // pack weights into fragment order (captured; runs each replay, ~60us)
    pack_qkv_w<<<(LAYERS * DMODEL * QKVW / 2 + 255) / 256, 256>>>(Wq, Wk, Wv, wqkvp);
    pack_w01 <<<(LAYERS * DMODEL * 2 * FFDIM / 2 + 255) / 256, 256>>>(w0, w1, w01p);
    pack_w_gen<<<(LAYERS * DMODEL * DMODEL / 2 + 255) / 256, 256>>>(Wo, wop, DMODEL, DMODEL);
    pack_w_gen<<<(LAYERS * FFDIM * DMODEL / 2 + 255) / 256, 256>>>(w2, w2p, FFDIM, DMODEL);

    const float* cur = x_in;
    for (int li = 0; li < LAYERS; li++) {
        rmsnorm_k<1><<<ROWS, 256>>>(cur, an_w + (size_t)li * DMODEL, hp);

        // fused QKV projection: [4096,768] @ [768,1280] -> row-major qkv
        tgemm_k<0><<<dim3(QKVW / 128, ROWS / 128), 256>>>(
            hp, wqkvp + (size_t)li * DMODEL * QKVW, qkv, nullptr, QKVW, DMODEL);

        rope_packed<<<(ROWS * 16 * 32 + 255) / 256, 256>>>(qkv);

        flash_kernel<<<dim3(SEQ / 64, NHEADS, BATCH), 256>>>(qkv, attnp);

        // x = cur + attn @ Wo
        tgemm_k<1><<<dim3(DMODEL / 128, ROWS / 128), 256>>>(
            attnp, wop + (size_t)li * DMODEL * DMODEL, x, cur, DMODEL, DMODEL);

        rmsnorm_k<1><<<ROWS, 256>>>(x, sn_w + (size_t)li * DMODEL, hp);

        // ff = silu(h@w0)*(h@w1) -> permuted; N=6144 interleaved
        tgemm_k<2><<<dim3(2 * FFDIM / 128, ROWS / 128), 256>>>(
            hp, w01p + (size_t)li * DMODEL * 2 * FFDIM, ffp, nullptr, 2 * FFDIM, DMODEL);

        // x += ff @ w2
        tgemm_k<1><<<dim3(DMODEL / 128, ROWS / 128), 256>>>(
            ffp, w2p + (size_t)li * FFDIM * DMODEL, x, x, DMODEL, FFDIM);
        cur = x;
    }

    rmsnorm_k<0><<<ROWS, 256>>>(x, on_w, (float*)d_out);
}

// round 7
// speedup vs baseline: 3.3959x; 1.4270x over previous
#include <cuda_runtime.h>
#include <cuda_bf16.h>
#include <math.h>
#include <stdint.h>

// Problem constants
#define LAYERS 2
#define BATCH  2
#define SEQ    2048
#define DMODEL 768
#define NHEADS 12
#define KVHEADS 4
#define NREP   3
#define HEADD  64
#define FFDIM  3072
#define ROWS   (BATCH*SEQ)     // 4096
#define QKVW   1280            // 768 q + 256 k + 256 v

// ---------------------------------------------------------------------------
// Scratch (allocation-free: __device__ globals)
// ---------------------------------------------------------------------------
__device__ float g_hp[ROWS * DMODEL];        // rmsnorm out, A-fragment-permuted
__device__ float g_qkv[ROWS * QKVW];         // row-major (flash reads it)
__device__ float g_attnp[ROWS * DMODEL];     // attention out, A-permuted
__device__ float g_x[ROWS * DMODEL];         // residual stream, row-major
__device__ float g_ffp[ROWS * FFDIM];        // gated FFN intermediate, A-permuted
__device__ float g_wqkvp[LAYERS * DMODEL * QKVW];      // B-permuted weights
__device__ float g_w01p[LAYERS * DMODEL * 2 * FFDIM];
__device__ float g_wop[LAYERS * DMODEL * DMODEL];
__device__ float g_w2p[LAYERS * FFDIM * DMODEL];

// ---------------------------------------------------------------------------
// tf32 helpers + fragment-permuted offset maps (M is always ROWS=4096)
// A perm:  [k8][m16(256)][lane(32)][j(4)]  (m16 stride 128, k8 stride 32768)
//   lane = (m&7)*4 + (k&3),  j = ((m>>3)&1) + 2*((k>>2)&1)
// B perm:  [k8][n8(N/8)][lane(32)][kh(2)]
//   lane = (n&7)*4 + (k&3),  kh = (k>>2)&1
// ---------------------------------------------------------------------------
__device__ __forceinline__ unsigned f2tf(float x) {
    unsigned r; asm("cvt.rna.tf32.f32 %0, %1;" : "=r"(r) : "f"(x)); return r;
}
__device__ __forceinline__ float tf32f(float x) { return __uint_as_float(f2tf(x)); }

__device__ __forceinline__ size_t aperm_off(int m, int k) {
    return (size_t)(k >> 3) * 32768 + (size_t)(m >> 4) * 128
         + ((m & 7) * 4 + (k & 3)) * 4 + ((m >> 3) & 1) + 2 * ((k >> 2) & 1);
}

__device__ __forceinline__ void mma8(float* d, const unsigned* a, const unsigned* b) {
    asm volatile("mma.sync.aligned.m16n8k8.row.col.f32.tf32.tf32.f32 "
        "{%0,%1,%2,%3}, {%4,%5,%6,%7}, {%8,%9}, {%0,%1,%2,%3};"
        : "+f"(d[0]), "+f"(d[1]), "+f"(d[2]), "+f"(d[3])
        : "r"(a[0]), "r"(a[1]), "r"(a[2]), "r"(a[3]), "r"(b[0]), "r"(b[1]));
}

// ---------------------------------------------------------------------------
// Weight pack kernels: one thread per float2 (dst words 2q, 2q+1 = kh pair).
// ---------------------------------------------------------------------------
__device__ __forceinline__ void pack_coords(int q, int N, int& k, int& n, int& dw) {
    dw = 2 * q;
    int block = dw >> 6;
    int lane  = (dw & 63) >> 1;
    int n8cnt = N >> 3;
    int k8 = block / n8cnt, n8 = block - k8 * n8cnt;
    n = n8 * 8 + (lane >> 2);
    k = k8 * 8 + (lane & 3);
}

__global__ void __launch_bounds__(256) pack_qkv_w(const float* __restrict__ Wq,
                                                  const float* __restrict__ Wk,
                                                  const float* __restrict__ Wv,
                                                  float* __restrict__ dst)
{
    int p = blockIdx.x * 256 + threadIdx.x;
    const int perL = DMODEL * QKVW / 2;
    if (p >= LAYERS * perL) return;
    int l = p / perL, q = p - l * perL;
    int k, n, dw; pack_coords(q, QKVW, k, n, dw);
    float v0, v1;
    if (n < 768) {
        const float* s = Wq + ((size_t)l * DMODEL + k) * 768 + n;
        v0 = s[0]; v1 = s[4 * 768];
    } else if (n < 1024) {
        const float* s = Wk + ((size_t)l * DMODEL + k) * 256 + (n - 768);
        v0 = s[0]; v1 = s[4 * 256];
    } else {
        const float* s = Wv + ((size_t)l * DMODEL + k) * 256 + (n - 1024);
        v0 = s[0]; v1 = s[4 * 256];
    }
    float2 o; o.x = tf32f(v0); o.y = tf32f(v1);
    *(float2*)(dst + (size_t)l * DMODEL * QKVW + dw) = o;
}

__global__ void __launch_bounds__(256) pack_w01(const float* __restrict__ w0,
                                                const float* __restrict__ w1,
                                                float* __restrict__ dst)
{
    int p = blockIdx.x * 256 + threadIdx.x;
    const int perL = DMODEL * 2 * FFDIM / 2;
    if (p >= LAYERS * perL) return;
    int l = p / perL, q = p - l * perL;
    int k, n, dw; pack_coords(q, 2 * FFDIM, k, n, dw);
    int f = n >> 1;
    const float* s = ((n & 1) ? w1 : w0) + ((size_t)l * DMODEL + k) * FFDIM + f;
    float2 o; o.x = tf32f(s[0]); o.y = tf32f(s[4 * FFDIM]);
    *(float2*)(dst + (size_t)l * DMODEL * 2 * FFDIM + dw) = o;
}

__global__ void __launch_bounds__(256) pack_w_gen(const float* __restrict__ src,
                                                  float* __restrict__ dst,
                                                  int K, int N)
{
    int p = blockIdx.x * 256 + threadIdx.x;
    const int perL = (K * N) >> 1;
    if (p >= LAYERS * perL) return;
    int l = p / perL, q = p - l * perL;
    int k, n, dw; pack_coords(q, N, k, n, dw);
    const float* s = src + ((size_t)l * K + k) * N + n;
    float2 o; o.x = tf32f(s[0]); o.y = tf32f(s[(size_t)4 * N]);
    *(float2*)(dst + (size_t)l * K * N + dw) = o;
}

// ---------------------------------------------------------------------------
// RMSNorm: one block per row of 768. PERM=1 -> write A-fragment-permuted+tf32
// ---------------------------------------------------------------------------
template<int PERM>
__global__ void __launch_bounds__(256) rmsnorm_k(const float* __restrict__ x,
                                                 const float* __restrict__ w,
                                                 float* __restrict__ y)
{
    int row = blockIdx.x;
    const float* xr = x + (size_t)row * DMODEL;
    int t = threadIdx.x;
    float v0 = xr[t], v1 = xr[t + 256], v2 = xr[t + 512];
    float ss = v0*v0 + v1*v1 + v2*v2;
    #pragma unroll
    for (int off = 16; off > 0; off >>= 1)
        ss += __shfl_xor_sync(0xffffffffu, ss, off);
    __shared__ float red[8];
    if ((t & 31) == 0) red[t >> 5] = ss;
    __syncthreads();
    if (t < 32) {
        float s = (t < 8) ? red[t] : 0.f;
        #pragma unroll
        for (int off = 4; off > 0; off >>= 1)
            s += __shfl_xor_sync(0xffffffffu, s, off);
        if (t == 0) red[0] = s;
    }
    __syncthreads();
    float inv = 1.0f / sqrtf(red[0] * (1.0f / DMODEL) + 1e-6f);
    float o0 = v0 * inv * w[t];
    float o1 = v1 * inv * w[t + 256];
    float o2 = v2 * inv * w[t + 512];
    if (PERM) {
        y[aperm_off(row, t)]       = tf32f(o0);
        y[aperm_off(row, t + 256)] = tf32f(o1);
        y[aperm_off(row, t + 512)] = tf32f(o2);
    } else {
        float* yr = y + (size_t)row * DMODEL;
        yr[t] = o0; yr[t + 256] = o1; yr[t + 512] = o2;
    }
}

// ---------------------------------------------------------------------------
// RoPE on packed qkv (row-major): q heads at col h*64, k heads at 768+kvh*64
// ---------------------------------------------------------------------------
__global__ void __launch_bounds__(256) rope_packed(float* __restrict__ qkv)
{
    int idx = blockIdx.x * 256 + threadIdx.x;
    const int total = ROWS * 16 * 32;
    if (idx >= total) return;
    int i    = idx & 31;
    int hh   = (idx >> 5) & 15;
    int row  = idx >> 9;
    int s    = row & (SEQ - 1);
    float freq = (float)exp(-9.210340371976184 * ((double)i / 32.0));
    float ang = (float)s * freq;
    float sn, cs;
    sincosf(ang, &sn, &cs);
    int coff = (hh < 12) ? hh * 64 : 768 + (hh - 12) * 64;
    float* p = qkv + (size_t)row * QKVW + coff + 2 * i;
    float t0 = p[0], t1 = p[1];
    p[0] = t0 * cs - t1 * sn;
    p[1] = t0 * sn + t1 * cs;
}

// ---------------------------------------------------------------------------
// tf32 tensor-core GEMM on pre-permuted operands. M == 4096 always.
// ---------------------------------------------------------------------------
template<int MODE>
__global__ void __launch_bounds__(256) tgemm_k(const float* __restrict__ Ap,
                                               const float* __restrict__ Bp,
                                               float* __restrict__ C,
                                               const float* __restrict__ R,
                                               int N, int K)
{
    __shared__ float As[4][8][32][4];    // 16 KB
    __shared__ float Bs[4][16][32][2];   // 16 KB

    int tid = threadIdx.x, lane = tid & 31, warp = tid >> 5;
    int wm = warp >> 2, wn = warp & 3;
    int m0 = blockIdx.y * 128, n0 = blockIdx.x * 128;

    float acc[4][4][4];
    #pragma unroll
    for (int a = 0; a < 4; a++)
        #pragma unroll
        for (int b = 0; b < 4; b++)
            #pragma unroll
            for (int c = 0; c < 4; c++) acc[a][b][c] = 0.f;

    const int k8n = N >> 3;
    const float* Ag = Ap + (size_t)((m0 >> 4) + warp) * 128 + lane * 4;
    const float* Bg = Bp + (size_t)((n0 >> 3) + (tid >> 4)) * 64 + (tid & 15) * 4;

    float4* AsDst = (float4*)As + warp * 32 + lane;
    float4* BsDst = (float4*)Bs + (tid >> 4) * 16 + (tid & 15);

    float4 pa[4], pb[4];
    #pragma unroll
    for (int p = 0; p < 4; p++) {
        pa[p] = *(const float4*)(Ag + (size_t)p * 32768);
        pb[p] = *(const float4*)(Bg + (size_t)p * k8n * 64);
    }

    for (int k0 = 0; k0 < K; k0 += 32) {
        #pragma unroll
        for (int p = 0; p < 4; p++) {
            AsDst[p * 256] = pa[p];
            BsDst[p * 256] = pb[p];
        }
        __syncthreads();

        int kn8 = (k0 >> 3) + 4;
        if (k0 + 32 < K) {
            #pragma unroll
            for (int p = 0; p < 4; p++) {
                pa[p] = *(const float4*)(Ag + (size_t)(kn8 + p) * 32768);
                pb[p] = *(const float4*)(Bg + (size_t)(kn8 + p) * k8n * 64);
            }
        }

        #pragma unroll
        for (int ks = 0; ks < 4; ks++) {
            unsigned af[4][4], bf[4][2];
            #pragma unroll
            for (int mt = 0; mt < 4; mt++)
                *(uint4*)af[mt] = *(const uint4*)&As[ks][wm * 4 + mt][lane][0];
            #pragma unroll
            for (int nt = 0; nt < 4; nt++)
                *(uint2*)bf[nt] = *(const uint2*)&Bs[ks][wn * 4 + nt][lane][0];
            #pragma unroll
            for (int mt = 0; mt < 4; mt++)
                #pragma unroll
                for (int nt = 0; nt < 4; nt++)
                    mma8(acc[mt][nt], af[mt], bf[nt]);
        }
        __syncthreads();
    }

    int g = lane >> 2, tg = lane & 3;
    #pragma unroll
    for (int mt = 0; mt < 4; mt++) {
        int row = m0 + wm * 64 + mt * 16 + g;
        #pragma unroll
        for (int nt = 0; nt < 4; nt++) {
            float* c = acc[mt][nt];
            if (MODE == 2) {
                int f = (n0 >> 1) + wn * 16 + nt * 4 + tg;
                float s0 = c[0] / (1.0f + __expf(-c[0]));
                float s2 = c[2] / (1.0f + __expf(-c[2]));
                C[aperm_off(row,     f)] = tf32f(s0 * c[1]);
                C[aperm_off(row + 8, f)] = tf32f(s2 * c[3]);
            } else {
                int col = n0 + wn * 32 + nt * 8 + tg * 2;
                size_t i0 = (size_t)row * N + col;
                size_t i1 = i0 + (size_t)8 * N;
                float2 v0 = make_float2(c[0], c[1]);
                float2 v1 = make_float2(c[2], c[3]);
                if (MODE == 1) {
                    v0.x += R[i0]; v0.y += R[i0 + 1];
                    v1.x += R[i1]; v1.y += R[i1 + 1];
                }
                *(float2*)&C[i0] = v0;
                *(float2*)&C[i1] = v1;
            }
        }
    }
}

// ---------------------------------------------------------------------------
// Tensor-core flash attention (causal, GQA). 128 threads = 4 warps;
// warp w owns q-rows [w*16, w*16+16) for ALL keys -> softmax stays in-warp.
// BQ=64, BK=32. All smem tiles stored in mma fragment order. 40KB static.
// Output written A-fragment-permuted (feeds the Wo GEMM).
// ---------------------------------------------------------------------------
__global__ void __launch_bounds__(128) flash_kernel(const float* __restrict__ qkv,
                                                    float* __restrict__ op)
{
    __shared__ float Qs[8][4][32][4];   // A-frag: [dim8][m16][lane][j]   16KB
    __shared__ float Ks[8][4][32][2];   // B-frag: [dim8][key8][lane][kh]  8KB
    __shared__ float Vs[4][8][32][2];   // B-frag: [key8][dim8][lane][kh]  8KB
    __shared__ float Ps[4][4][32][4];   // A-frag: [key8][m16][lane][j]    8KB

    int qt = blockIdx.x, h = blockIdx.y, b = blockIdx.z;
    int kvh = h / NREP;
    int tid = threadIdx.x, lane = tid & 31, warp = tid >> 5;
    int g = lane >> 2, tg = lane & 3;
    int q0 = qt * 64;

    // Load Q once: 64x64, convert + fragment-permute
    const float* qbase = qkv + (size_t)(b * SEQ + q0) * QKVW + h * HEADD;
    for (int i = tid; i < 64 * 64; i += 128) {
        int r = i >> 6, d = i & 63;
        Qs[d >> 3][r >> 4][(r & 7) * 4 + (d & 3)][((r >> 3) & 1) + 2 * ((d >> 2) & 1)]
            = tf32f(qbase[(size_t)r * QKVW + d]);
    }

    float mr0 = -INFINITY, mr1 = -INFINITY, l0 = 0.f, l1 = 0.f;
    float o_acc[8][4];
    #pragma unroll
    for (int nt = 0; nt < 8; nt++)
        #pragma unroll
        for (int c = 0; c < 4; c++) o_acc[nt][c] = 0.f;

    const float* kbase = qkv + (size_t)(b * SEQ) * QKVW + 768 + kvh * HEADD;
    const float* vbase = qkv + (size_t)(b * SEQ) * QKVW + 1024 + kvh * HEADD;

    int ntiles = 2 * qt + 2;
    for (int kt = 0; kt < ntiles; kt++) {
        __syncthreads();
        for (int i = tid; i < 32 * 64; i += 128) {
            int r = i >> 6, d = i & 63;   // r=key 0..31, d=dim 0..63
            size_t goff = (size_t)(kt * 32 + r) * QKVW + d;
            Ks[d >> 3][r >> 3][(r & 7) * 4 + (d & 3)][(d >> 2) & 1] = tf32f(kbase[goff]);
            Vs[r >> 3][d >> 3][(d & 7) * 4 + (r & 3)][(r >> 2) & 1] = tf32f(vbase[goff]);
        }
        __syncthreads();

        // S = Q @ K^T : warp computes its 16 rows x 32 keys
        float s[4][4];
        #pragma unroll
        for (int nt = 0; nt < 4; nt++)
            #pragma unroll
            for (int c = 0; c < 4; c++) s[nt][c] = 0.f;

        #pragma unroll
        for (int ks = 0; ks < 8; ks++) {
            unsigned af[4];
            *(uint4*)af = *(const uint4*)&Qs[ks][warp][lane][0];
            #pragma unroll
            for (int nt = 0; nt < 4; nt++) {
                unsigned bf[2];
                *(uint2*)bf = *(const uint2*)&Ks[ks][nt][lane][0];
                mma8(s[nt], af, bf);
            }
        }
        #pragma unroll
        for (int nt = 0; nt < 4; nt++)
            #pragma unroll
            for (int c = 0; c < 4; c++) s[nt][c] *= 0.125f;

        // Causal mask (only tiles overlapping the diagonal)
        if (kt >= 2 * qt) {
            int qg0 = q0 + warp * 16 + g;
            int qg1 = qg0 + 8;
            #pragma unroll
            for (int nt = 0; nt < 4; nt++) {
                int kg = kt * 32 + nt * 8 + tg * 2;
                if (kg > qg0)     s[nt][0] = -INFINITY;
                if (kg + 1 > qg0) s[nt][1] = -INFINITY;
                if (kg > qg1)     s[nt][2] = -INFINITY;
                if (kg + 1 > qg1) s[nt][3] = -INFINITY;
            }
        }

        // Online softmax: rows g (c0,c1) and g+8 (c2,c3); quad reduce over tg
        float mx0 = -INFINITY, mx1 = -INFINITY;
        #pragma unroll
        for (int nt = 0; nt < 4; nt++) {
            mx0 = fmaxf(mx0, fmaxf(s[nt][0], s[nt][1]));
            mx1 = fmaxf(mx1, fmaxf(s[nt][2], s[nt][3]));
        }
        mx0 = fmaxf(mx0, __shfl_xor_sync(0xffffffffu, mx0, 1));
        mx0 = fmaxf(mx0, __shfl_xor_sync(0xffffffffu, mx0, 2));
        mx1 = fmaxf(mx1, __shfl_xor_sync(0xffffffffu, mx1, 1));
        mx1 = fmaxf(mx1, __shfl_xor_sync(0xffffffffu, mx1, 2));
        float mn0 = fmaxf(mr0, mx0), mn1 = fmaxf(mr1, mx1);
        float sum0 = 0.f, sum1 = 0.f;
        #pragma unroll
        for (int nt = 0; nt < 4; nt++) {
            s[nt][0] = __expf(s[nt][0] - mn0);
            s[nt][1] = __expf(s[nt][1] - mn0);
            s[nt][2] = __expf(s[nt][2] - mn1);
            s[nt][3] = __expf(s[nt][3] - mn1);
            sum0 += s[nt][0] + s[nt][1];
            sum1 += s[nt][2] + s[nt][3];
        }
        sum0 += __shfl_xor_sync(0xffffffffu, sum0, 1);
        sum0 += __shfl_xor_sync(0xffffffffu, sum0, 2);
        sum1 += __shfl_xor_sync(0xffffffffu, sum1, 1);
        sum1 += __shfl_xor_sync(0xffffffffu, sum1, 2);
        float a0 = __expf(mr0 - mn0), a1 = __expf(mr1 - mn1);
        l0 = l0 * a0 + sum0;  l1 = l1 * a1 + sum1;
        mr0 = mn0;  mr1 = mn1;
        #pragma unroll
        for (int nt = 0; nt < 8; nt++) {
            o_acc[nt][0] *= a0; o_acc[nt][1] *= a0;
            o_acc[nt][2] *= a1; o_acc[nt][3] *= a1;
        }

        // Store P (tf32) into A-frag layout; each warp writes only its m-tile
        {
            int k0i = (2 * tg) & 3;
            int k1i = (2 * tg + 1) & 3;
            int jb  = 2 * (tg >> 1);     // kh bit of key
            #pragma unroll
            for (int nt = 0; nt < 4; nt++) {
                Ps[nt][warp][g * 4 + k0i][jb]     = tf32f(s[nt][0]);
                Ps[nt][warp][g * 4 + k1i][jb]     = tf32f(s[nt][1]);
                Ps[nt][warp][g * 4 + k0i][1 + jb] = tf32f(s[nt][2]);
                Ps[nt][warp][g * 4 + k1i][1 + jb] = tf32f(s[nt][3]);
            }
        }
        __syncwarp();

        // O += P @ V
        #pragma unroll
        for (int kks = 0; kks < 4; kks++) {
            unsigned af[4];
            *(uint4*)af = *(const uint4*)&Ps[kks][warp][lane][0];
            #pragma unroll
            for (int nt = 0; nt < 8; nt++) {
                unsigned bf[2];
                *(uint2*)bf = *(const uint2*)&Vs[kks][nt][lane][0];
                mma8(o_acc[nt], af, bf);
            }
        }
        __syncwarp();
    }

    // Write output, A-fragment-permuted
    float inv0 = 1.0f / l0, inv1 = 1.0f / l1;
    int mrow = b * SEQ + q0 + warp * 16 + g;
    #pragma unroll
    for (int nt = 0; nt < 8; nt++) {
        int col = h * HEADD + nt * 8 + tg * 2;
        op[aperm_off(mrow,     col)]     = tf32f(o_acc[nt][0] * inv0);
        op[aperm_off(mrow,     col + 1)] = tf32f(o_acc[nt][1] * inv0);
        op[aperm_off(mrow + 8, col)]     = tf32f(o_acc[nt][2] * inv1);
        op[aperm_off(mrow + 8, col + 1)] = tf32f(o_acc[nt][3] * inv1);
    }
}

// ---------------------------------------------------------------------------
// Launch sequence
// ---------------------------------------------------------------------------
extern "C" void kernel_launch(void* const* d_in, const int* in_sizes, int n_in,
                              void* d_out, int out_size)
{
    (void)in_sizes; (void)n_in; (void)out_size;
    const float* x_in = (const float*)d_in[0];
    const float* Wq   = (const float*)d_in[1];
    const float* Wk   = (const float*)d_in[2];
    const float* Wv   = (const float*)d_in[3];
    const float* Wo   = (const float*)d_in[4];
    const float* an_w = (const float*)d_in[5];
    const float* w0   = (const float*)d_in[6];
    const float* w1   = (const float*)d_in[7];
    const float* w2   = (const float*)d_in[8];
    const float* sn_w = (const float*)d_in[9];
    const float* on_w = (const float*)d_in[10];

    float *hp, *qkv, *attnp, *x, *ffp, *wqkvp, *w01p, *wop, *w2p;
    cudaGetSymbolAddress((void**)&hp,    g_hp);
    cudaGetSymbolAddress((void**)&qkv,   g_qkv);
    cudaGetSymbolAddress((void**)&attnp, g_attnp);
    cudaGetSymbolAddress((void**)&x,     g_x);
    cudaGetSymbolAddress((void**)&ffp,   g_ffp);
    cudaGetSymbolAddress((void**)&wqkvp, g_wqkvp);
    cudaGetSymbolAddress((void**)&w01p,  g_w01p);
    cudaGetSymbolAddress((void**)&wop,   g_wop);
    cudaGetSymbolAddress((void**)&w2p,   g_w2p);

    // pack weights into fragment order (captured; runs each replay, ~60us)
    pack_qkv_w<<<(LAYERS * DMODEL * QKVW / 2 + 255) / 256, 256>>>(Wq, Wk, Wv, wqkvp);
    pack_w01 <<<(LAYERS * DMODEL * 2 * FFDIM / 2 + 255) / 256, 256>>>(w0, w1, w01p);
    pack_w_gen<<<(LAYERS * DMODEL * DMODEL / 2 + 255) / 256, 256>>>(Wo, wop, DMODEL, DMODEL);
    pack_w_gen<<<(LAYERS * FFDIM * DMODEL / 2 + 255) / 256, 256>>>(w2, w2p, FFDIM, DMODEL);

    const float* cur = x_in;
    for (int li = 0; li < LAYERS; li++) {
        rmsnorm_k<1><<<ROWS, 256>>>(cur, an_w + (size_t)li * DMODEL, hp);

        tgemm_k<0><<<dim3(QKVW / 128, ROWS / 128), 256>>>(
            hp, wqkvp + (size_t)li * DMODEL * QKVW, qkv, nullptr, QKVW, DMODEL);

        rope_packed<<<(ROWS * 16 * 32 + 255) / 256, 256>>>(qkv);

        flash_kernel<<<dim3(SEQ / 64, NHEADS, BATCH), 128>>>(qkv, attnp);

        tgemm_k<1><<<dim3(DMODEL / 128, ROWS / 128), 256>>>(
            attnp, wop + (size_t)li * DMODEL * DMODEL, x, cur, DMODEL, DMODEL);

        rmsnorm_k<1><<<ROWS, 256>>>(x, sn_w + (size_t)li * DMODEL, hp);

        tgemm_k<2><<<dim3(2 * FFDIM / 128, ROWS / 128), 256>>>(
            hp, w01p + (size_t)li * DMODEL * 2 * FFDIM, ffp, nullptr, 2 * FFDIM, DMODEL);

        tgemm_k<1><<<dim3(DMODEL / 128, ROWS / 128), 256>>>(
            ffp, w2p + (size_t)li * FFDIM * DMODEL, x, x, DMODEL, FFDIM);
        cur = x;
    }

    rmsnorm_k<0><<<ROWS, 256>>>(x, on_w, (float*)d_out);
}

// round 10
// speedup vs baseline: 4.0648x; 1.1969x over previous
#include <cuda_runtime.h>
#include <cuda_bf16.h>
#include <math.h>
#include <stdint.h>

// Problem constants
#define LAYERS 2
#define BATCH  2
#define SEQ    2048
#define DMODEL 768
#define NHEADS 12
#define KVHEADS 4
#define NREP   3
#define HEADD  64
#define FFDIM  3072
#define ROWS   (BATCH*SEQ)     // 4096
#define QKVW   1280            // 768 q + 256 k + 256 v

// ---------------------------------------------------------------------------
// Scratch (allocation-free: __device__ globals)
// Attention side = bf16, FFN side = tf32.
// ---------------------------------------------------------------------------
__device__ __nv_bfloat16 g_hp16[ROWS * DMODEL];    // rmsnorm out, bf16 A-perm
__device__ float         g_hp32[ROWS * DMODEL];    // rmsnorm out, tf32 A-perm
__device__ float         g_qkv[ROWS * QKVW];       // row-major fp32
__device__ __nv_bfloat16 g_attnp[ROWS * DMODEL];   // attention out, bf16 A-perm
__device__ float         g_x[ROWS * DMODEL];       // residual stream fp32
__device__ float         g_ffp[ROWS * FFDIM];      // FFN intermediate, tf32 A-perm
__device__ unsigned g_wqkvp[LAYERS * DMODEL * QKVW / 2];   // bf16 B-perm words
__device__ unsigned g_wop[LAYERS * DMODEL * DMODEL / 2];   // bf16 B-perm words
__device__ float    g_w01p[LAYERS * DMODEL * 2 * FFDIM];   // tf32 B-perm
__device__ float    g_w2p[LAYERS * FFDIM * DMODEL];        // tf32 B-perm

// ---------------------------------------------------------------------------
// tf32 helpers (m16n8k8)
// ---------------------------------------------------------------------------
__device__ __forceinline__ unsigned f2tf(float x) {
    unsigned r; asm("cvt.rna.tf32.f32 %0, %1;" : "=r"(r) : "f"(x)); return r;
}
__device__ __forceinline__ float tf32f(float x) { return __uint_as_float(f2tf(x)); }

__device__ __forceinline__ size_t aperm_off32(int m, int k) {
    return (size_t)(k >> 3) * 32768 + (size_t)(m >> 4) * 128
         + ((m & 7) * 4 + (k & 3)) * 4 + ((m >> 3) & 1) + 2 * ((k >> 2) & 1);
}

__device__ __forceinline__ void mma8(float* d, const unsigned* a, const unsigned* b) {
    asm volatile("mma.sync.aligned.m16n8k8.row.col.f32.tf32.tf32.f32 "
        "{%0,%1,%2,%3}, {%4,%5,%6,%7}, {%8,%9}, {%0,%1,%2,%3};"
        : "+f"(d[0]), "+f"(d[1]), "+f"(d[2]), "+f"(d[3])
        : "r"(a[0]), "r"(a[1]), "r"(a[2]), "r"(a[3]), "r"(b[0]), "r"(b[1]));
}

// ---------------------------------------------------------------------------
// bf16 helpers (m16n8k16)
// ---------------------------------------------------------------------------
__device__ __forceinline__ unsigned pack_bf16(float lo, float hi) {
    __nv_bfloat162 t = __floats2bfloat162_rn(lo, hi);
    return *reinterpret_cast<unsigned*>(&t);
}

__device__ __forceinline__ size_t aperm_off16(int m, int k) {  // element offset
    return (size_t)(k >> 4) * 65536 + (size_t)(m >> 4) * 256
         + ((m & 7) * 4 + ((k >> 1) & 3)) * 8
         + (((m >> 3) & 1) + 2 * ((k >> 3) & 1)) * 2 + (k & 1);
}
__device__ __forceinline__ size_t aperm_woff16(int m, int k) { // word offset, k even
    return (size_t)(k >> 4) * 32768 + (size_t)(m >> 4) * 128
         + ((m & 7) * 4 + ((k >> 1) & 3)) * 4
         + ((m >> 3) & 1) + 2 * ((k >> 3) & 1);
}

__device__ __forceinline__ void mma16(float* d, const unsigned* a, const unsigned* b) {
    asm volatile("mma.sync.aligned.m16n8k16.row.col.f32.bf16.bf16.f32 "
        "{%0,%1,%2,%3}, {%4,%5,%6,%7}, {%8,%9}, {%0,%1,%2,%3};"
        : "+f"(d[0]), "+f"(d[1]), "+f"(d[2]), "+f"(d[3])
        : "r"(a[0]), "r"(a[1]), "r"(a[2]), "r"(a[3]), "r"(b[0]), "r"(b[1]));
}

// ---------------------------------------------------------------------------
// Weight packing — bf16 (QKV, Wo)
// ---------------------------------------------------------------------------
__device__ __forceinline__ void pack_coords16(int dw, int N, int& kbase, int& n) {
    int j  = dw & 1;
    int ln = (dw >> 1) & 31;
    int blk = dw >> 6;
    int n8cnt = N >> 3;
    int k16 = blk / n8cnt, n8 = blk - k16 * n8cnt;
    n = n8 * 8 + (ln >> 2);
    kbase = k16 * 16 + j * 8 + (ln & 3) * 2;
}

__global__ void __launch_bounds__(256) pack_qkv_w16(const float* __restrict__ Wq,
                                                    const float* __restrict__ Wk,
                                                    const float* __restrict__ Wv,
                                                    unsigned* __restrict__ dst)
{
    int p = blockIdx.x * 256 + threadIdx.x;
    const int perL = DMODEL * QKVW / 2;
    if (p >= LAYERS * perL) return;
    int l = p / perL, dw = p - l * perL;
    int k, n; pack_coords16(dw, QKVW, k, n);
    float v0, v1;
    if (n < 768) {
        const float* s = Wq + ((size_t)l * DMODEL + k) * 768 + n;
        v0 = s[0]; v1 = s[768];
    } else if (n < 1024) {
        const float* s = Wk + ((size_t)l * DMODEL + k) * 256 + (n - 768);
        v0 = s[0]; v1 = s[256];
    } else {
        const float* s = Wv + ((size_t)l * DMODEL + k) * 256 + (n - 1024);
        v0 = s[0]; v1 = s[256];
    }
    dst[(size_t)l * perL + dw] = pack_bf16(v0, v1);
}

__global__ void __launch_bounds__(256) pack_w_gen16(const float* __restrict__ src,
                                                    unsigned* __restrict__ dst,
                                                    int K, int N)
{
    int p = blockIdx.x * 256 + threadIdx.x;
    const int perL = (K * N) >> 1;
    if (p >= LAYERS * perL) return;
    int l = p / perL, dw = p - l * perL;
    int k, n; pack_coords16(dw, N, k, n);
    const float* s = src + ((size_t)l * K + k) * N + n;
    dst[(size_t)l * perL + dw] = pack_bf16(s[0], s[N]);
}

// ---------------------------------------------------------------------------
// Weight packing — tf32 (w01 interleaved, w2)
// ---------------------------------------------------------------------------
__device__ __forceinline__ void pack_coords32(int q, int N, int& k, int& n, int& dw) {
    dw = 2 * q;
    int block = dw >> 6;
    int lane  = (dw & 63) >> 1;
    int n8cnt = N >> 3;
    int k8 = block / n8cnt, n8 = block - k8 * n8cnt;
    n = n8 * 8 + (lane >> 2);
    k = k8 * 8 + (lane & 3);
}

__global__ void __launch_bounds__(256) pack_w01_32(const float* __restrict__ w0,
                                                   const float* __restrict__ w1,
                                                   float* __restrict__ dst)
{
    int p = blockIdx.x * 256 + threadIdx.x;
    const int perL = DMODEL * 2 * FFDIM / 2;
    if (p >= LAYERS * perL) return;
    int l = p / perL, q = p - l * perL;
    int k, n, dw; pack_coords32(q, 2 * FFDIM, k, n, dw);
    int f = n >> 1;
    const float* s = ((n & 1) ? w1 : w0) + ((size_t)l * DMODEL + k) * FFDIM + f;
    float2 o; o.x = tf32f(s[0]); o.y = tf32f(s[4 * FFDIM]);
    *(float2*)(dst + (size_t)l * DMODEL * 2 * FFDIM + dw) = o;
}

__global__ void __launch_bounds__(256) pack_w_gen32(const float* __restrict__ src,
                                                    float* __restrict__ dst,
                                                    int K, int N)
{
    int p = blockIdx.x * 256 + threadIdx.x;
    const int perL = (K * N) >> 1;
    if (p >= LAYERS * perL) return;
    int l = p / perL, q = p - l * perL;
    int k, n, dw; pack_coords32(q, N, k, n, dw);
    const float* s = src + ((size_t)l * K + k) * N + n;
    float2 o; o.x = tf32f(s[0]); o.y = tf32f(s[(size_t)4 * N]);
    *(float2*)(dst + (size_t)l * K * N + dw) = o;
}

// ---------------------------------------------------------------------------
// RMSNorm: PERM 0 = fp32 row-major, 1 = tf32 A-perm, 2 = bf16 A-perm
// ---------------------------------------------------------------------------
template<int PERM>
__global__ void __launch_bounds__(256) rmsnorm_k(const float* __restrict__ x,
                                                 const float* __restrict__ w,
                                                 void* __restrict__ yv)
{
    int row = blockIdx.x;
    const float* xr = x + (size_t)row * DMODEL;
    int t = threadIdx.x;
    float v0 = xr[t], v1 = xr[t + 256], v2 = xr[t + 512];
    float ss = v0*v0 + v1*v1 + v2*v2;
    #pragma unroll
    for (int off = 16; off > 0; off >>= 1)
        ss += __shfl_xor_sync(0xffffffffu, ss, off);
    __shared__ float red[8];
    if ((t & 31) == 0) red[t >> 5] = ss;
    __syncthreads();
    if (t < 32) {
        float s = (t < 8) ? red[t] : 0.f;
        #pragma unroll
        for (int off = 4; off > 0; off >>= 1)
            s += __shfl_xor_sync(0xffffffffu, s, off);
        if (t == 0) red[0] = s;
    }
    __syncthreads();
    float inv = 1.0f / sqrtf(red[0] * (1.0f / DMODEL) + 1e-6f);
    float o0 = v0 * inv * w[t];
    float o1 = v1 * inv * w[t + 256];
    float o2 = v2 * inv * w[t + 512];
    if (PERM == 1) {
        float* y = (float*)yv;
        y[aperm_off32(row, t)]       = tf32f(o0);
        y[aperm_off32(row, t + 256)] = tf32f(o1);
        y[aperm_off32(row, t + 512)] = tf32f(o2);
    } else if (PERM == 2) {
        __nv_bfloat16* y = (__nv_bfloat16*)yv;
        y[aperm_off16(row, t)]       = __float2bfloat16(o0);
        y[aperm_off16(row, t + 256)] = __float2bfloat16(o1);
        y[aperm_off16(row, t + 512)] = __float2bfloat16(o2);
    } else {
        float* yr = (float*)yv + (size_t)row * DMODEL;
        yr[t] = o0; yr[t + 256] = o1; yr[t + 512] = o2;
    }
}

// ---------------------------------------------------------------------------
// RoPE on packed qkv (row-major fp32)
// ---------------------------------------------------------------------------
__global__ void __launch_bounds__(256) rope_packed(float* __restrict__ qkv)
{
    int idx = blockIdx.x * 256 + threadIdx.x;
    const int total = ROWS * 16 * 32;
    if (idx >= total) return;
    int i    = idx & 31;
    int hh   = (idx >> 5) & 15;
    int row  = idx >> 9;
    int s    = row & (SEQ - 1);
    float freq = (float)exp(-9.210340371976184 * ((double)i / 32.0));
    float ang = (float)s * freq;
    float sn, cs;
    sincosf(ang, &sn, &cs);
    int coff = (hh < 12) ? hh * 64 : 768 + (hh - 12) * 64;
    float* p = qkv + (size_t)row * QKVW + coff + 2 * i;
    float t0 = p[0], t1 = p[1];
    p[0] = t0 * cs - t1 * sn;
    p[1] = t0 * sn + t1 * cs;
}

// ---------------------------------------------------------------------------
// tf32 GEMM (pre-permuted). MODE 1: C=AB+R fp32; MODE 2: gated silu -> tf32
// A-perm out (K'=N/2). FFN path. (R7 datapath, verified.)
// ---------------------------------------------------------------------------
template<int MODE>
__global__ void __launch_bounds__(256) tgemm32_k(const float* __restrict__ Ap,
                                                 const float* __restrict__ Bp,
                                                 float* __restrict__ C,
                                                 const float* __restrict__ R,
                                                 int N, int K)
{
    __shared__ float As[4][8][32][4];
    __shared__ float Bs[4][16][32][2];

    int tid = threadIdx.x, lane = tid & 31, warp = tid >> 5;
    int wm = warp >> 2, wn = warp & 3;
    int m0 = blockIdx.y * 128, n0 = blockIdx.x * 128;

    float acc[4][4][4];
    #pragma unroll
    for (int a = 0; a < 4; a++)
        #pragma unroll
        for (int b = 0; b < 4; b++)
            #pragma unroll
            for (int c = 0; c < 4; c++) acc[a][b][c] = 0.f;

    const int k8n = N >> 3;
    const float* Ag = Ap + (size_t)((m0 >> 4) + warp) * 128 + lane * 4;
    const float* Bg = Bp + (size_t)((n0 >> 3) + (tid >> 4)) * 64 + (tid & 15) * 4;

    float4* AsDst = (float4*)As + warp * 32 + lane;
    float4* BsDst = (float4*)Bs + (tid >> 4) * 16 + (tid & 15);

    float4 pa[4], pb[4];
    #pragma unroll
    for (int p = 0; p < 4; p++) {
        pa[p] = *(const float4*)(Ag + (size_t)p * 32768);
        pb[p] = *(const float4*)(Bg + (size_t)p * k8n * 64);
    }

    for (int k0 = 0; k0 < K; k0 += 32) {
        #pragma unroll
        for (int p = 0; p < 4; p++) {
            AsDst[p * 256] = pa[p];
            BsDst[p * 256] = pb[p];
        }
        __syncthreads();

        int kn8 = (k0 >> 3) + 4;
        if (k0 + 32 < K) {
            #pragma unroll
            for (int p = 0; p < 4; p++) {
                pa[p] = *(const float4*)(Ag + (size_t)(kn8 + p) * 32768);
                pb[p] = *(const float4*)(Bg + (size_t)(kn8 + p) * k8n * 64);
            }
        }

        #pragma unroll
        for (int ks = 0; ks < 4; ks++) {
            unsigned af[4][4], bf[4][2];
            #pragma unroll
            for (int mt = 0; mt < 4; mt++)
                *(uint4*)af[mt] = *(const uint4*)&As[ks][wm * 4 + mt][lane][0];
            #pragma unroll
            for (int nt = 0; nt < 4; nt++)
                *(uint2*)bf[nt] = *(const uint2*)&Bs[ks][wn * 4 + nt][lane][0];
            #pragma unroll
            for (int mt = 0; mt < 4; mt++)
                #pragma unroll
                for (int nt = 0; nt < 4; nt++)
                    mma8(acc[mt][nt], af[mt], bf[nt]);
        }
        __syncthreads();
    }

    int g = lane >> 2, tg = lane & 3;
    #pragma unroll
    for (int mt = 0; mt < 4; mt++) {
        int row = m0 + wm * 64 + mt * 16 + g;
        #pragma unroll
        for (int nt = 0; nt < 4; nt++) {
            float* c = acc[mt][nt];
            if (MODE == 2) {
                int f = (n0 >> 1) + wn * 16 + nt * 4 + tg;
                float s0 = c[0] / (1.0f + __expf(-c[0]));
                float s2 = c[2] / (1.0f + __expf(-c[2]));
                C[aperm_off32(row,     f)] = tf32f(s0 * c[1]);
                C[aperm_off32(row + 8, f)] = tf32f(s2 * c[3]);
            } else {
                int col = n0 + wn * 32 + nt * 8 + tg * 2;
                size_t i0 = (size_t)row * N + col;
                size_t i1 = i0 + (size_t)8 * N;
                float2 v0 = make_float2(c[0], c[1]);
                float2 v1 = make_float2(c[2], c[3]);
                if (MODE == 1) {
                    v0.x += R[i0]; v0.y += R[i0 + 1];
                    v1.x += R[i1]; v1.y += R[i1 + 1];
                }
                *(float2*)&C[i0] = v0;
                *(float2*)&C[i1] = v1;
            }
        }
    }
}

// ---------------------------------------------------------------------------
// bf16 GEMM (pre-permuted). MODE 0: C=AB fp32; MODE 1: C=AB+R fp32.
// Attention path. (R8 datapath, verified.)
// ---------------------------------------------------------------------------
template<int MODE>
__global__ void __launch_bounds__(256) tgemm16_k(const __nv_bfloat16* __restrict__ Ap,
                                                 const unsigned* __restrict__ Bp,
                                                 float* __restrict__ C,
                                                 const float* __restrict__ R,
                                                 int N, int K)
{
    __shared__ unsigned As[4][8][32][4];
    __shared__ unsigned Bs[4][16][32][2];

    int tid = threadIdx.x, lane = tid & 31, warp = tid >> 5;
    int wm = warp >> 2, wn = warp & 3;
    int m0 = blockIdx.y * 128, n0 = blockIdx.x * 128;

    float acc[4][4][4];
    #pragma unroll
    for (int a = 0; a < 4; a++)
        #pragma unroll
        for (int b = 0; b < 4; b++)
            #pragma unroll
            for (int c = 0; c < 4; c++) acc[a][b][c] = 0.f;

    const int n8cnt = N >> 3;
    const uint4* Ag = (const uint4*)Ap + (size_t)((m0 >> 4) + warp) * 32 + lane;
    const uint4* Bg = (const uint4*)Bp + (size_t)((n0 >> 3) + (tid >> 4)) * 16 + (tid & 15);

    uint4* AsDst = (uint4*)As + warp * 32 + lane;
    uint4* BsDst = (uint4*)Bs + (tid >> 4) * 16 + (tid & 15);

    uint4 pa[4], pb[4];
    #pragma unroll
    for (int p = 0; p < 4; p++) {
        pa[p] = Ag[(size_t)p * 8192];
        pb[p] = Bg[(size_t)p * n8cnt * 16];
    }

    for (int k0 = 0; k0 < K; k0 += 64) {
        #pragma unroll
        for (int p = 0; p < 4; p++) {
            AsDst[p * 256] = pa[p];
            BsDst[p * 256] = pb[p];
        }
        __syncthreads();

        int kb = (k0 >> 4) + 4;
        if (k0 + 64 < K) {
            #pragma unroll
            for (int p = 0; p < 4; p++) {
                pa[p] = Ag[(size_t)(kb + p) * 8192];
                pb[p] = Bg[(size_t)(kb + p) * n8cnt * 16];
            }
        }

        #pragma unroll
        for (int ks = 0; ks < 4; ks++) {
            unsigned af[4][4], bf[4][2];
            #pragma unroll
            for (int mt = 0; mt < 4; mt++)
                *(uint4*)af[mt] = *(const uint4*)&As[ks][wm * 4 + mt][lane][0];
            #pragma unroll
            for (int nt = 0; nt < 4; nt++)
                *(uint2*)bf[nt] = *(const uint2*)&Bs[ks][wn * 4 + nt][lane][0];
            #pragma unroll
            for (int mt = 0; mt < 4; mt++)
                #pragma unroll
                for (int nt = 0; nt < 4; nt++)
                    mma16(acc[mt][nt], af[mt], bf[nt]);
        }
        __syncthreads();
    }

    int g = lane >> 2, tg = lane & 3;
    #pragma unroll
    for (int mt = 0; mt < 4; mt++) {
        int row = m0 + wm * 64 + mt * 16 + g;
        #pragma unroll
        for (int nt = 0; nt < 4; nt++) {
            float* c = acc[mt][nt];
            int col = n0 + wn * 32 + nt * 8 + tg * 2;
            size_t i0 = (size_t)row * N + col;
            size_t i1 = i0 + (size_t)8 * N;
            float2 v0 = make_float2(c[0], c[1]);
            float2 v1 = make_float2(c[2], c[3]);
            if (MODE == 1) {
                v0.x += R[i0]; v0.y += R[i0 + 1];
                v1.x += R[i1]; v1.y += R[i1 + 1];
            }
            *(float2*)&C[i0] = v0;
            *(float2*)&C[i1] = v1;
        }
    }
}

// ---------------------------------------------------------------------------
// bf16 tensor-core flash attention (R8 datapath, verified). Output bf16 A-perm.
// 128 threads = 4 warps; warp owns 16 q-rows for all keys. BQ=64, BK=32.
// ---------------------------------------------------------------------------
__global__ void __launch_bounds__(128) flash_kernel(const float* __restrict__ qkv,
                                                    __nv_bfloat16* __restrict__ op)
{
    __shared__ unsigned Qs[4][4][32][4];   // [d16][m16][lane][j]
    __shared__ unsigned Ks[4][4][32][2];   // [d16][key8][lane][j]
    __shared__ unsigned Vs[2][8][32][2];   // [key16][dim8][lane][j]
    __shared__ unsigned Ps[2][4][32][4];   // [key16][m16][lane][j]

    int qt = blockIdx.x, h = blockIdx.y, b = blockIdx.z;
    int kvh = h / NREP;
    int tid = threadIdx.x, lane = tid & 31, warp = tid >> 5;
    int g = lane >> 2, tg = lane & 3;
    int q0 = qt * 64;

    const float* qbase = qkv + (size_t)(b * SEQ + q0) * QKVW + h * HEADD;
    for (int w = tid; w < 2048; w += 128) {
        int j = w & 3, ln = (w >> 2) & 31, m16 = (w >> 7) & 3, d16 = w >> 9;
        int m = m16 * 16 + (j & 1) * 8 + (ln >> 2);
        int d = d16 * 16 + ((j >> 1) & 1) * 8 + (ln & 3) * 2;
        float2 qv = *(const float2*)(qbase + (size_t)m * QKVW + d);
        Qs[d16][m16][ln][j] = pack_bf16(qv.x, qv.y);
    }

    float mr0 = -INFINITY, mr1 = -INFINITY, l0 = 0.f, l1 = 0.f;
    float o_acc[8][4];
    #pragma unroll
    for (int nt = 0; nt < 8; nt++)
        #pragma unroll
        for (int c = 0; c < 4; c++) o_acc[nt][c] = 0.f;

    const float* kbase = qkv + (size_t)(b * SEQ) * QKVW + 768 + kvh * HEADD;
    const float* vbase = qkv + (size_t)(b * SEQ) * QKVW + 1024 + kvh * HEADD;

    int ntiles = 2 * qt + 2;
    for (int kt = 0; kt < ntiles; kt++) {
        __syncthreads();
        for (int w = tid; w < 1024; w += 128) {
            int j = w & 1, ln = (w >> 1) & 31;
            {
                int key8 = (w >> 6) & 3, d16 = w >> 8;
                int key = key8 * 8 + (ln >> 2);
                int d = d16 * 16 + j * 8 + (ln & 3) * 2;
                float2 kv = *(const float2*)(kbase + (size_t)(kt * 32 + key) * QKVW + d);
                Ks[d16][key8][ln][j] = pack_bf16(kv.x, kv.y);
            }
            {
                int d8 = (w >> 6) & 7, k16 = w >> 9;
                int dim = d8 * 8 + (ln >> 2);
                int key = k16 * 16 + j * 8 + (ln & 3) * 2;
                float v0 = vbase[(size_t)(kt * 32 + key) * QKVW + dim];
                float v1 = vbase[(size_t)(kt * 32 + key + 1) * QKVW + dim];
                Vs[k16][d8][ln][j] = pack_bf16(v0, v1);
            }
        }
        __syncthreads();

        float s[4][4];
        #pragma unroll
        for (int nt = 0; nt < 4; nt++)
            #pragma unroll
            for (int c = 0; c < 4; c++) s[nt][c] = 0.f;

        #pragma unroll
        for (int ks = 0; ks < 4; ks++) {
            unsigned af[4];
            *(uint4*)af = *(const uint4*)&Qs[ks][warp][lane][0];
            #pragma unroll
            for (int nt = 0; nt < 4; nt++) {
                unsigned bf[2];
                *(uint2*)bf = *(const uint2*)&Ks[ks][nt][lane][0];
                mma16(s[nt], af, bf);
            }
        }
        #pragma unroll
        for (int nt = 0; nt < 4; nt++)
            #pragma unroll
            for (int c = 0; c < 4; c++) s[nt][c] *= 0.125f;

        if (kt >= 2 * qt) {
            int qg0 = q0 + warp * 16 + g;
            int qg1 = qg0 + 8;
            #pragma unroll
            for (int nt = 0; nt < 4; nt++) {
                int kg = kt * 32 + nt * 8 + tg * 2;
                if (kg > qg0)     s[nt][0] = -INFINITY;
                if (kg + 1 > qg0) s[nt][1] = -INFINITY;
                if (kg > qg1)     s[nt][2] = -INFINITY;
                if (kg + 1 > qg1) s[nt][3] = -INFINITY;
            }
        }

        float mx0 = -INFINITY, mx1 = -INFINITY;
        #pragma unroll
        for (int nt = 0; nt < 4; nt++) {
            mx0 = fmaxf(mx0, fmaxf(s[nt][0], s[nt][1]));
            mx1 = fmaxf(mx1, fmaxf(s[nt][2], s[nt][3]));
        }
        mx0 = fmaxf(mx0, __shfl_xor_sync(0xffffffffu, mx0, 1));
        mx0 = fmaxf(mx0, __shfl_xor_sync(0xffffffffu, mx0, 2));
        mx1 = fmaxf(mx1, __shfl_xor_sync(0xffffffffu, mx1, 1));
        mx1 = fmaxf(mx1, __shfl_xor_sync(0xffffffffu, mx1, 2));
        float mn0 = fmaxf(mr0, mx0), mn1 = fmaxf(mr1, mx1);
        float sum0 = 0.f, sum1 = 0.f;
        #pragma unroll
        for (int nt = 0; nt < 4; nt++) {
            s[nt][0] = __expf(s[nt][0] - mn0);
            s[nt][1] = __expf(s[nt][1] - mn0);
            s[nt][2] = __expf(s[nt][2] - mn1);
            s[nt][3] = __expf(s[nt][3] - mn1);
            sum0 += s[nt][0] + s[nt][1];
            sum1 += s[nt][2] + s[nt][3];
        }
        sum0 += __shfl_xor_sync(0xffffffffu, sum0, 1);
        sum0 += __shfl_xor_sync(0xffffffffu, sum0, 2);
        sum1 += __shfl_xor_sync(0xffffffffu, sum1, 1);
        sum1 += __shfl_xor_sync(0xffffffffu, sum1, 2);
        float a0 = __expf(mr0 - mn0), a1 = __expf(mr1 - mn1);
        l0 = l0 * a0 + sum0;  l1 = l1 * a1 + sum1;
        mr0 = mn0;  mr1 = mn1;
        #pragma unroll
        for (int nt = 0; nt < 8; nt++) {
            o_acc[nt][0] *= a0; o_acc[nt][1] *= a0;
            o_acc[nt][2] *= a1; o_acc[nt][3] *= a1;
        }

        #pragma unroll
        for (int nt = 0; nt < 4; nt++) {
            Ps[nt >> 1][warp][lane][2 * (nt & 1)]     = pack_bf16(s[nt][0], s[nt][1]);
            Ps[nt >> 1][warp][lane][2 * (nt & 1) + 1] = pack_bf16(s[nt][2], s[nt][3]);
        }
        __syncwarp();

        #pragma unroll
        for (int kks = 0; kks < 2; kks++) {
            unsigned af[4];
            *(uint4*)af = *(const uint4*)&Ps[kks][warp][lane][0];
            #pragma unroll
            for (int nt = 0; nt < 8; nt++) {
                unsigned bf[2];
                *(uint2*)bf = *(const uint2*)&Vs[kks][nt][lane][0];
                mma16(o_acc[nt], af, bf);
            }
        }
        __syncwarp();
    }

    float inv0 = 1.0f / l0, inv1 = 1.0f / l1;
    int mrow = b * SEQ + q0 + warp * 16 + g;
    unsigned* opw = (unsigned*)op;
    #pragma unroll
    for (int nt = 0; nt < 8; nt++) {
        int col = h * HEADD + nt * 8 + tg * 2;
        opw[aperm_woff16(mrow,     col)] = pack_bf16(o_acc[nt][0] * inv0, o_acc[nt][1] * inv0);
        opw[aperm_woff16(mrow + 8, col)] = pack_bf16(o_acc[nt][2] * inv1, o_acc[nt][3] * inv1);
    }
}

// ---------------------------------------------------------------------------
// Launch sequence
// ---------------------------------------------------------------------------
extern "C" void kernel_launch(void* const* d_in, const int* in_sizes, int n_in,
                              void* d_out, int out_size)
{
    (void)in_sizes; (void)n_in; (void)out_size;
    const float* x_in = (const float*)d_in[0];
    const float* Wq   = (const float*)d_in[1];
    const float* Wk   = (const float*)d_in[2];
    const float* Wv   = (const float*)d_in[3];
    const float* Wo   = (const float*)d_in[4];
    const float* an_w = (const float*)d_in[5];
    const float* w0   = (const float*)d_in[6];
    const float* w1   = (const float*)d_in[7];
    const float* w2   = (const float*)d_in[8];
    const float* sn_w = (const float*)d_in[9];
    const float* on_w = (const float*)d_in[10];

    __nv_bfloat16 *hp16, *attnp;
    float *hp32, *qkv, *x, *ffp, *w01p, *w2p;
    unsigned *wqkvp, *wop;
    cudaGetSymbolAddress((void**)&hp16,  g_hp16);
    cudaGetSymbolAddress((void**)&hp32,  g_hp32);
    cudaGetSymbolAddress((void**)&qkv,   g_qkv);
    cudaGetSymbolAddress((void**)&attnp, g_attnp);
    cudaGetSymbolAddress((void**)&x,     g_x);
    cudaGetSymbolAddress((void**)&ffp,   g_ffp);
    cudaGetSymbolAddress((void**)&wqkvp, g_wqkvp);
    cudaGetSymbolAddress((void**)&wop,   g_wop);
    cudaGetSymbolAddress((void**)&w01p,  g_w01p);
    cudaGetSymbolAddress((void**)&w2p,   g_w2p);

    // pack weights (captured; runs each replay; ~60us total)
    pack_qkv_w16<<<(LAYERS * DMODEL * QKVW / 2 + 255) / 256, 256>>>(Wq, Wk, Wv, wqkvp);
    pack_w_gen16<<<(LAYERS * DMODEL * DMODEL / 2 + 255) / 256, 256>>>(Wo, wop, DMODEL, DMODEL);
    pack_w01_32<<<(LAYERS * DMODEL * 2 * FFDIM / 2 + 255) / 256, 256>>>(w0, w1, w01p);
    pack_w_gen32<<<(LAYERS * FFDIM * DMODEL / 2 + 255) / 256, 256>>>(w2, w2p, FFDIM, DMODEL);

    const float* cur = x_in;
    for (int li = 0; li < LAYERS; li++) {
        // attention side (bf16)
        rmsnorm_k<2><<<ROWS, 256>>>(cur, an_w + (size_t)li * DMODEL, hp16);

        tgemm16_k<0><<<dim3(QKVW / 128, ROWS / 128), 256>>>(
            hp16, wqkvp + (size_t)li * DMODEL * QKVW / 2, qkv, nullptr, QKVW, DMODEL);

        rope_packed<<<(ROWS * 16 * 32 + 255) / 256, 256>>>(qkv);

        flash_kernel<<<dim3(SEQ / 64, NHEADS, BATCH), 128>>>(qkv, attnp);

        tgemm16_k<1><<<dim3(DMODEL / 128, ROWS / 128), 256>>>(
            attnp, wop + (size_t)li * DMODEL * DMODEL / 2, x, cur, DMODEL, DMODEL);

        // FFN side (tf32)
        rmsnorm_k<1><<<ROWS, 256>>>(x, sn_w + (size_t)li * DMODEL, hp32);

        tgemm32_k<2><<<dim3(2 * FFDIM / 128, ROWS / 128), 256>>>(
            hp32, w01p + (size_t)li * DMODEL * 2 * FFDIM, ffp, nullptr, 2 * FFDIM, DMODEL);

        tgemm32_k<1><<<dim3(DMODEL / 128, ROWS / 128), 256>>>(
            ffp, w2p + (size_t)li * FFDIM * DMODEL, x, x, DMODEL, FFDIM);
        cur = x;
    }

    rmsnorm_k<0><<<ROWS, 256>>>(x, on_w, (float*)d_out);
}

// round 11
// speedup vs baseline: 4.4987x; 1.1068x over previous
#include <cuda_runtime.h>
#include <cuda_bf16.h>
#include <math.h>
#include <stdint.h>

// Problem constants
#define LAYERS 2
#define BATCH  2
#define SEQ    2048
#define DMODEL 768
#define NHEADS 12
#define KVHEADS 4
#define NREP   3
#define HEADD  64
#define FFDIM  3072
#define ROWS   (BATCH*SEQ)     // 4096
#define QKVW   1280            // 768 q + 256 k + 256 v

// ---------------------------------------------------------------------------
// Scratch (allocation-free: __device__ globals)
// Attention side = bf16, FFN side = tf32.
// ---------------------------------------------------------------------------
__device__ __nv_bfloat16 g_hp16[ROWS * DMODEL];    // rmsnorm out, bf16 A-perm
__device__ float         g_hp32[ROWS * DMODEL];    // rmsnorm out, tf32 A-perm
__device__ float         g_qkv[ROWS * QKVW];       // row-major fp32
__device__ __nv_bfloat16 g_attnp[ROWS * DMODEL];   // attention out, bf16 A-perm
__device__ float         g_x[ROWS * DMODEL];       // residual stream fp32
__device__ float         g_ffp[ROWS * FFDIM];      // FFN intermediate, tf32 A-perm
__device__ unsigned g_wqkvp[LAYERS * DMODEL * QKVW / 2];   // bf16 B-perm words
__device__ unsigned g_wop[LAYERS * DMODEL * DMODEL / 2];   // bf16 B-perm words
__device__ float    g_w01p[LAYERS * DMODEL * 2 * FFDIM];   // tf32 B-perm
__device__ float    g_w2p[LAYERS * FFDIM * DMODEL];        // tf32 B-perm

// ---------------------------------------------------------------------------
// cp.async helpers
// ---------------------------------------------------------------------------
__device__ __forceinline__ uint32_t smem_u32(const void* p) {
    return (uint32_t)__cvta_generic_to_shared(p);
}
__device__ __forceinline__ void cp16(uint32_t dst, const void* src) {
    asm volatile("cp.async.cg.shared.global [%0], [%1], 16;" :: "r"(dst), "l"(src));
}
__device__ __forceinline__ void cp_commit() { asm volatile("cp.async.commit_group;"); }
__device__ __forceinline__ void cp_wait1()  { asm volatile("cp.async.wait_group 1;"); }

// ---------------------------------------------------------------------------
// tf32 helpers (m16n8k8)
// ---------------------------------------------------------------------------
__device__ __forceinline__ unsigned f2tf(float x) {
    unsigned r; asm("cvt.rna.tf32.f32 %0, %1;" : "=r"(r) : "f"(x)); return r;
}
__device__ __forceinline__ float tf32f(float x) { return __uint_as_float(f2tf(x)); }

__device__ __forceinline__ size_t aperm_off32(int m, int k) {
    return (size_t)(k >> 3) * 32768 + (size_t)(m >> 4) * 128
         + ((m & 7) * 4 + (k & 3)) * 4 + ((m >> 3) & 1) + 2 * ((k >> 2) & 1);
}

__device__ __forceinline__ void mma8(float* d, const unsigned* a, const unsigned* b) {
    asm volatile("mma.sync.aligned.m16n8k8.row.col.f32.tf32.tf32.f32 "
        "{%0,%1,%2,%3}, {%4,%5,%6,%7}, {%8,%9}, {%0,%1,%2,%3};"
        : "+f"(d[0]), "+f"(d[1]), "+f"(d[2]), "+f"(d[3])
        : "r"(a[0]), "r"(a[1]), "r"(a[2]), "r"(a[3]), "r"(b[0]), "r"(b[1]));
}

// ---------------------------------------------------------------------------
// bf16 helpers (m16n8k16)
// ---------------------------------------------------------------------------
__device__ __forceinline__ unsigned pack_bf16(float lo, float hi) {
    __nv_bfloat162 t = __floats2bfloat162_rn(lo, hi);
    return *reinterpret_cast<unsigned*>(&t);
}

__device__ __forceinline__ size_t aperm_off16(int m, int k) {  // element offset
    return (size_t)(k >> 4) * 65536 + (size_t)(m >> 4) * 256
         + ((m & 7) * 4 + ((k >> 1) & 3)) * 8
         + (((m >> 3) & 1) + 2 * ((k >> 3) & 1)) * 2 + (k & 1);
}
__device__ __forceinline__ size_t aperm_woff16(int m, int k) { // word offset, k even
    return (size_t)(k >> 4) * 32768 + (size_t)(m >> 4) * 128
         + ((m & 7) * 4 + ((k >> 1) & 3)) * 4
         + ((m >> 3) & 1) + 2 * ((k >> 3) & 1);
}

__device__ __forceinline__ void mma16(float* d, const unsigned* a, const unsigned* b) {
    asm volatile("mma.sync.aligned.m16n8k16.row.col.f32.bf16.bf16.f32 "
        "{%0,%1,%2,%3}, {%4,%5,%6,%7}, {%8,%9}, {%0,%1,%2,%3};"
        : "+f"(d[0]), "+f"(d[1]), "+f"(d[2]), "+f"(d[3])
        : "r"(a[0]), "r"(a[1]), "r"(a[2]), "r"(a[3]), "r"(b[0]), "r"(b[1]));
}

// ---------------------------------------------------------------------------
// Merged weight packing: one launch covers all four weight groups.
// seg0 qkv->bf16, seg1 Wo->bf16, seg2 w01->tf32 interleaved, seg3 w2->tf32
// ---------------------------------------------------------------------------
#define QKV_WORDS   (LAYERS * DMODEL * QKVW / 2)       // 983040  -> 3840 blocks
#define WO_WORDS    (LAYERS * DMODEL * DMODEL / 2)     // 589824  -> 2304 blocks
#define W01_PAIRS   (LAYERS * DMODEL * 2 * FFDIM / 2)  // 4718592 -> 18432 blocks
#define W2_PAIRS    (LAYERS * FFDIM * DMODEL / 2)      // 2359296 -> 9216 blocks
#define QKV_BLKS    ((QKV_WORDS + 255) / 256)
#define WO_BLKS     ((WO_WORDS + 255) / 256)
#define W01_BLKS    ((W01_PAIRS + 255) / 256)
#define W2_BLKS     ((W2_PAIRS + 255) / 256)
#define PACK_BLKS   (QKV_BLKS + WO_BLKS + W01_BLKS + W2_BLKS)

__device__ __forceinline__ void pack_coords16(int dw, int N, int& kbase, int& n) {
    int j  = dw & 1;
    int ln = (dw >> 1) & 31;
    int blk = dw >> 6;
    int n8cnt = N >> 3;
    int k16 = blk / n8cnt, n8 = blk - k16 * n8cnt;
    n = n8 * 8 + (ln >> 2);
    kbase = k16 * 16 + j * 8 + (ln & 3) * 2;
}
__device__ __forceinline__ void pack_coords32(int q, int N, int& k, int& n, int& dw) {
    dw = 2 * q;
    int block = dw >> 6;
    int lane  = (dw & 63) >> 1;
    int n8cnt = N >> 3;
    int k8 = block / n8cnt, n8 = block - k8 * n8cnt;
    n = n8 * 8 + (lane >> 2);
    k = k8 * 8 + (lane & 3);
}

__global__ void __launch_bounds__(256) pack_all(const float* __restrict__ Wq,
                                                const float* __restrict__ Wk,
                                                const float* __restrict__ Wv,
                                                const float* __restrict__ Wo,
                                                const float* __restrict__ w0,
                                                const float* __restrict__ w1,
                                                const float* __restrict__ w2,
                                                unsigned* __restrict__ wqkvp,
                                                unsigned* __restrict__ wop,
                                                float* __restrict__ w01p,
                                                float* __restrict__ w2p)
{
    int bid = blockIdx.x;
    if (bid < QKV_BLKS) {
        int p = bid * 256 + threadIdx.x;
        if (p >= QKV_WORDS) return;
        const int perL = DMODEL * QKVW / 2;
        int l = p / perL, dw = p - l * perL;
        int k, n; pack_coords16(dw, QKVW, k, n);
        float v0, v1;
        if (n < 768) {
            const float* s = Wq + ((size_t)l * DMODEL + k) * 768 + n;
            v0 = s[0]; v1 = s[768];
        } else if (n < 1024) {
            const float* s = Wk + ((size_t)l * DMODEL + k) * 256 + (n - 768);
            v0 = s[0]; v1 = s[256];
        } else {
            const float* s = Wv + ((size_t)l * DMODEL + k) * 256 + (n - 1024);
            v0 = s[0]; v1 = s[256];
        }
        wqkvp[(size_t)l * perL + dw] = pack_bf16(v0, v1);
    } else if (bid < QKV_BLKS + WO_BLKS) {
        int p = (bid - QKV_BLKS) * 256 + threadIdx.x;
        if (p >= WO_WORDS) return;
        const int perL = DMODEL * DMODEL / 2;
        int l = p / perL, dw = p - l * perL;
        int k, n; pack_coords16(dw, DMODEL, k, n);
        const float* s = Wo + ((size_t)l * DMODEL + k) * DMODEL + n;
        wop[(size_t)l * perL + dw] = pack_bf16(s[0], s[DMODEL]);
    } else if (bid < QKV_BLKS + WO_BLKS + W01_BLKS) {
        int p = (bid - QKV_BLKS - WO_BLKS) * 256 + threadIdx.x;
        if (p >= W01_PAIRS) return;
        const int perL = DMODEL * 2 * FFDIM / 2;
        int l = p / perL, q = p - l * perL;
        int k, n, dw; pack_coords32(q, 2 * FFDIM, k, n, dw);
        int f = n >> 1;
        const float* s = ((n & 1) ? w1 : w0) + ((size_t)l * DMODEL + k) * FFDIM + f;
        float2 o; o.x = tf32f(s[0]); o.y = tf32f(s[4 * FFDIM]);
        *(float2*)(w01p + (size_t)l * DMODEL * 2 * FFDIM + dw) = o;
    } else {
        int p = (bid - QKV_BLKS - WO_BLKS - W01_BLKS) * 256 + threadIdx.x;
        if (p >= W2_PAIRS) return;
        const int perL = FFDIM * DMODEL / 2;
        int l = p / perL, q = p - l * perL;
        int k, n, dw; pack_coords32(q, DMODEL, k, n, dw);
        const float* s = w2 + ((size_t)l * FFDIM + k) * DMODEL + n;
        float2 o; o.x = tf32f(s[0]); o.y = tf32f(s[(size_t)4 * DMODEL]);
        *(float2*)(w2p + (size_t)l * FFDIM * DMODEL + dw) = o;
    }
}

// ---------------------------------------------------------------------------
// RMSNorm: PERM 0 = fp32 row-major, 1 = tf32 A-perm, 2 = bf16 A-perm
// ---------------------------------------------------------------------------
template<int PERM>
__global__ void __launch_bounds__(256) rmsnorm_k(const float* __restrict__ x,
                                                 const float* __restrict__ w,
                                                 void* __restrict__ yv)
{
    int row = blockIdx.x;
    const float* xr = x + (size_t)row * DMODEL;
    int t = threadIdx.x;
    float v0 = xr[t], v1 = xr[t + 256], v2 = xr[t + 512];
    float ss = v0*v0 + v1*v1 + v2*v2;
    #pragma unroll
    for (int off = 16; off > 0; off >>= 1)
        ss += __shfl_xor_sync(0xffffffffu, ss, off);
    __shared__ float red[8];
    if ((t & 31) == 0) red[t >> 5] = ss;
    __syncthreads();
    if (t < 32) {
        float s = (t < 8) ? red[t] : 0.f;
        #pragma unroll
        for (int off = 4; off > 0; off >>= 1)
            s += __shfl_xor_sync(0xffffffffu, s, off);
        if (t == 0) red[0] = s;
    }
    __syncthreads();
    float inv = 1.0f / sqrtf(red[0] * (1.0f / DMODEL) + 1e-6f);
    float o0 = v0 * inv * w[t];
    float o1 = v1 * inv * w[t + 256];
    float o2 = v2 * inv * w[t + 512];
    if (PERM == 1) {
        float* y = (float*)yv;
        y[aperm_off32(row, t)]       = tf32f(o0);
        y[aperm_off32(row, t + 256)] = tf32f(o1);
        y[aperm_off32(row, t + 512)] = tf32f(o2);
    } else if (PERM == 2) {
        __nv_bfloat16* y = (__nv_bfloat16*)yv;
        y[aperm_off16(row, t)]       = __float2bfloat16(o0);
        y[aperm_off16(row, t + 256)] = __float2bfloat16(o1);
        y[aperm_off16(row, t + 512)] = __float2bfloat16(o2);
    } else {
        float* yr = (float*)yv + (size_t)row * DMODEL;
        yr[t] = o0; yr[t + 256] = o1; yr[t + 512] = o2;
    }
}

// ---------------------------------------------------------------------------
// RoPE on packed qkv (row-major fp32)
// ---------------------------------------------------------------------------
__global__ void __launch_bounds__(256) rope_packed(float* __restrict__ qkv)
{
    int idx = blockIdx.x * 256 + threadIdx.x;
    const int total = ROWS * 16 * 32;
    if (idx >= total) return;
    int i    = idx & 31;
    int hh   = (idx >> 5) & 15;
    int row  = idx >> 9;
    int s    = row & (SEQ - 1);
    float freq = (float)exp(-9.210340371976184 * ((double)i / 32.0));
    float ang = (float)s * freq;
    float sn, cs;
    sincosf(ang, &sn, &cs);
    int coff = (hh < 12) ? hh * 64 : 768 + (hh - 12) * 64;
    float* p = qkv + (size_t)row * QKVW + coff + 2 * i;
    float t0 = p[0], t1 = p[1];
    p[0] = t0 * cs - t1 * sn;
    p[1] = t0 * sn + t1 * cs;
}

// ---------------------------------------------------------------------------
// tf32 GEMM, 3-stage cp.async pipeline. K-tile = 16 (2 k8 steps / stage).
// Stage = 16KB (A 8KB + B 8KB); 3 stages = 48KB static smem; 2 CTAs/SM.
// MODE 1: C = AB + R fp32; MODE 2: gated silu -> tf32 A-perm out (K'=N/2).
// ---------------------------------------------------------------------------
template<int MODE>
__global__ void __launch_bounds__(256, 2) tgemm32_k(const float* __restrict__ Ap,
                                                    const float* __restrict__ Bp,
                                                    float* __restrict__ C,
                                                    const float* __restrict__ R,
                                                    int N, int K)
{
    __shared__ float sm[3][4096];  // stage: [0,2048)=A [2][8][32][4], [2048,4096)=B [2][16][32][2]

    int tid = threadIdx.x, lane = tid & 31, warp = tid >> 5;
    int wm = warp >> 2, wn = warp & 3;
    int m0 = blockIdx.y * 128, n0 = blockIdx.x * 128;

    float acc[4][4][4];
    #pragma unroll
    for (int a = 0; a < 4; a++)
        #pragma unroll
        for (int b = 0; b < 4; b++)
            #pragma unroll
            for (int c = 0; c < 4; c++) acc[a][b][c] = 0.f;

    const int k8n = N >> 3;
    const float* Ag = Ap + (size_t)((m0 >> 4) + warp) * 128 + lane * 4;
    const float* Bg = Bp + (size_t)((n0 >> 3) + (tid >> 4)) * 64 + (tid & 15) * 4;

    uint32_t smBase = smem_u32(sm);
    uint32_t aDst = smBase + (warp * 32 + lane) * 16;                  // + st*16384 + p*4096
    uint32_t bDst = smBase + 8192 + ((tid >> 4) * 16 + (tid & 15)) * 16;

    const int ntiles = K >> 4;

    // prologue: issue tiles 0 and 1
    #pragma unroll
    for (int t = 0; t < 2; t++) {
        uint32_t sb = t * 16384;
        #pragma unroll
        for (int p = 0; p < 2; p++) {
            int q = 2 * t + p;
            cp16(aDst + sb + p * 4096, Ag + (size_t)q * 32768);
            cp16(bDst + sb + p * 4096, Bg + (size_t)q * k8n * 64);
        }
        cp_commit();
    }

    for (int kt = 0; kt < ntiles; kt++) {
        cp_wait1();
        __syncthreads();
        int st = kt % 3;
        const float* S = sm[st];

        #pragma unroll
        for (int ks = 0; ks < 2; ks++) {
            unsigned af[4][4], bf[4][2];
            #pragma unroll
            for (int mt = 0; mt < 4; mt++)
                *(uint4*)af[mt] = *(const uint4*)&S[ks * 1024 + (wm * 4 + mt) * 128 + lane * 4];
            #pragma unroll
            for (int nt = 0; nt < 4; nt++)
                *(uint2*)bf[nt] = *(const uint2*)&S[2048 + ks * 1024 + (wn * 4 + nt) * 64 + lane * 2];
            #pragma unroll
            for (int mt = 0; mt < 4; mt++)
                #pragma unroll
                for (int nt = 0; nt < 4; nt++)
                    mma8(acc[mt][nt], af[mt], bf[nt]);
        }

        int kn = kt + 2;
        if (kn < ntiles) {
            uint32_t sb = (kn % 3) * 16384;
            #pragma unroll
            for (int p = 0; p < 2; p++) {
                int q = 2 * kn + p;
                cp16(aDst + sb + p * 4096, Ag + (size_t)q * 32768);
                cp16(bDst + sb + p * 4096, Bg + (size_t)q * k8n * 64);
            }
        }
        cp_commit();
    }

    int g = lane >> 2, tg = lane & 3;
    #pragma unroll
    for (int mt = 0; mt < 4; mt++) {
        int row = m0 + wm * 64 + mt * 16 + g;
        #pragma unroll
        for (int nt = 0; nt < 4; nt++) {
            float* c = acc[mt][nt];
            if (MODE == 2) {
                int f = (n0 >> 1) + wn * 16 + nt * 4 + tg;
                float s0 = c[0] / (1.0f + __expf(-c[0]));
                float s2 = c[2] / (1.0f + __expf(-c[2]));
                C[aperm_off32(row,     f)] = tf32f(s0 * c[1]);
                C[aperm_off32(row + 8, f)] = tf32f(s2 * c[3]);
            } else {
                int col = n0 + wn * 32 + nt * 8 + tg * 2;
                size_t i0 = (size_t)row * N + col;
                size_t i1 = i0 + (size_t)8 * N;
                float2 v0 = make_float2(c[0], c[1]);
                float2 v1 = make_float2(c[2], c[3]);
                if (MODE == 1) {
                    v0.x += R[i0]; v0.y += R[i0 + 1];
                    v1.x += R[i1]; v1.y += R[i1 + 1];
                }
                *(float2*)&C[i0] = v0;
                *(float2*)&C[i1] = v1;
            }
        }
    }
}

// ---------------------------------------------------------------------------
// bf16 GEMM, 3-stage cp.async pipeline. K-tile = 32 (2 k16 steps / stage).
// Stage = 16KB; 3 stages = 48KB static smem; 2 CTAs/SM.
// MODE 0: C = AB fp32; MODE 1: C = AB + R fp32.
// ---------------------------------------------------------------------------
template<int MODE>
__global__ void __launch_bounds__(256, 2) tgemm16_k(const __nv_bfloat16* __restrict__ Ap,
                                                    const unsigned* __restrict__ Bp,
                                                    float* __restrict__ C,
                                                    const float* __restrict__ R,
                                                    int N, int K)
{
    __shared__ unsigned sm[3][4096];  // stage: [0,2048)=A [2][8][32][4], [2048,4096)=B

    int tid = threadIdx.x, lane = tid & 31, warp = tid >> 5;
    int wm = warp >> 2, wn = warp & 3;
    int m0 = blockIdx.y * 128, n0 = blockIdx.x * 128;

    float acc[4][4][4];
    #pragma unroll
    for (int a = 0; a < 4; a++)
        #pragma unroll
        for (int b = 0; b < 4; b++)
            #pragma unroll
            for (int c = 0; c < 4; c++) acc[a][b][c] = 0.f;

    const int n8cnt = N >> 3;
    const uint4* Ag = (const uint4*)Ap + (size_t)((m0 >> 4) + warp) * 32 + lane;
    const uint4* Bg = (const uint4*)Bp + (size_t)((n0 >> 3) + (tid >> 4)) * 16 + (tid & 15);

    uint32_t smBase = smem_u32(sm);
    uint32_t aDst = smBase + (warp * 32 + lane) * 16;
    uint32_t bDst = smBase + 8192 + ((tid >> 4) * 16 + (tid & 15)) * 16;

    const int ntiles = K >> 5;

    #pragma unroll
    for (int t = 0; t < 2; t++) {
        uint32_t sb = t * 16384;
        #pragma unroll
        for (int p = 0; p < 2; p++) {
            int q = 2 * t + p;
            cp16(aDst + sb + p * 4096, Ag + (size_t)q * 8192);
            cp16(bDst + sb + p * 4096, Bg + (size_t)q * n8cnt * 16);
        }
        cp_commit();
    }

    for (int kt = 0; kt < ntiles; kt++) {
        cp_wait1();
        __syncthreads();
        int st = kt % 3;
        const unsigned* S = sm[st];

        #pragma unroll
        for (int ks = 0; ks < 2; ks++) {
            unsigned af[4][4], bf[4][2];
            #pragma unroll
            for (int mt = 0; mt < 4; mt++)
                *(uint4*)af[mt] = *(const uint4*)&S[ks * 1024 + (wm * 4 + mt) * 128 + lane * 4];
            #pragma unroll
            for (int nt = 0; nt < 4; nt++)
                *(uint2*)bf[nt] = *(const uint2*)&S[2048 + ks * 1024 + (wn * 4 + nt) * 64 + lane * 2];
            #pragma unroll
            for (int mt = 0; mt < 4; mt++)
                #pragma unroll
                for (int nt = 0; nt < 4; nt++)
                    mma16(acc[mt][nt], af[mt], bf[nt]);
        }

        int kn = kt + 2;
        if (kn < ntiles) {
            uint32_t sb = (kn % 3) * 16384;
            #pragma unroll
            for (int p = 0; p < 2; p++) {
                int q = 2 * kn + p;
                cp16(aDst + sb + p * 4096, Ag + (size_t)q * 8192);
                cp16(bDst + sb + p * 4096, Bg + (size_t)q * n8cnt * 16);
            }
        }
        cp_commit();
    }

    int g = lane >> 2, tg = lane & 3;
    #pragma unroll
    for (int mt = 0; mt < 4; mt++) {
        int row = m0 + wm * 64 + mt * 16 + g;
        #pragma unroll
        for (int nt = 0; nt < 4; nt++) {
            float* c = acc[mt][nt];
            int col = n0 + wn * 32 + nt * 8 + tg * 2;
            size_t i0 = (size_t)row * N + col;
            size_t i1 = i0 + (size_t)8 * N;
            float2 v0 = make_float2(c[0], c[1]);
            float2 v1 = make_float2(c[2], c[3]);
            if (MODE == 1) {
                v0.x += R[i0]; v0.y += R[i0 + 1];
                v1.x += R[i1]; v1.y += R[i1 + 1];
            }
            *(float2*)&C[i0] = v0;
            *(float2*)&C[i1] = v1;
        }
    }
}

// ---------------------------------------------------------------------------
// bf16 tensor-core flash attention (verified R8/R10). Output bf16 A-perm.
// ---------------------------------------------------------------------------
__global__ void __launch_bounds__(128) flash_kernel(const float* __restrict__ qkv,
                                                    __nv_bfloat16* __restrict__ op)
{
    __shared__ unsigned Qs[4][4][32][4];
    __shared__ unsigned Ks[4][4][32][2];
    __shared__ unsigned Vs[2][8][32][2];
    __shared__ unsigned Ps[2][4][32][4];

    int qt = blockIdx.x, h = blockIdx.y, b = blockIdx.z;
    int kvh = h / NREP;
    int tid = threadIdx.x, lane = tid & 31, warp = tid >> 5;
    int g = lane >> 2, tg = lane & 3;
    int q0 = qt * 64;

    const float* qbase = qkv + (size_t)(b * SEQ + q0) * QKVW + h * HEADD;
    for (int w = tid; w < 2048; w += 128) {
        int j = w & 3, ln = (w >> 2) & 31, m16 = (w >> 7) & 3, d16 = w >> 9;
        int m = m16 * 16 + (j & 1) * 8 + (ln >> 2);
        int d = d16 * 16 + ((j >> 1) & 1) * 8 + (ln & 3) * 2;
        float2 qv = *(const float2*)(qbase + (size_t)m * QKVW + d);
        Qs[d16][m16][ln][j] = pack_bf16(qv.x, qv.y);
    }

    float mr0 = -INFINITY, mr1 = -INFINITY, l0 = 0.f, l1 = 0.f;
    float o_acc[8][4];
    #pragma unroll
    for (int nt = 0; nt < 8; nt++)
        #pragma unroll
        for (int c = 0; c < 4; c++) o_acc[nt][c] = 0.f;

    const float* kbase = qkv + (size_t)(b * SEQ) * QKVW + 768 + kvh * HEADD;
    const float* vbase = qkv + (size_t)(b * SEQ) * QKVW + 1024 + kvh * HEADD;

    int ntiles = 2 * qt + 2;
    for (int kt = 0; kt < ntiles; kt++) {
        __syncthreads();
        for (int w = tid; w < 1024; w += 128) {
            int j = w & 1, ln = (w >> 1) & 31;
            {
                int key8 = (w >> 6) & 3, d16 = w >> 8;
                int key = key8 * 8 + (ln >> 2);
                int d = d16 * 16 + j * 8 + (ln & 3) * 2;
                float2 kv = *(const float2*)(kbase + (size_t)(kt * 32 + key) * QKVW + d);
                Ks[d16][key8][ln][j] = pack_bf16(kv.x, kv.y);
            }
            {
                int d8 = (w >> 6) & 7, k16 = w >> 9;
                int dim = d8 * 8 + (ln >> 2);
                int key = k16 * 16 + j * 8 + (ln & 3) * 2;
                float v0 = vbase[(size_t)(kt * 32 + key) * QKVW + dim];
                float v1 = vbase[(size_t)(kt * 32 + key + 1) * QKVW + dim];
                Vs[k16][d8][ln][j] = pack_bf16(v0, v1);
            }
        }
        __syncthreads();

        float s[4][4];
        #pragma unroll
        for (int nt = 0; nt < 4; nt++)
            #pragma unroll
            for (int c = 0; c < 4; c++) s[nt][c] = 0.f;

        #pragma unroll
        for (int ks = 0; ks < 4; ks++) {
            unsigned af[4];
            *(uint4*)af = *(const uint4*)&Qs[ks][warp][lane][0];
            #pragma unroll
            for (int nt = 0; nt < 4; nt++) {
                unsigned bf[2];
                *(uint2*)bf = *(const uint2*)&Ks[ks][nt][lane][0];
                mma16(s[nt], af, bf);
            }
        }
        #pragma unroll
        for (int nt = 0; nt < 4; nt++)
            #pragma unroll
            for (int c = 0; c < 4; c++) s[nt][c] *= 0.125f;

        if (kt >= 2 * qt) {
            int qg0 = q0 + warp * 16 + g;
            int qg1 = qg0 + 8;
            #pragma unroll
            for (int nt = 0; nt < 4; nt++) {
                int kg = kt * 32 + nt * 8 + tg * 2;
                if (kg > qg0)     s[nt][0] = -INFINITY;
                if (kg + 1 > qg0) s[nt][1] = -INFINITY;
                if (kg > qg1)     s[nt][2] = -INFINITY;
                if (kg + 1 > qg1) s[nt][3] = -INFINITY;
            }
        }

        float mx0 = -INFINITY, mx1 = -INFINITY;
        #pragma unroll
        for (int nt = 0; nt < 4; nt++) {
            mx0 = fmaxf(mx0, fmaxf(s[nt][0], s[nt][1]));
            mx1 = fmaxf(mx1, fmaxf(s[nt][2], s[nt][3]));
        }
        mx0 = fmaxf(mx0, __shfl_xor_sync(0xffffffffu, mx0, 1));
        mx0 = fmaxf(mx0, __shfl_xor_sync(0xffffffffu, mx0, 2));
        mx1 = fmaxf(mx1, __shfl_xor_sync(0xffffffffu, mx1, 1));
        mx1 = fmaxf(mx1, __shfl_xor_sync(0xffffffffu, mx1, 2));
        float mn0 = fmaxf(mr0, mx0), mn1 = fmaxf(mr1, mx1);
        float sum0 = 0.f, sum1 = 0.f;
        #pragma unroll
        for (int nt = 0; nt < 4; nt++) {
            s[nt][0] = __expf(s[nt][0] - mn0);
            s[nt][1] = __expf(s[nt][1] - mn0);
            s[nt][2] = __expf(s[nt][2] - mn1);
            s[nt][3] = __expf(s[nt][3] - mn1);
            sum0 += s[nt][0] + s[nt][1];
            sum1 += s[nt][2] + s[nt][3];
        }
        sum0 += __shfl_xor_sync(0xffffffffu, sum0, 1);
        sum0 += __shfl_xor_sync(0xffffffffu, sum0, 2);
        sum1 += __shfl_xor_sync(0xffffffffu, sum1, 1);
        sum1 += __shfl_xor_sync(0xffffffffu, sum1, 2);
        float a0 = __expf(mr0 - mn0), a1 = __expf(mr1 - mn1);
        l0 = l0 * a0 + sum0;  l1 = l1 * a1 + sum1;
        mr0 = mn0;  mr1 = mn1;
        #pragma unroll
        for (int nt = 0; nt < 8; nt++) {
            o_acc[nt][0] *= a0; o_acc[nt][1] *= a0;
            o_acc[nt][2] *= a1; o_acc[nt][3] *= a1;
        }

        #pragma unroll
        for (int nt = 0; nt < 4; nt++) {
            Ps[nt >> 1][warp][lane][2 * (nt & 1)]     = pack_bf16(s[nt][0], s[nt][1]);
            Ps[nt >> 1][warp][lane][2 * (nt & 1) + 1] = pack_bf16(s[nt][2], s[nt][3]);
        }
        __syncwarp();

        #pragma unroll
        for (int kks = 0; kks < 2; kks++) {
            unsigned af[4];
            *(uint4*)af = *(const uint4*)&Ps[kks][warp][lane][0];
            #pragma unroll
            for (int nt = 0; nt < 8; nt++) {
                unsigned bf[2];
                *(uint2*)bf = *(const uint2*)&Vs[kks][nt][lane][0];
                mma16(o_acc[nt], af, bf);
            }
        }
        __syncwarp();
    }

    float inv0 = 1.0f / l0, inv1 = 1.0f / l1;
    int mrow = b * SEQ + q0 + warp * 16 + g;
    unsigned* opw = (unsigned*)op;
    #pragma unroll
    for (int nt = 0; nt < 8; nt++) {
        int col = h * HEADD + nt * 8 + tg * 2;
        opw[aperm_woff16(mrow,     col)] = pack_bf16(o_acc[nt][0] * inv0, o_acc[nt][1] * inv0);
        opw[aperm_woff16(mrow + 8, col)] = pack_bf16(o_acc[nt][2] * inv1, o_acc[nt][3] * inv1);
    }
}

// ---------------------------------------------------------------------------
// Launch sequence
// ---------------------------------------------------------------------------
extern "C" void kernel_launch(void* const* d_in, const int* in_sizes, int n_in,
                              void* d_out, int out_size)
{
    (void)in_sizes; (void)n_in; (void)out_size;
    const float* x_in = (const float*)d_in[0];
    const float* Wq   = (const float*)d_in[1];
    const float* Wk   = (const float*)d_in[2];
    const float* Wv   = (const float*)d_in[3];
    const float* Wo   = (const float*)d_in[4];
    const float* an_w = (const float*)d_in[5];
    const float* w0   = (const float*)d_in[6];
    const float* w1   = (const float*)d_in[7];
    const float* w2   = (const float*)d_in[8];
    const float* sn_w = (const float*)d_in[9];
    const float* on_w = (const float*)d_in[10];

    __nv_bfloat16 *hp16, *attnp;
    float *hp32, *qkv, *x, *ffp, *w01p, *w2p;
    unsigned *wqkvp, *wop;
    cudaGetSymbolAddress((void**)&hp16,  g_hp16);
    cudaGetSymbolAddress((void**)&hp32,  g_hp32);
    cudaGetSymbolAddress((void**)&qkv,   g_qkv);
    cudaGetSymbolAddress((void**)&attnp, g_attnp);
    cudaGetSymbolAddress((void**)&x,     g_x);
    cudaGetSymbolAddress((void**)&ffp,   g_ffp);
    cudaGetSymbolAddress((void**)&wqkvp, g_wqkvp);
    cudaGetSymbolAddress((void**)&wop,   g_wop);
    cudaGetSymbolAddress((void**)&w01p,  g_w01p);
    cudaGetSymbolAddress((void**)&w2p,   g_w2p);

    pack_all<<<PACK_BLKS, 256>>>(Wq, Wk, Wv, Wo, w0, w1, w2, wqkvp, wop, w01p, w2p);

    const float* cur = x_in;
    for (int li = 0; li < LAYERS; li++) {
        // attention side (bf16)
        rmsnorm_k<2><<<ROWS, 256>>>(cur, an_w + (size_t)li * DMODEL, hp16);

        tgemm16_k<0><<<dim3(QKVW / 128, ROWS / 128), 256>>>(
            hp16, wqkvp + (size_t)li * DMODEL * QKVW / 2, qkv, nullptr, QKVW, DMODEL);

        rope_packed<<<(ROWS * 16 * 32 + 255) / 256, 256>>>(qkv);

        flash_kernel<<<dim3(SEQ / 64, NHEADS, BATCH), 128>>>(qkv, attnp);

        tgemm16_k<1><<<dim3(DMODEL / 128, ROWS / 128), 256>>>(
            attnp, wop + (size_t)li * DMODEL * DMODEL / 2, x, cur, DMODEL, DMODEL);

        // FFN side (tf32)
        rmsnorm_k<1><<<ROWS, 256>>>(x, sn_w + (size_t)li * DMODEL, hp32);

        tgemm32_k<2><<<dim3(2 * FFDIM / 128, ROWS / 128), 256>>>(
            hp32, w01p + (size_t)li * DMODEL * 2 * FFDIM, ffp, nullptr, 2 * FFDIM, DMODEL);

        tgemm32_k<1><<<dim3(DMODEL / 128, ROWS / 128), 256>>>(
            ffp, w2p + (size_t)li * FFDIM * DMODEL, x, x, DMODEL, FFDIM);
        cur = x;
    }

    rmsnorm_k<0><<<ROWS, 256>>>(x, on_w, (float*)d_out);
}

// round 12
// speedup vs baseline: 4.8206x; 1.0715x over previous
#include <cuda_runtime.h>
#include <cuda_bf16.h>
#include <math.h>
#include <stdint.h>

// Problem constants
#define LAYERS 2
#define BATCH  2
#define SEQ    2048
#define DMODEL 768
#define NHEADS 12
#define KVHEADS 4
#define NREP   3
#define HEADD  64
#define FFDIM  3072
#define ROWS   (BATCH*SEQ)     // 4096
#define QKVW   1280            // 768 q + 256 k + 256 v

#define GEMM_SMEM (3 * 32768)  // 3 stages x 32KB

// ---------------------------------------------------------------------------
// Scratch (allocation-free: __device__ globals)
// Attention side = bf16, FFN side = tf32.
// ---------------------------------------------------------------------------
__device__ __nv_bfloat16 g_hp16[ROWS * DMODEL];
__device__ float         g_hp32[ROWS * DMODEL];
__device__ float         g_qkv[ROWS * QKVW];
__device__ __nv_bfloat16 g_attnp[ROWS * DMODEL];
__device__ float         g_x[ROWS * DMODEL];
__device__ float         g_ffp[ROWS * FFDIM];
__device__ unsigned g_wqkvp[LAYERS * DMODEL * QKVW / 2];
__device__ unsigned g_wop[LAYERS * DMODEL * DMODEL / 2];
__device__ float    g_w01p[LAYERS * DMODEL * 2 * FFDIM];
__device__ float    g_w2p[LAYERS * FFDIM * DMODEL];

// ---------------------------------------------------------------------------
// cp.async helpers
// ---------------------------------------------------------------------------
__device__ __forceinline__ uint32_t smem_u32(const void* p) {
    return (uint32_t)__cvta_generic_to_shared(p);
}
__device__ __forceinline__ void cp16(uint32_t dst, const void* src) {
    asm volatile("cp.async.cg.shared.global [%0], [%1], 16;" :: "r"(dst), "l"(src));
}
__device__ __forceinline__ void cp_commit() { asm volatile("cp.async.commit_group;"); }
__device__ __forceinline__ void cp_wait1()  { asm volatile("cp.async.wait_group 1;"); }

// ---------------------------------------------------------------------------
// tf32 helpers (m16n8k8)
// ---------------------------------------------------------------------------
__device__ __forceinline__ unsigned f2tf(float x) {
    unsigned r; asm("cvt.rna.tf32.f32 %0, %1;" : "=r"(r) : "f"(x)); return r;
}
__device__ __forceinline__ float tf32f(float x) { return __uint_as_float(f2tf(x)); }

__device__ __forceinline__ size_t aperm_off32(int m, int k) {
    return (size_t)(k >> 3) * 32768 + (size_t)(m >> 4) * 128
         + ((m & 7) * 4 + (k & 3)) * 4 + ((m >> 3) & 1) + 2 * ((k >> 2) & 1);
}

__device__ __forceinline__ void mma8(float* d, const unsigned* a, const unsigned* b) {
    asm volatile("mma.sync.aligned.m16n8k8.row.col.f32.tf32.tf32.f32 "
        "{%0,%1,%2,%3}, {%4,%5,%6,%7}, {%8,%9}, {%0,%1,%2,%3};"
        : "+f"(d[0]), "+f"(d[1]), "+f"(d[2]), "+f"(d[3])
        : "r"(a[0]), "r"(a[1]), "r"(a[2]), "r"(a[3]), "r"(b[0]), "r"(b[1]));
}

// ---------------------------------------------------------------------------
// bf16 helpers (m16n8k16)
// ---------------------------------------------------------------------------
__device__ __forceinline__ unsigned pack_bf16(float lo, float hi) {
    __nv_bfloat162 t = __floats2bfloat162_rn(lo, hi);
    return *reinterpret_cast<unsigned*>(&t);
}

__device__ __forceinline__ size_t aperm_off16(int m, int k) {
    return (size_t)(k >> 4) * 65536 + (size_t)(m >> 4) * 256
         + ((m & 7) * 4 + ((k >> 1) & 3)) * 8
         + (((m >> 3) & 1) + 2 * ((k >> 3) & 1)) * 2 + (k & 1);
}
__device__ __forceinline__ size_t aperm_woff16(int m, int k) {
    return (size_t)(k >> 4) * 32768 + (size_t)(m >> 4) * 128
         + ((m & 7) * 4 + ((k >> 1) & 3)) * 4
         + ((m >> 3) & 1) + 2 * ((k >> 3) & 1);
}

__device__ __forceinline__ void mma16(float* d, const unsigned* a, const unsigned* b) {
    asm volatile("mma.sync.aligned.m16n8k16.row.col.f32.bf16.bf16.f32 "
        "{%0,%1,%2,%3}, {%4,%5,%6,%7}, {%8,%9}, {%0,%1,%2,%3};"
        : "+f"(d[0]), "+f"(d[1]), "+f"(d[2]), "+f"(d[3])
        : "r"(a[0]), "r"(a[1]), "r"(a[2]), "r"(a[3]), "r"(b[0]), "r"(b[1]));
}

// ---------------------------------------------------------------------------
// Merged weight packing (one launch, 4 segments)
// ---------------------------------------------------------------------------
#define QKV_WORDS   (LAYERS * DMODEL * QKVW / 2)
#define WO_WORDS    (LAYERS * DMODEL * DMODEL / 2)
#define W01_PAIRS   (LAYERS * DMODEL * 2 * FFDIM / 2)
#define W2_PAIRS    (LAYERS * FFDIM * DMODEL / 2)
#define QKV_BLKS    ((QKV_WORDS + 255) / 256)
#define WO_BLKS     ((WO_WORDS + 255) / 256)
#define W01_BLKS    ((W01_PAIRS + 255) / 256)
#define W2_BLKS     ((W2_PAIRS + 255) / 256)
#define PACK_BLKS   (QKV_BLKS + WO_BLKS + W01_BLKS + W2_BLKS)

__device__ __forceinline__ void pack_coords16(int dw, int N, int& kbase, int& n) {
    int j  = dw & 1;
    int ln = (dw >> 1) & 31;
    int blk = dw >> 6;
    int n8cnt = N >> 3;
    int k16 = blk / n8cnt, n8 = blk - k16 * n8cnt;
    n = n8 * 8 + (ln >> 2);
    kbase = k16 * 16 + j * 8 + (ln & 3) * 2;
}
__device__ __forceinline__ void pack_coords32(int q, int N, int& k, int& n, int& dw) {
    dw = 2 * q;
    int block = dw >> 6;
    int lane  = (dw & 63) >> 1;
    int n8cnt = N >> 3;
    int k8 = block / n8cnt, n8 = block - k8 * n8cnt;
    n = n8 * 8 + (lane >> 2);
    k = k8 * 8 + (lane & 3);
}

__global__ void __launch_bounds__(256) pack_all(const float* __restrict__ Wq,
                                                const float* __restrict__ Wk,
                                                const float* __restrict__ Wv,
                                                const float* __restrict__ Wo,
                                                const float* __restrict__ w0,
                                                const float* __restrict__ w1,
                                                const float* __restrict__ w2,
                                                unsigned* __restrict__ wqkvp,
                                                unsigned* __restrict__ wop,
                                                float* __restrict__ w01p,
                                                float* __restrict__ w2p)
{
    int bid = blockIdx.x;
    if (bid < QKV_BLKS) {
        int p = bid * 256 + threadIdx.x;
        if (p >= QKV_WORDS) return;
        const int perL = DMODEL * QKVW / 2;
        int l = p / perL, dw = p - l * perL;
        int k, n; pack_coords16(dw, QKVW, k, n);
        float v0, v1;
        if (n < 768) {
            const float* s = Wq + ((size_t)l * DMODEL + k) * 768 + n;
            v0 = s[0]; v1 = s[768];
        } else if (n < 1024) {
            const float* s = Wk + ((size_t)l * DMODEL + k) * 256 + (n - 768);
            v0 = s[0]; v1 = s[256];
        } else {
            const float* s = Wv + ((size_t)l * DMODEL + k) * 256 + (n - 1024);
            v0 = s[0]; v1 = s[256];
        }
        wqkvp[(size_t)l * perL + dw] = pack_bf16(v0, v1);
    } else if (bid < QKV_BLKS + WO_BLKS) {
        int p = (bid - QKV_BLKS) * 256 + threadIdx.x;
        if (p >= WO_WORDS) return;
        const int perL = DMODEL * DMODEL / 2;
        int l = p / perL, dw = p - l * perL;
        int k, n; pack_coords16(dw, DMODEL, k, n);
        const float* s = Wo + ((size_t)l * DMODEL + k) * DMODEL + n;
        wop[(size_t)l * perL + dw] = pack_bf16(s[0], s[DMODEL]);
    } else if (bid < QKV_BLKS + WO_BLKS + W01_BLKS) {
        int p = (bid - QKV_BLKS - WO_BLKS) * 256 + threadIdx.x;
        if (p >= W01_PAIRS) return;
        const int perL = DMODEL * 2 * FFDIM / 2;
        int l = p / perL, q = p - l * perL;
        int k, n, dw; pack_coords32(q, 2 * FFDIM, k, n, dw);
        int f = n >> 1;
        const float* s = ((n & 1) ? w1 : w0) + ((size_t)l * DMODEL + k) * FFDIM + f;
        float2 o; o.x = tf32f(s[0]); o.y = tf32f(s[4 * FFDIM]);
        *(float2*)(w01p + (size_t)l * DMODEL * 2 * FFDIM + dw) = o;
    } else {
        int p = (bid - QKV_BLKS - WO_BLKS - W01_BLKS) * 256 + threadIdx.x;
        if (p >= W2_PAIRS) return;
        const int perL = FFDIM * DMODEL / 2;
        int l = p / perL, q = p - l * perL;
        int k, n, dw; pack_coords32(q, DMODEL, k, n, dw);
        const float* s = w2 + ((size_t)l * FFDIM + k) * DMODEL + n;
        float2 o; o.x = tf32f(s[0]); o.y = tf32f(s[(size_t)4 * DMODEL]);
        *(float2*)(w2p + (size_t)l * FFDIM * DMODEL + dw) = o;
    }
}

// ---------------------------------------------------------------------------
// RMSNorm: PERM 0 = fp32 row-major, 1 = tf32 A-perm, 2 = bf16 A-perm
// ---------------------------------------------------------------------------
template<int PERM>
__global__ void __launch_bounds__(256) rmsnorm_k(const float* __restrict__ x,
                                                 const float* __restrict__ w,
                                                 void* __restrict__ yv)
{
    int row = blockIdx.x;
    const float* xr = x + (size_t)row * DMODEL;
    int t = threadIdx.x;
    float v0 = xr[t], v1 = xr[t + 256], v2 = xr[t + 512];
    float ss = v0*v0 + v1*v1 + v2*v2;
    #pragma unroll
    for (int off = 16; off > 0; off >>= 1)
        ss += __shfl_xor_sync(0xffffffffu, ss, off);
    __shared__ float red[8];
    if ((t & 31) == 0) red[t >> 5] = ss;
    __syncthreads();
    if (t < 32) {
        float s = (t < 8) ? red[t] : 0.f;
        #pragma unroll
        for (int off = 4; off > 0; off >>= 1)
            s += __shfl_xor_sync(0xffffffffu, s, off);
        if (t == 0) red[0] = s;
    }
    __syncthreads();
    float inv = 1.0f / sqrtf(red[0] * (1.0f / DMODEL) + 1e-6f);
    float o0 = v0 * inv * w[t];
    float o1 = v1 * inv * w[t + 256];
    float o2 = v2 * inv * w[t + 512];
    if (PERM == 1) {
        float* y = (float*)yv;
        y[aperm_off32(row, t)]       = tf32f(o0);
        y[aperm_off32(row, t + 256)] = tf32f(o1);
        y[aperm_off32(row, t + 512)] = tf32f(o2);
    } else if (PERM == 2) {
        __nv_bfloat16* y = (__nv_bfloat16*)yv;
        y[aperm_off16(row, t)]       = __float2bfloat16(o0);
        y[aperm_off16(row, t + 256)] = __float2bfloat16(o1);
        y[aperm_off16(row, t + 512)] = __float2bfloat16(o2);
    } else {
        float* yr = (float*)yv + (size_t)row * DMODEL;
        yr[t] = o0; yr[t + 256] = o1; yr[t + 512] = o2;
    }
}

// ---------------------------------------------------------------------------
// RoPE on packed qkv (row-major fp32)
// ---------------------------------------------------------------------------
__global__ void __launch_bounds__(256) rope_packed(float* __restrict__ qkv)
{
    int idx = blockIdx.x * 256 + threadIdx.x;
    const int total = ROWS * 16 * 32;
    if (idx >= total) return;
    int i    = idx & 31;
    int hh   = (idx >> 5) & 15;
    int row  = idx >> 9;
    int s    = row & (SEQ - 1);
    float freq = (float)exp(-9.210340371976184 * ((double)i / 32.0));
    float ang = (float)s * freq;
    float sn, cs;
    sincosf(ang, &sn, &cs);
    int coff = (hh < 12) ? hh * 64 : 768 + (hh - 12) * 64;
    float* p = qkv + (size_t)row * QKVW + coff + 2 * i;
    float t0 = p[0], t1 = p[1];
    p[0] = t0 * cs - t1 * sn;
    p[1] = t0 * sn + t1 * cs;
}

// ---------------------------------------------------------------------------
// tf32 GEMM, 3-stage cp.async pipeline. K-tile = 32 (4 k8 steps / stage).
// Stage = 32KB; 3 stages = 96KB dynamic smem; 2 CTAs/SM (192KB <= 228KB).
// MODE 1: C = AB + R fp32; MODE 2: gated silu -> tf32 A-perm out (K'=N/2).
// ---------------------------------------------------------------------------
template<int MODE>
__global__ void __launch_bounds__(256, 2) tgemm32_k(const float* __restrict__ Ap,
                                                    const float* __restrict__ Bp,
                                                    float* __restrict__ C,
                                                    const float* __restrict__ R,
                                                    int N, int K)
{
    extern __shared__ float sm32[];  // 3 x 8192 floats; stage: A[0,4096) B[4096,8192)

    int tid = threadIdx.x, lane = tid & 31, warp = tid >> 5;
    int wm = warp >> 2, wn = warp & 3;
    int m0 = blockIdx.y * 128, n0 = blockIdx.x * 128;

    float acc[4][4][4];
    #pragma unroll
    for (int a = 0; a < 4; a++)
        #pragma unroll
        for (int b = 0; b < 4; b++)
            #pragma unroll
            for (int c = 0; c < 4; c++) acc[a][b][c] = 0.f;

    const int k8n = N >> 3;
    const float* Ag = Ap + (size_t)((m0 >> 4) + warp) * 128 + lane * 4;
    const float* Bg = Bp + (size_t)((n0 >> 3) + (tid >> 4)) * 64 + (tid & 15) * 4;

    uint32_t smBase = smem_u32(sm32);
    uint32_t aDst = smBase + (warp * 32 + lane) * 16;                      // +st*32768 + p*4096
    uint32_t bDst = smBase + 16384 + ((tid >> 4) * 16 + (tid & 15)) * 16;  // +st*32768 + p*4096

    const int ntiles = K >> 5;

    #pragma unroll
    for (int t = 0; t < 2; t++) {
        uint32_t sb = t * 32768;
        #pragma unroll
        for (int p = 0; p < 4; p++) {
            int q = 4 * t + p;
            cp16(aDst + sb + p * 4096, Ag + (size_t)q * 32768);
            cp16(bDst + sb + p * 4096, Bg + (size_t)q * k8n * 64);
        }
        cp_commit();
    }

    for (int kt = 0; kt < ntiles; kt++) {
        cp_wait1();
        __syncthreads();
        const float* S = sm32 + (kt % 3) * 8192;

        #pragma unroll
        for (int ks = 0; ks < 4; ks++) {
            unsigned af[4][4], bf[4][2];
            #pragma unroll
            for (int mt = 0; mt < 4; mt++)
                *(uint4*)af[mt] = *(const uint4*)&S[ks * 1024 + (wm * 4 + mt) * 128 + lane * 4];
            #pragma unroll
            for (int nt = 0; nt < 4; nt++)
                *(uint2*)bf[nt] = *(const uint2*)&S[4096 + ks * 1024 + (wn * 4 + nt) * 64 + lane * 2];
            #pragma unroll
            for (int mt = 0; mt < 4; mt++)
                #pragma unroll
                for (int nt = 0; nt < 4; nt++)
                    mma8(acc[mt][nt], af[mt], bf[nt]);
        }

        int kn = kt + 2;
        if (kn < ntiles) {
            uint32_t sb = (kn % 3) * 32768;
            #pragma unroll
            for (int p = 0; p < 4; p++) {
                int q = 4 * kn + p;
                cp16(aDst + sb + p * 4096, Ag + (size_t)q * 32768);
                cp16(bDst + sb + p * 4096, Bg + (size_t)q * k8n * 64);
            }
        }
        cp_commit();
    }

    int g = lane >> 2, tg = lane & 3;
    #pragma unroll
    for (int mt = 0; mt < 4; mt++) {
        int row = m0 + wm * 64 + mt * 16 + g;
        #pragma unroll
        for (int nt = 0; nt < 4; nt++) {
            float* c = acc[mt][nt];
            if (MODE == 2) {
                int f = (n0 >> 1) + wn * 16 + nt * 4 + tg;
                float s0 = c[0] / (1.0f + __expf(-c[0]));
                float s2 = c[2] / (1.0f + __expf(-c[2]));
                C[aperm_off32(row,     f)] = tf32f(s0 * c[1]);
                C[aperm_off32(row + 8, f)] = tf32f(s2 * c[3]);
            } else {
                int col = n0 + wn * 32 + nt * 8 + tg * 2;
                size_t i0 = (size_t)row * N + col;
                size_t i1 = i0 + (size_t)8 * N;
                float2 v0 = make_float2(c[0], c[1]);
                float2 v1 = make_float2(c[2], c[3]);
                if (MODE == 1) {
                    v0.x += R[i0]; v0.y += R[i0 + 1];
                    v1.x += R[i1]; v1.y += R[i1 + 1];
                }
                *(float2*)&C[i0] = v0;
                *(float2*)&C[i1] = v1;
            }
        }
    }
}

// ---------------------------------------------------------------------------
// bf16 GEMM, 3-stage cp.async pipeline. K-tile = 64 (4 k16 steps / stage).
// Stage = 32KB; 3 stages = 96KB dynamic smem; 2 CTAs/SM.
// MODE 0: C = AB fp32; MODE 1: C = AB + R fp32.
// ---------------------------------------------------------------------------
template<int MODE>
__global__ void __launch_bounds__(256, 2) tgemm16_k(const __nv_bfloat16* __restrict__ Ap,
                                                    const unsigned* __restrict__ Bp,
                                                    float* __restrict__ C,
                                                    const float* __restrict__ R,
                                                    int N, int K)
{
    extern __shared__ unsigned sm16[];  // 3 x 8192 words; stage: A[0,4096) B[4096,8192)

    int tid = threadIdx.x, lane = tid & 31, warp = tid >> 5;
    int wm = warp >> 2, wn = warp & 3;
    int m0 = blockIdx.y * 128, n0 = blockIdx.x * 128;

    float acc[4][4][4];
    #pragma unroll
    for (int a = 0; a < 4; a++)
        #pragma unroll
        for (int b = 0; b < 4; b++)
            #pragma unroll
            for (int c = 0; c < 4; c++) acc[a][b][c] = 0.f;

    const int n8cnt = N >> 3;
    const uint4* Ag = (const uint4*)Ap + (size_t)((m0 >> 4) + warp) * 32 + lane;
    const uint4* Bg = (const uint4*)Bp + (size_t)((n0 >> 3) + (tid >> 4)) * 16 + (tid & 15);

    uint32_t smBase = smem_u32(sm16);
    uint32_t aDst = smBase + (warp * 32 + lane) * 16;
    uint32_t bDst = smBase + 16384 + ((tid >> 4) * 16 + (tid & 15)) * 16;

    const int ntiles = K >> 6;

    #pragma unroll
    for (int t = 0; t < 2; t++) {
        uint32_t sb = t * 32768;
        #pragma unroll
        for (int p = 0; p < 4; p++) {
            int q = 4 * t + p;
            cp16(aDst + sb + p * 4096, Ag + (size_t)q * 8192);
            cp16(bDst + sb + p * 4096, Bg + (size_t)q * n8cnt * 16);
        }
        cp_commit();
    }

    for (int kt = 0; kt < ntiles; kt++) {
        cp_wait1();
        __syncthreads();
        const unsigned* S = sm16 + (kt % 3) * 8192;

        #pragma unroll
        for (int ks = 0; ks < 4; ks++) {
            unsigned af[4][4], bf[4][2];
            #pragma unroll
            for (int mt = 0; mt < 4; mt++)
                *(uint4*)af[mt] = *(const uint4*)&S[ks * 1024 + (wm * 4 + mt) * 128 + lane * 4];
            #pragma unroll
            for (int nt = 0; nt < 4; nt++)
                *(uint2*)bf[nt] = *(const uint2*)&S[4096 + ks * 1024 + (wn * 4 + nt) * 64 + lane * 2];
            #pragma unroll
            for (int mt = 0; mt < 4; mt++)
                #pragma unroll
                for (int nt = 0; nt < 4; nt++)
                    mma16(acc[mt][nt], af[mt], bf[nt]);
        }

        int kn = kt + 2;
        if (kn < ntiles) {
            uint32_t sb = (kn % 3) * 32768;
            #pragma unroll
            for (int p = 0; p < 4; p++) {
                int q = 4 * kn + p;
                cp16(aDst + sb + p * 4096, Ag + (size_t)q * 8192);
                cp16(bDst + sb + p * 4096, Bg + (size_t)q * n8cnt * 16);
            }
        }
        cp_commit();
    }

    int g = lane >> 2, tg = lane & 3;
    #pragma unroll
    for (int mt = 0; mt < 4; mt++) {
        int row = m0 + wm * 64 + mt * 16 + g;
        #pragma unroll
        for (int nt = 0; nt < 4; nt++) {
            float* c = acc[mt][nt];
            int col = n0 + wn * 32 + nt * 8 + tg * 2;
            size_t i0 = (size_t)row * N + col;
            size_t i1 = i0 + (size_t)8 * N;
            float2 v0 = make_float2(c[0], c[1]);
            float2 v1 = make_float2(c[2], c[3]);
            if (MODE == 1) {
                v0.x += R[i0]; v0.y += R[i0 + 1];
                v1.x += R[i1]; v1.y += R[i1 + 1];
            }
            *(float2*)&C[i0] = v0;
            *(float2*)&C[i1] = v1;
        }
    }
}

// ---------------------------------------------------------------------------
// bf16 tensor-core flash attention (verified R8/R10). Output bf16 A-perm.
// ---------------------------------------------------------------------------
__global__ void __launch_bounds__(128) flash_kernel(const float* __restrict__ qkv,
                                                    __nv_bfloat16* __restrict__ op)
{
    __shared__ unsigned Qs[4][4][32][4];
    __shared__ unsigned Ks[4][4][32][2];
    __shared__ unsigned Vs[2][8][32][2];
    __shared__ unsigned Ps[2][4][32][4];

    int qt = blockIdx.x, h = blockIdx.y, b = blockIdx.z;
    int kvh = h / NREP;
    int tid = threadIdx.x, lane = tid & 31, warp = tid >> 5;
    int g = lane >> 2, tg = lane & 3;
    int q0 = qt * 64;

    const float* qbase = qkv + (size_t)(b * SEQ + q0) * QKVW + h * HEADD;
    for (int w = tid; w < 2048; w += 128) {
        int j = w & 3, ln = (w >> 2) & 31, m16 = (w >> 7) & 3, d16 = w >> 9;
        int m = m16 * 16 + (j & 1) * 8 + (ln >> 2);
        int d = d16 * 16 + ((j >> 1) & 1) * 8 + (ln & 3) * 2;
        float2 qv = *(const float2*)(qbase + (size_t)m * QKVW + d);
        Qs[d16][m16][ln][j] = pack_bf16(qv.x, qv.y);
    }

    float mr0 = -INFINITY, mr1 = -INFINITY, l0 = 0.f, l1 = 0.f;
    float o_acc[8][4];
    #pragma unroll
    for (int nt = 0; nt < 8; nt++)
        #pragma unroll
        for (int c = 0; c < 4; c++) o_acc[nt][c] = 0.f;

    const float* kbase = qkv + (size_t)(b * SEQ) * QKVW + 768 + kvh * HEADD;
    const float* vbase = qkv + (size_t)(b * SEQ) * QKVW + 1024 + kvh * HEADD;

    int ntiles = 2 * qt + 2;
    for (int kt = 0; kt < ntiles; kt++) {
        __syncthreads();
        for (int w = tid; w < 1024; w += 128) {
            int j = w & 1, ln = (w >> 1) & 31;
            {
                int key8 = (w >> 6) & 3, d16 = w >> 8;
                int key = key8 * 8 + (ln >> 2);
                int d = d16 * 16 + j * 8 + (ln & 3) * 2;
                float2 kv = *(const float2*)(kbase + (size_t)(kt * 32 + key) * QKVW + d);
                Ks[d16][key8][ln][j] = pack_bf16(kv.x, kv.y);
            }
            {
                int d8 = (w >> 6) & 7, k16 = w >> 9;
                int dim = d8 * 8 + (ln >> 2);
                int key = k16 * 16 + j * 8 + (ln & 3) * 2;
                float v0 = vbase[(size_t)(kt * 32 + key) * QKVW + dim];
                float v1 = vbase[(size_t)(kt * 32 + key + 1) * QKVW + dim];
                Vs[k16][d8][ln][j] = pack_bf16(v0, v1);
            }
        }
        __syncthreads();

        float s[4][4];
        #pragma unroll
        for (int nt = 0; nt < 4; nt++)
            #pragma unroll
            for (int c = 0; c < 4; c++) s[nt][c] = 0.f;

        #pragma unroll
        for (int ks = 0; ks < 4; ks++) {
            unsigned af[4];
            *(uint4*)af = *(const uint4*)&Qs[ks][warp][lane][0];
            #pragma unroll
            for (int nt = 0; nt < 4; nt++) {
                unsigned bf[2];
                *(uint2*)bf = *(const uint2*)&Ks[ks][nt][lane][0];
                mma16(s[nt], af, bf);
            }
        }
        #pragma unroll
        for (int nt = 0; nt < 4; nt++)
            #pragma unroll
            for (int c = 0; c < 4; c++) s[nt][c] *= 0.125f;

        if (kt >= 2 * qt) {
            int qg0 = q0 + warp * 16 + g;
            int qg1 = qg0 + 8;
            #pragma unroll
            for (int nt = 0; nt < 4; nt++) {
                int kg = kt * 32 + nt * 8 + tg * 2;
                if (kg > qg0)     s[nt][0] = -INFINITY;
                if (kg + 1 > qg0) s[nt][1] = -INFINITY;
                if (kg > qg1)     s[nt][2] = -INFINITY;
                if (kg + 1 > qg1) s[nt][3] = -INFINITY;
            }
        }

        float mx0 = -INFINITY, mx1 = -INFINITY;
        #pragma unroll
        for (int nt = 0; nt < 4; nt++) {
            mx0 = fmaxf(mx0, fmaxf(s[nt][0], s[nt][1]));
            mx1 = fmaxf(mx1, fmaxf(s[nt][2], s[nt][3]));
        }
        mx0 = fmaxf(mx0, __shfl_xor_sync(0xffffffffu, mx0, 1));
        mx0 = fmaxf(mx0, __shfl_xor_sync(0xffffffffu, mx0, 2));
        mx1 = fmaxf(mx1, __shfl_xor_sync(0xffffffffu, mx1, 1));
        mx1 = fmaxf(mx1, __shfl_xor_sync(0xffffffffu, mx1, 2));
        float mn0 = fmaxf(mr0, mx0), mn1 = fmaxf(mr1, mx1);
        float sum0 = 0.f, sum1 = 0.f;
        #pragma unroll
        for (int nt = 0; nt < 4; nt++) {
            s[nt][0] = __expf(s[nt][0] - mn0);
            s[nt][1] = __expf(s[nt][1] - mn0);
            s[nt][2] = __expf(s[nt][2] - mn1);
            s[nt][3] = __expf(s[nt][3] - mn1);
            sum0 += s[nt][0] + s[nt][1];
            sum1 += s[nt][2] + s[nt][3];
        }
        sum0 += __shfl_xor_sync(0xffffffffu, sum0, 1);
        sum0 += __shfl_xor_sync(0xffffffffu, sum0, 2);
        sum1 += __shfl_xor_sync(0xffffffffu, sum1, 1);
        sum1 += __shfl_xor_sync(0xffffffffu, sum1, 2);
        float a0 = __expf(mr0 - mn0), a1 = __expf(mr1 - mn1);
        l0 = l0 * a0 + sum0;  l1 = l1 * a1 + sum1;
        mr0 = mn0;  mr1 = mn1;
        #pragma unroll
        for (int nt = 0; nt < 8; nt++) {
            o_acc[nt][0] *= a0; o_acc[nt][1] *= a0;
            o_acc[nt][2] *= a1; o_acc[nt][3] *= a1;
        }

        #pragma unroll
        for (int nt = 0; nt < 4; nt++) {
            Ps[nt >> 1][warp][lane][2 * (nt & 1)]     = pack_bf16(s[nt][0], s[nt][1]);
            Ps[nt >> 1][warp][lane][2 * (nt & 1) + 1] = pack_bf16(s[nt][2], s[nt][3]);
        }
        __syncwarp();

        #pragma unroll
        for (int kks = 0; kks < 2; kks++) {
            unsigned af[4];
            *(uint4*)af = *(const uint4*)&Ps[kks][warp][lane][0];
            #pragma unroll
            for (int nt = 0; nt < 8; nt++) {
                unsigned bf[2];
                *(uint2*)bf = *(const uint2*)&Vs[kks][nt][lane][0];
                mma16(o_acc[nt], af, bf);
            }
        }
        __syncwarp();
    }

    float inv0 = 1.0f / l0, inv1 = 1.0f / l1;
    int mrow = b * SEQ + q0 + warp * 16 + g;
    unsigned* opw = (unsigned*)op;
    #pragma unroll
    for (int nt = 0; nt < 8; nt++) {
        int col = h * HEADD + nt * 8 + tg * 2;
        opw[aperm_woff16(mrow,     col)] = pack_bf16(o_acc[nt][0] * inv0, o_acc[nt][1] * inv0);
        opw[aperm_woff16(mrow + 8, col)] = pack_bf16(o_acc[nt][2] * inv1, o_acc[nt][3] * inv1);
    }
}

// ---------------------------------------------------------------------------
// Launch sequence
// ---------------------------------------------------------------------------
extern "C" void kernel_launch(void* const* d_in, const int* in_sizes, int n_in,
                              void* d_out, int out_size)
{
    (void)in_sizes; (void)n_in; (void)out_size;
    const float* x_in = (const float*)d_in[0];
    const float* Wq   = (const float*)d_in[1];
    const float* Wk   = (const float*)d_in[2];
    const float* Wv   = (const float*)d_in[3];
    const float* Wo   = (const float*)d_in[4];
    const float* an_w = (const float*)d_in[5];
    const float* w0   = (const float*)d_in[6];
    const float* w1   = (const float*)d_in[7];
    const float* w2   = (const float*)d_in[8];
    const float* sn_w = (const float*)d_in[9];
    const float* on_w = (const float*)d_in[10];

    __nv_bfloat16 *hp16, *attnp;
    float *hp32, *qkv, *x, *ffp, *w01p, *w2p;
    unsigned *wqkvp, *wop;
    cudaGetSymbolAddress((void**)&hp16,  g_hp16);
    cudaGetSymbolAddress((void**)&hp32,  g_hp32);
    cudaGetSymbolAddress((void**)&qkv,   g_qkv);
    cudaGetSymbolAddress((void**)&attnp, g_attnp);
    cudaGetSymbolAddress((void**)&x,     g_x);
    cudaGetSymbolAddress((void**)&ffp,   g_ffp);
    cudaGetSymbolAddress((void**)&wqkvp, g_wqkvp);
    cudaGetSymbolAddress((void**)&wop,   g_wop);
    cudaGetSymbolAddress((void**)&w01p,  g_w01p);
    cudaGetSymbolAddress((void**)&w2p,   g_w2p);

    // allow 96KB dynamic smem (idempotent; legal during capture — not a stream op)
    cudaFuncSetAttribute(tgemm32_k<1>, cudaFuncAttributeMaxDynamicSharedMemorySize, GEMM_SMEM);
    cudaFuncSetAttribute(tgemm32_k<2>, cudaFuncAttributeMaxDynamicSharedMemorySize, GEMM_SMEM);
    cudaFuncSetAttribute(tgemm16_k<0>, cudaFuncAttributeMaxDynamicSharedMemorySize, GEMM_SMEM);
    cudaFuncSetAttribute(tgemm16_k<1>, cudaFuncAttributeMaxDynamicSharedMemorySize, GEMM_SMEM);

    pack_all<<<PACK_BLKS, 256>>>(Wq, Wk, Wv, Wo, w0, w1, w2, wqkvp, wop, w01p, w2p);

    const float* cur = x_in;
    for (int li = 0; li < LAYERS; li++) {
        // attention side (bf16)
        rmsnorm_k<2><<<ROWS, 256>>>(cur, an_w + (size_t)li * DMODEL, hp16);

        tgemm16_k<0><<<dim3(QKVW / 128, ROWS / 128), 256, GEMM_SMEM>>>(
            hp16, wqkvp + (size_t)li * DMODEL * QKVW / 2, qkv, nullptr, QKVW, DMODEL);

        rope_packed<<<(ROWS * 16 * 32 + 255) / 256, 256>>>(qkv);

        flash_kernel<<<dim3(SEQ / 64, NHEADS, BATCH), 128>>>(qkv, attnp);

        tgemm16_k<1><<<dim3(DMODEL / 128, ROWS / 128), 256, GEMM_SMEM>>>(
            attnp, wop + (size_t)li * DMODEL * DMODEL / 2, x, cur, DMODEL, DMODEL);

        // FFN side (tf32)
        rmsnorm_k<1><<<ROWS, 256>>>(x, sn_w + (size_t)li * DMODEL, hp32);

        tgemm32_k<2><<<dim3(2 * FFDIM / 128, ROWS / 128), 256, GEMM_SMEM>>>(
            hp32, w01p + (size_t)li * DMODEL * 2 * FFDIM, ffp, nullptr, 2 * FFDIM, DMODEL);

        tgemm32_k<1><<<dim3(DMODEL / 128, ROWS / 128), 256, GEMM_SMEM>>>(
            ffp, w2p + (size_t)li * FFDIM * DMODEL, x, x, DMODEL, FFDIM);
        cur = x;
    }

    rmsnorm_k<0><<<ROWS, 256>>>(x, on_w, (float*)d_out);
}

// round 13
// speedup vs baseline: 6.4074x; 1.3292x over previous
#include <cuda_runtime.h>
#include <cuda_bf16.h>
#include <cuda_fp16.h>
#include <math.h>
#include <stdint.h>

// Problem constants
#define LAYERS 2
#define BATCH  2
#define SEQ    2048
#define DMODEL 768
#define NHEADS 12
#define KVHEADS 4
#define NREP   3
#define HEADD  64
#define FFDIM  3072
#define ROWS   (BATCH*SEQ)     // 4096
#define QKVW   1280            // 768 q + 256 k + 256 v

#define GEMM_SMEM (3 * 32768)  // 3 stages x 32KB

// ---------------------------------------------------------------------------
// Scratch (allocation-free: __device__ globals)
// Attention side = bf16, FFN side = fp16 (same eps as tf32, 2x speed).
// ---------------------------------------------------------------------------
__device__ __nv_bfloat16 g_hp16[ROWS * DMODEL];    // rmsnorm out, bf16 A-perm
__device__ __half        g_hpf[ROWS * DMODEL];     // rmsnorm out, fp16 A-perm
__device__ float         g_qkv[ROWS * QKVW];       // row-major fp32
__device__ __nv_bfloat16 g_attnp[ROWS * DMODEL];   // attention out, bf16 A-perm
__device__ float         g_x[ROWS * DMODEL];       // residual stream fp32
__device__ __half        g_ffp[ROWS * FFDIM];      // FFN intermediate, fp16 A-perm
__device__ unsigned g_wqkvp[LAYERS * DMODEL * QKVW / 2];     // bf16 B-perm words
__device__ unsigned g_wop[LAYERS * DMODEL * DMODEL / 2];     // bf16 B-perm words
__device__ unsigned g_w01p[LAYERS * DMODEL * 2 * FFDIM / 2]; // fp16 B-perm words
__device__ unsigned g_w2p[LAYERS * FFDIM * DMODEL / 2];      // fp16 B-perm words

// ---------------------------------------------------------------------------
// cp.async helpers
// ---------------------------------------------------------------------------
__device__ __forceinline__ uint32_t smem_u32(const void* p) {
    return (uint32_t)__cvta_generic_to_shared(p);
}
__device__ __forceinline__ void cp16(uint32_t dst, const void* src) {
    asm volatile("cp.async.cg.shared.global [%0], [%1], 16;" :: "r"(dst), "l"(src));
}
__device__ __forceinline__ void cp_commit() { asm volatile("cp.async.commit_group;"); }
__device__ __forceinline__ void cp_wait1()  { asm volatile("cp.async.wait_group 1;"); }

// ---------------------------------------------------------------------------
// 16-bit packing helpers + shared k16 fragment layouts
// A perm (elements): lane=(m&7)*4+((k>>1)&3), j=((m>>3)&1)+2*((k>>3)&1), h=k&1
// B perm (words):    lane=(n&7)*4+((k>>1)&3), j=(k>>3)&1
// ---------------------------------------------------------------------------
__device__ __forceinline__ unsigned pack_bf16(float lo, float hi) {
    __nv_bfloat162 t = __floats2bfloat162_rn(lo, hi);
    return *reinterpret_cast<unsigned*>(&t);
}
__device__ __forceinline__ unsigned pack_f16(float lo, float hi) {
    __half2 t = __floats2half2_rn(lo, hi);
    return *reinterpret_cast<unsigned*>(&t);
}

__device__ __forceinline__ size_t aperm_off16(int m, int k) {  // element offset
    return (size_t)(k >> 4) * 65536 + (size_t)(m >> 4) * 256
         + ((m & 7) * 4 + ((k >> 1) & 3)) * 8
         + (((m >> 3) & 1) + 2 * ((k >> 3) & 1)) * 2 + (k & 1);
}
__device__ __forceinline__ size_t aperm_woff16(int m, int k) { // word offset, k even
    return (size_t)(k >> 4) * 32768 + (size_t)(m >> 4) * 128
         + ((m & 7) * 4 + ((k >> 1) & 3)) * 4
         + ((m >> 3) & 1) + 2 * ((k >> 3) & 1);
}

template<bool FP16>
__device__ __forceinline__ void mma16(float* d, const unsigned* a, const unsigned* b);

template<>
__device__ __forceinline__ void mma16<false>(float* d, const unsigned* a, const unsigned* b) {
    asm volatile("mma.sync.aligned.m16n8k16.row.col.f32.bf16.bf16.f32 "
        "{%0,%1,%2,%3}, {%4,%5,%6,%7}, {%8,%9}, {%0,%1,%2,%3};"
        : "+f"(d[0]), "+f"(d[1]), "+f"(d[2]), "+f"(d[3])
        : "r"(a[0]), "r"(a[1]), "r"(a[2]), "r"(a[3]), "r"(b[0]), "r"(b[1]));
}
template<>
__device__ __forceinline__ void mma16<true>(float* d, const unsigned* a, const unsigned* b) {
    asm volatile("mma.sync.aligned.m16n8k16.row.col.f32.f16.f16.f32 "
        "{%0,%1,%2,%3}, {%4,%5,%6,%7}, {%8,%9}, {%0,%1,%2,%3};"
        : "+f"(d[0]), "+f"(d[1]), "+f"(d[2]), "+f"(d[3])
        : "r"(a[0]), "r"(a[1]), "r"(a[2]), "r"(a[3]), "r"(b[0]), "r"(b[1]));
}

// ---------------------------------------------------------------------------
// Merged weight packing (one launch, 4 segments, all k16 B layout)
// ---------------------------------------------------------------------------
#define QKV_WORDS   (LAYERS * DMODEL * QKVW / 2)
#define WO_WORDS    (LAYERS * DMODEL * DMODEL / 2)
#define W01_WORDS   (LAYERS * DMODEL * 2 * FFDIM / 2)
#define W2_WORDS    (LAYERS * FFDIM * DMODEL / 2)
#define QKV_BLKS    ((QKV_WORDS + 255) / 256)
#define WO_BLKS     ((WO_WORDS + 255) / 256)
#define W01_BLKS    ((W01_WORDS + 255) / 256)
#define W2_BLKS     ((W2_WORDS + 255) / 256)
#define PACK_BLKS   (QKV_BLKS + WO_BLKS + W01_BLKS + W2_BLKS)

__device__ __forceinline__ void pack_coords16(int dw, int N, int& kbase, int& n) {
    int j  = dw & 1;
    int ln = (dw >> 1) & 31;
    int blk = dw >> 6;
    int n8cnt = N >> 3;
    int k16 = blk / n8cnt, n8 = blk - k16 * n8cnt;
    n = n8 * 8 + (ln >> 2);
    kbase = k16 * 16 + j * 8 + (ln & 3) * 2;
}

__global__ void __launch_bounds__(256) pack_all(const float* __restrict__ Wq,
                                                const float* __restrict__ Wk,
                                                const float* __restrict__ Wv,
                                                const float* __restrict__ Wo,
                                                const float* __restrict__ w0,
                                                const float* __restrict__ w1,
                                                const float* __restrict__ w2,
                                                unsigned* __restrict__ wqkvp,
                                                unsigned* __restrict__ wop,
                                                unsigned* __restrict__ w01p,
                                                unsigned* __restrict__ w2p)
{
    int bid = blockIdx.x;
    if (bid < QKV_BLKS) {
        int p = bid * 256 + threadIdx.x;
        if (p >= QKV_WORDS) return;
        const int perL = DMODEL * QKVW / 2;
        int l = p / perL, dw = p - l * perL;
        int k, n; pack_coords16(dw, QKVW, k, n);
        float v0, v1;
        if (n < 768) {
            const float* s = Wq + ((size_t)l * DMODEL + k) * 768 + n;
            v0 = s[0]; v1 = s[768];
        } else if (n < 1024) {
            const float* s = Wk + ((size_t)l * DMODEL + k) * 256 + (n - 768);
            v0 = s[0]; v1 = s[256];
        } else {
            const float* s = Wv + ((size_t)l * DMODEL + k) * 256 + (n - 1024);
            v0 = s[0]; v1 = s[256];
        }
        wqkvp[(size_t)l * perL + dw] = pack_bf16(v0, v1);
    } else if (bid < QKV_BLKS + WO_BLKS) {
        int p = (bid - QKV_BLKS) * 256 + threadIdx.x;
        if (p >= WO_WORDS) return;
        const int perL = DMODEL * DMODEL / 2;
        int l = p / perL, dw = p - l * perL;
        int k, n; pack_coords16(dw, DMODEL, k, n);
        const float* s = Wo + ((size_t)l * DMODEL + k) * DMODEL + n;
        wop[(size_t)l * perL + dw] = pack_bf16(s[0], s[DMODEL]);
    } else if (bid < QKV_BLKS + WO_BLKS + W01_BLKS) {
        int p = (bid - QKV_BLKS - WO_BLKS) * 256 + threadIdx.x;
        if (p >= W01_WORDS) return;
        const int perL = DMODEL * 2 * FFDIM / 2;
        int l = p / perL, dw = p - l * perL;
        int k, n; pack_coords16(dw, 2 * FFDIM, k, n);
        int f = n >> 1;
        const float* s = ((n & 1) ? w1 : w0) + ((size_t)l * DMODEL + k) * FFDIM + f;
        w01p[(size_t)l * perL + dw] = pack_f16(s[0], s[FFDIM]);
    } else {
        int p = (bid - QKV_BLKS - WO_BLKS - W01_BLKS) * 256 + threadIdx.x;
        if (p >= W2_WORDS) return;
        const int perL = FFDIM * DMODEL / 2;
        int l = p / perL, dw = p - l * perL;
        int k, n; pack_coords16(dw, DMODEL, k, n);
        const float* s = w2 + ((size_t)l * FFDIM + k) * DMODEL + n;
        w2p[(size_t)l * perL + dw] = pack_f16(s[0], s[DMODEL]);
    }
}

// ---------------------------------------------------------------------------
// RMSNorm: PERM 0 = fp32 row-major, 1 = fp16 A-perm, 2 = bf16 A-perm
// ---------------------------------------------------------------------------
template<int PERM>
__global__ void __launch_bounds__(256) rmsnorm_k(const float* __restrict__ x,
                                                 const float* __restrict__ w,
                                                 void* __restrict__ yv)
{
    int row = blockIdx.x;
    const float* xr = x + (size_t)row * DMODEL;
    int t = threadIdx.x;
    float v0 = xr[t], v1 = xr[t + 256], v2 = xr[t + 512];
    float ss = v0*v0 + v1*v1 + v2*v2;
    #pragma unroll
    for (int off = 16; off > 0; off >>= 1)
        ss += __shfl_xor_sync(0xffffffffu, ss, off);
    __shared__ float red[8];
    if ((t & 31) == 0) red[t >> 5] = ss;
    __syncthreads();
    if (t < 32) {
        float s = (t < 8) ? red[t] : 0.f;
        #pragma unroll
        for (int off = 4; off > 0; off >>= 1)
            s += __shfl_xor_sync(0xffffffffu, s, off);
        if (t == 0) red[0] = s;
    }
    __syncthreads();
    float inv = 1.0f / sqrtf(red[0] * (1.0f / DMODEL) + 1e-6f);
    float o0 = v0 * inv * w[t];
    float o1 = v1 * inv * w[t + 256];
    float o2 = v2 * inv * w[t + 512];
    if (PERM == 1) {
        __half* y = (__half*)yv;
        y[aperm_off16(row, t)]       = __float2half_rn(o0);
        y[aperm_off16(row, t + 256)] = __float2half_rn(o1);
        y[aperm_off16(row, t + 512)] = __float2half_rn(o2);
    } else if (PERM == 2) {
        __nv_bfloat16* y = (__nv_bfloat16*)yv;
        y[aperm_off16(row, t)]       = __float2bfloat16(o0);
        y[aperm_off16(row, t + 256)] = __float2bfloat16(o1);
        y[aperm_off16(row, t + 512)] = __float2bfloat16(o2);
    } else {
        float* yr = (float*)yv + (size_t)row * DMODEL;
        yr[t] = o0; yr[t + 256] = o1; yr[t + 512] = o2;
    }
}

// ---------------------------------------------------------------------------
// RoPE on packed qkv (row-major fp32)
// ---------------------------------------------------------------------------
__global__ void __launch_bounds__(256) rope_packed(float* __restrict__ qkv)
{
    int idx = blockIdx.x * 256 + threadIdx.x;
    const int total = ROWS * 16 * 32;
    if (idx >= total) return;
    int i    = idx & 31;
    int hh   = (idx >> 5) & 15;
    int row  = idx >> 9;
    int s    = row & (SEQ - 1);
    float freq = (float)exp(-9.210340371976184 * ((double)i / 32.0));
    float ang = (float)s * freq;
    float sn, cs;
    sincosf(ang, &sn, &cs);
    int coff = (hh < 12) ? hh * 64 : 768 + (hh - 12) * 64;
    float* p = qkv + (size_t)row * QKVW + coff + 2 * i;
    float t0 = p[0], t1 = p[1];
    p[0] = t0 * cs - t1 * sn;
    p[1] = t0 * sn + t1 * cs;
}

// ---------------------------------------------------------------------------
// 16-bit tensor-core GEMM, 3-stage cp.async pipeline. K-tile = 64
// (4 k16 steps / stage). Stage = 32KB; 96KB dynamic smem; 2 CTAs/SM.
// FP16 selects f16 vs bf16 mma (identical layouts).
// MODE 0: C = AB fp32 row-major
// MODE 1: C = AB + R fp32 row-major (R may alias C)
// MODE 2: interleaved (w0,w1) cols -> silu(c0)*c1, fp16 A-perm out (K'=N/2)
// ---------------------------------------------------------------------------
template<int MODE, bool FP16>
__global__ void __launch_bounds__(256, 2) tgemm16_k(const void* __restrict__ Ap_,
                                                    const unsigned* __restrict__ Bp,
                                                    void* __restrict__ C_,
                                                    const float* __restrict__ R,
                                                    int N, int K)
{
    extern __shared__ unsigned sm16[];  // 3 x 8192 words; stage: A[0,4096) B[4096,8192)

    int tid = threadIdx.x, lane = tid & 31, warp = tid >> 5;
    int wm = warp >> 2, wn = warp & 3;
    int m0 = blockIdx.y * 128, n0 = blockIdx.x * 128;

    float acc[4][4][4];
    #pragma unroll
    for (int a = 0; a < 4; a++)
        #pragma unroll
        for (int b = 0; b < 4; b++)
            #pragma unroll
            for (int c = 0; c < 4; c++) acc[a][b][c] = 0.f;

    const int n8cnt = N >> 3;
    const uint4* Ag = (const uint4*)Ap_ + (size_t)((m0 >> 4) + warp) * 32 + lane;
    const uint4* Bg = (const uint4*)Bp + (size_t)((n0 >> 3) + (tid >> 4)) * 16 + (tid & 15);

    uint32_t smBase = smem_u32(sm16);
    uint32_t aDst = smBase + (warp * 32 + lane) * 16;
    uint32_t bDst = smBase + 16384 + ((tid >> 4) * 16 + (tid & 15)) * 16;

    const int ntiles = K >> 6;

    #pragma unroll
    for (int t = 0; t < 2; t++) {
        uint32_t sb = t * 32768;
        #pragma unroll
        for (int p = 0; p < 4; p++) {
            int q = 4 * t + p;
            cp16(aDst + sb + p * 4096, Ag + (size_t)q * 8192);
            cp16(bDst + sb + p * 4096, Bg + (size_t)q * n8cnt * 16);
        }
        cp_commit();
    }

    for (int kt = 0; kt < ntiles; kt++) {
        cp_wait1();
        __syncthreads();
        const unsigned* S = sm16 + (kt % 3) * 8192;

        #pragma unroll
        for (int ks = 0; ks < 4; ks++) {
            unsigned af[4][4], bf[4][2];
            #pragma unroll
            for (int mt = 0; mt < 4; mt++)
                *(uint4*)af[mt] = *(const uint4*)&S[ks * 1024 + (wm * 4 + mt) * 128 + lane * 4];
            #pragma unroll
            for (int nt = 0; nt < 4; nt++)
                *(uint2*)bf[nt] = *(const uint2*)&S[4096 + ks * 1024 + (wn * 4 + nt) * 64 + lane * 2];
            #pragma unroll
            for (int mt = 0; mt < 4; mt++)
                #pragma unroll
                for (int nt = 0; nt < 4; nt++)
                    mma16<FP16>(acc[mt][nt], af[mt], bf[nt]);
        }

        int kn = kt + 2;
        if (kn < ntiles) {
            uint32_t sb = (kn % 3) * 32768;
            #pragma unroll
            for (int p = 0; p < 4; p++) {
                int q = 4 * kn + p;
                cp16(aDst + sb + p * 4096, Ag + (size_t)q * 8192);
                cp16(bDst + sb + p * 4096, Bg + (size_t)q * n8cnt * 16);
            }
        }
        cp_commit();
    }

    int g = lane >> 2, tg = lane & 3;
    #pragma unroll
    for (int mt = 0; mt < 4; mt++) {
        int row = m0 + wm * 64 + mt * 16 + g;
        #pragma unroll
        for (int nt = 0; nt < 4; nt++) {
            float* c = acc[mt][nt];
            if (MODE == 2) {
                int f = (n0 >> 1) + wn * 16 + nt * 4 + tg;
                float s0 = c[0] / (1.0f + __expf(-c[0]));
                float s2 = c[2] / (1.0f + __expf(-c[2]));
                __half* Cb = (__half*)C_;
                Cb[aperm_off16(row,     f)] = __float2half_rn(s0 * c[1]);
                Cb[aperm_off16(row + 8, f)] = __float2half_rn(s2 * c[3]);
            } else {
                float* C = (float*)C_;
                int col = n0 + wn * 32 + nt * 8 + tg * 2;
                size_t i0 = (size_t)row * N + col;
                size_t i1 = i0 + (size_t)8 * N;
                float2 v0 = make_float2(c[0], c[1]);
                float2 v1 = make_float2(c[2], c[3]);
                if (MODE == 1) {
                    v0.x += R[i0]; v0.y += R[i0 + 1];
                    v1.x += R[i1]; v1.y += R[i1 + 1];
                }
                *(float2*)&C[i0] = v0;
                *(float2*)&C[i1] = v1;
            }
        }
    }
}

// ---------------------------------------------------------------------------
// bf16 tensor-core flash attention (verified R8/R10/R12). Output bf16 A-perm.
// ---------------------------------------------------------------------------
__global__ void __launch_bounds__(128) flash_kernel(const float* __restrict__ qkv,
                                                    __nv_bfloat16* __restrict__ op)
{
    __shared__ unsigned Qs[4][4][32][4];
    __shared__ unsigned Ks[4][4][32][2];
    __shared__ unsigned Vs[2][8][32][2];
    __shared__ unsigned Ps[2][4][32][4];

    int qt = blockIdx.x, h = blockIdx.y, b = blockIdx.z;
    int kvh = h / NREP;
    int tid = threadIdx.x, lane = tid & 31, warp = tid >> 5;
    int g = lane >> 2, tg = lane & 3;
    int q0 = qt * 64;

    const float* qbase = qkv + (size_t)(b * SEQ + q0) * QKVW + h * HEADD;
    for (int w = tid; w < 2048; w += 128) {
        int j = w & 3, ln = (w >> 2) & 31, m16 = (w >> 7) & 3, d16 = w >> 9;
        int m = m16 * 16 + (j & 1) * 8 + (ln >> 2);
        int d = d16 * 16 + ((j >> 1) & 1) * 8 + (ln & 3) * 2;
        float2 qv = *(const float2*)(qbase + (size_t)m * QKVW + d);
        Qs[d16][m16][ln][j] = pack_bf16(qv.x, qv.y);
    }

    float mr0 = -INFINITY, mr1 = -INFINITY, l0 = 0.f, l1 = 0.f;
    float o_acc[8][4];
    #pragma unroll
    for (int nt = 0; nt < 8; nt++)
        #pragma unroll
        for (int c = 0; c < 4; c++) o_acc[nt][c] = 0.f;

    const float* kbase = qkv + (size_t)(b * SEQ) * QKVW + 768 + kvh * HEADD;
    const float* vbase = qkv + (size_t)(b * SEQ) * QKVW + 1024 + kvh * HEADD;

    int ntiles = 2 * qt + 2;
    for (int kt = 0; kt < ntiles; kt++) {
        __syncthreads();
        for (int w = tid; w < 1024; w += 128) {
            int j = w & 1, ln = (w >> 1) & 31;
            {
                int key8 = (w >> 6) & 3, d16 = w >> 8;
                int key = key8 * 8 + (ln >> 2);
                int d = d16 * 16 + j * 8 + (ln & 3) * 2;
                float2 kv = *(const float2*)(kbase + (size_t)(kt * 32 + key) * QKVW + d);
                Ks[d16][key8][ln][j] = pack_bf16(kv.x, kv.y);
            }
            {
                int d8 = (w >> 6) & 7, k16 = w >> 9;
                int dim = d8 * 8 + (ln >> 2);
                int key = k16 * 16 + j * 8 + (ln & 3) * 2;
                float v0 = vbase[(size_t)(kt * 32 + key) * QKVW + dim];
                float v1 = vbase[(size_t)(kt * 32 + key + 1) * QKVW + dim];
                Vs[k16][d8][ln][j] = pack_bf16(v0, v1);
            }
        }
        __syncthreads();

        float s[4][4];
        #pragma unroll
        for (int nt = 0; nt < 4; nt++)
            #pragma unroll
            for (int c = 0; c < 4; c++) s[nt][c] = 0.f;

        #pragma unroll
        for (int ks = 0; ks < 4; ks++) {
            unsigned af[4];
            *(uint4*)af = *(const uint4*)&Qs[ks][warp][lane][0];
            #pragma unroll
            for (int nt = 0; nt < 4; nt++) {
                unsigned bf[2];
                *(uint2*)bf = *(const uint2*)&Ks[ks][nt][lane][0];
                mma16<false>(s[nt], af, bf);
            }
        }
        #pragma unroll
        for (int nt = 0; nt < 4; nt++)
            #pragma unroll
            for (int c = 0; c < 4; c++) s[nt][c] *= 0.125f;

        if (kt >= 2 * qt) {
            int qg0 = q0 + warp * 16 + g;
            int qg1 = qg0 + 8;
            #pragma unroll
            for (int nt = 0; nt < 4; nt++) {
                int kg = kt * 32 + nt * 8 + tg * 2;
                if (kg > qg0)     s[nt][0] = -INFINITY;
                if (kg + 1 > qg0) s[nt][1] = -INFINITY;
                if (kg > qg1)     s[nt][2] = -INFINITY;
                if (kg + 1 > qg1) s[nt][3] = -INFINITY;
            }
        }

        float mx0 = -INFINITY, mx1 = -INFINITY;
        #pragma unroll
        for (int nt = 0; nt < 4; nt++) {
            mx0 = fmaxf(mx0, fmaxf(s[nt][0], s[nt][1]));
            mx1 = fmaxf(mx1, fmaxf(s[nt][2], s[nt][3]));
        }
        mx0 = fmaxf(mx0, __shfl_xor_sync(0xffffffffu, mx0, 1));
        mx0 = fmaxf(mx0, __shfl_xor_sync(0xffffffffu, mx0, 2));
        mx1 = fmaxf(mx1, __shfl_xor_sync(0xffffffffu, mx1, 1));
        mx1 = fmaxf(mx1, __shfl_xor_sync(0xffffffffu, mx1, 2));
        float mn0 = fmaxf(mr0, mx0), mn1 = fmaxf(mr1, mx1);
        float sum0 = 0.f, sum1 = 0.f;
        #pragma unroll
        for (int nt = 0; nt < 4; nt++) {
            s[nt][0] = __expf(s[nt][0] - mn0);
            s[nt][1] = __expf(s[nt][1] - mn0);
            s[nt][2] = __expf(s[nt][2] - mn1);
            s[nt][3] = __expf(s[nt][3] - mn1);
            sum0 += s[nt][0] + s[nt][1];
            sum1 += s[nt][2] + s[nt][3];
        }
        sum0 += __shfl_xor_sync(0xffffffffu, sum0, 1);
        sum0 += __shfl_xor_sync(0xffffffffu, sum0, 2);
        sum1 += __shfl_xor_sync(0xffffffffu, sum1, 1);
        sum1 += __shfl_xor_sync(0xffffffffu, sum1, 2);
        float a0 = __expf(mr0 - mn0), a1 = __expf(mr1 - mn1);
        l0 = l0 * a0 + sum0;  l1 = l1 * a1 + sum1;
        mr0 = mn0;  mr1 = mn1;
        #pragma unroll
        for (int nt = 0; nt < 8; nt++) {
            o_acc[nt][0] *= a0; o_acc[nt][1] *= a0;
            o_acc[nt][2] *= a1; o_acc[nt][3] *= a1;
        }

        #pragma unroll
        for (int nt = 0; nt < 4; nt++) {
            Ps[nt >> 1][warp][lane][2 * (nt & 1)]     = pack_bf16(s[nt][0], s[nt][1]);
            Ps[nt >> 1][warp][lane][2 * (nt & 1) + 1] = pack_bf16(s[nt][2], s[nt][3]);
        }
        __syncwarp();

        #pragma unroll
        for (int kks = 0; kks < 2; kks++) {
            unsigned af[4];
            *(uint4*)af = *(const uint4*)&Ps[kks][warp][lane][0];
            #pragma unroll
            for (int nt = 0; nt < 8; nt++) {
                unsigned bf[2];
                *(uint2*)bf = *(const uint2*)&Vs[kks][nt][lane][0];
                mma16<false>(o_acc[nt], af, bf);
            }
        }
        __syncwarp();
    }

    float inv0 = 1.0f / l0, inv1 = 1.0f / l1;
    int mrow = b * SEQ + q0 + warp * 16 + g;
    unsigned* opw = (unsigned*)op;
    #pragma unroll
    for (int nt = 0; nt < 8; nt++) {
        int col = h * HEADD + nt * 8 + tg * 2;
        opw[aperm_woff16(mrow,     col)] = pack_bf16(o_acc[nt][0] * inv0, o_acc[nt][1] * inv0);
        opw[aperm_woff16(mrow + 8, col)] = pack_bf16(o_acc[nt][2] * inv1, o_acc[nt][3] * inv1);
    }
}

// ---------------------------------------------------------------------------
// Launch sequence
// ---------------------------------------------------------------------------
extern "C" void kernel_launch(void* const* d_in, const int* in_sizes, int n_in,
                              void* d_out, int out_size)
{
    (void)in_sizes; (void)n_in; (void)out_size;
    const float* x_in = (const float*)d_in[0];
    const float* Wq   = (const float*)d_in[1];
    const float* Wk   = (const float*)d_in[2];
    const float* Wv   = (const float*)d_in[3];
    const float* Wo   = (const float*)d_in[4];
    const float* an_w = (const float*)d_in[5];
    const float* w0   = (const float*)d_in[6];
    const float* w1   = (const float*)d_in[7];
    const float* w2   = (const float*)d_in[8];
    const float* sn_w = (const float*)d_in[9];
    const float* on_w = (const float*)d_in[10];

    __nv_bfloat16 *hp16, *attnp;
    __half *hpf, *ffp;
    float *qkv, *x;
    unsigned *wqkvp, *wop, *w01p, *w2p;
    cudaGetSymbolAddress((void**)&hp16,  g_hp16);
    cudaGetSymbolAddress((void**)&hpf,   g_hpf);
    cudaGetSymbolAddress((void**)&qkv,   g_qkv);
    cudaGetSymbolAddress((void**)&attnp, g_attnp);
    cudaGetSymbolAddress((void**)&x,     g_x);
    cudaGetSymbolAddress((void**)&ffp,   g_ffp);
    cudaGetSymbolAddress((void**)&wqkvp, g_wqkvp);
    cudaGetSymbolAddress((void**)&wop,   g_wop);
    cudaGetSymbolAddress((void**)&w01p,  g_w01p);
    cudaGetSymbolAddress((void**)&w2p,   g_w2p);

    // allow 96KB dynamic smem (idempotent; not a stream op)
    cudaFuncSetAttribute(tgemm16_k<0,false>, cudaFuncAttributeMaxDynamicSharedMemorySize, GEMM_SMEM);
    cudaFuncSetAttribute(tgemm16_k<1,false>, cudaFuncAttributeMaxDynamicSharedMemorySize, GEMM_SMEM);
    cudaFuncSetAttribute(tgemm16_k<1,true>,  cudaFuncAttributeMaxDynamicSharedMemorySize, GEMM_SMEM);
    cudaFuncSetAttribute(tgemm16_k<2,true>,  cudaFuncAttributeMaxDynamicSharedMemorySize, GEMM_SMEM);

    pack_all<<<PACK_BLKS, 256>>>(Wq, Wk, Wv, Wo, w0, w1, w2, wqkvp, wop, w01p, w2p);

    const float* cur = x_in;
    for (int li = 0; li < LAYERS; li++) {
        // attention side (bf16)
        rmsnorm_k<2><<<ROWS, 256>>>(cur, an_w + (size_t)li * DMODEL, hp16);

        tgemm16_k<0,false><<<dim3(QKVW / 128, ROWS / 128), 256, GEMM_SMEM>>>(
            hp16, wqkvp + (size_t)li * DMODEL * QKVW / 2, qkv, nullptr, QKVW, DMODEL);

        rope_packed<<<(ROWS * 16 * 32 + 255) / 256, 256>>>(qkv);

        flash_kernel<<<dim3(SEQ / 64, NHEADS, BATCH), 128>>>(qkv, attnp);

        tgemm16_k<1,false><<<dim3(DMODEL / 128, ROWS / 128), 256, GEMM_SMEM>>>(
            attnp, wop + (size_t)li * DMODEL * DMODEL / 2, x, cur, DMODEL, DMODEL);

        // FFN side (fp16 — same eps as tf32, 2x speed)
        rmsnorm_k<1><<<ROWS, 256>>>(x, sn_w + (size_t)li * DMODEL, hpf);

        tgemm16_k<2,true><<<dim3(2 * FFDIM / 128, ROWS / 128), 256, GEMM_SMEM>>>(
            hpf, w01p + (size_t)li * DMODEL * 2 * FFDIM / 2, ffp, nullptr, 2 * FFDIM, DMODEL);

        tgemm16_k<1,true><<<dim3(DMODEL / 128, ROWS / 128), 256, GEMM_SMEM>>>(
            ffp, w2p + (size_t)li * FFDIM * DMODEL / 2, x, x, DMODEL, FFDIM);
        cur = x;
    }

    rmsnorm_k<0><<<ROWS, 256>>>(x, on_w, (float*)d_out);
}